// round 2
// baseline (speedup 1.0000x reference)
#include <cuda_runtime.h>
#include <cuda_bf16.h>
#include <math.h>

#define B_  4
#define T_  2048
#define C_  768
#define NH_ 12
#define HD_ 64
#define RD_ 16
#define M_  (B_ * T_)          // 8192
#define NQKV (3 * C_)          // 2304

// ---------------- scratch (device globals; no allocation allowed) ------------
__device__ float g_qkv[M_ * NQKV];               // [B*T, 2304]
__device__ float g_q[B_ * NH_ * T_ * HD_];       // [BH, T, 64]
__device__ float g_k[B_ * NH_ * T_ * HD_];
__device__ float g_v[B_ * NH_ * T_ * HD_];
__device__ float g_o[M_ * C_];                   // [B*T, 768] attention output

// ---------------- GEMM: C[m,n] = sum_k A[m,k] * B[n,k]  (C = A @ B^T) --------
// 128x64 block tile, BK=32, 256 threads, 8x4 per-thread tile.
#define GBM 128
#define GBN 64
#define GBK 32
#define APAD 132
#define BPAD 68

__global__ __launch_bounds__(256) void gemm_tn_kernel(
    const float* __restrict__ A, const float* __restrict__ Bm,
    float* __restrict__ C, int M, int N, int K)
{
    __shared__ float As[GBK * APAD];  // As[k][m], m in 0..127
    __shared__ float Bs[GBK * BPAD];  // Bs[k][n], n in 0..63

    const int tid = threadIdx.x;
    const int tx = tid & 15;          // col group (4 cols)
    const int ty = tid >> 4;          // row group (8 rows)
    const int m0 = blockIdx.y * GBM;
    const int n0 = blockIdx.x * GBN;

    float acc[8][4];
#pragma unroll
    for (int i = 0; i < 8; i++)
#pragma unroll
        for (int j = 0; j < 4; j++) acc[i][j] = 0.f;

    for (int k0 = 0; k0 < K; k0 += GBK) {
        // load A tile 128x32 (16 elems/thread) and B tile 64x32 (8 elems/thread)
#pragma unroll
        for (int l = 0; l < 16; l++) {
            int idx = l * 256 + tid;
            int mm = idx >> 5;        // 0..127
            int kk = idx & 31;        // 0..31
            As[kk * APAD + mm] = A[(size_t)(m0 + mm) * K + k0 + kk];
        }
#pragma unroll
        for (int l = 0; l < 8; l++) {
            int idx = l * 256 + tid;
            int nn = idx >> 5;        // 0..63
            int kk = idx & 31;
            Bs[kk * BPAD + nn] = Bm[(size_t)(n0 + nn) * K + k0 + kk];
        }
        __syncthreads();

#pragma unroll
        for (int kk = 0; kk < GBK; kk++) {
            float4 a0 = *(const float4*)&As[kk * APAD + ty * 8];
            float4 a1 = *(const float4*)&As[kk * APAD + ty * 8 + 4];
            float4 b  = *(const float4*)&Bs[kk * BPAD + tx * 4];
            float av[8] = {a0.x, a0.y, a0.z, a0.w, a1.x, a1.y, a1.z, a1.w};
            float bv[4] = {b.x, b.y, b.z, b.w};
#pragma unroll
            for (int i = 0; i < 8; i++)
#pragma unroll
                for (int j = 0; j < 4; j++) acc[i][j] += av[i] * bv[j];
        }
        __syncthreads();
    }

#pragma unroll
    for (int i = 0; i < 8; i++) {
        float4 o = make_float4(acc[i][0], acc[i][1], acc[i][2], acc[i][3]);
        *(float4*)&C[(size_t)(m0 + ty * 8 + i) * N + n0 + tx * 4] = o;
    }
}

// ---------------- RoPE + rearrange: qkv[B*T,2304] -> q/k/v [BH,T,64] ---------
__global__ __launch_bounds__(256) void rope_rearrange_kernel()
{
    const long long total = 3LL * B_ * NH_ * T_ * HD_;
    long long idx = (long long)blockIdx.x * blockDim.x + threadIdx.x;
    if (idx >= total) return;

    int d = (int)(idx & 63);
    long long r = idx >> 6;
    int t = (int)(r % T_); r /= T_;
    int h = (int)(r % NH_); r /= NH_;
    int b = (int)(r % B_);
    int sel = (int)(r / B_);

    const size_t srow = ((size_t)(b * T_ + t)) * NQKV + sel * C_ + h * HD_;
    float val = g_qkv[srow + d];

    if (sel < 2 && d < RD_) {
        int j = (d < 8) ? d : d - 8;
        float freq = __powf(10000.0f, -(float)j / 8.0f);
        float ang = (float)t * freq;
        float c = cosf(ang), s = sinf(ang);
        if (d < 8) {
            float r2 = g_qkv[srow + d + 8];
            val = val * c - r2 * s;
        } else {
            float r1 = g_qkv[srow + d - 8];
            val = val * c + r1 * s;
        }
    }

    float* dst = (sel == 0) ? g_q : (sel == 1) ? g_k : g_v;
    dst[(((size_t)(b * NH_ + h)) * T_ + t) * HD_ + d] = val;
}

// ---------------- Flash attention (fp32, causal, parallel softmax) -----------
// grid: (T/64 q-tiles, B*NH), 256 threads, BLOCK_Q = BLOCK_K = 64.
#define FQ 64
#define FK 64
#define FPAD 68
#define SPAD 65

__global__ __launch_bounds__(256) void flash_kernel()
{
    extern __shared__ float sm[];
    float* QsT = sm;                      // [64][68]  (d-major: QsT[d][r]), pre-scaled
    float* KsT = QsT + 64 * FPAD;         // [64][68]  (KsT[d][c])
    float* Vs  = KsT + 64 * FPAD;         // [64][68]  (Vs[k][d])
    float* Ss  = Vs  + 64 * FPAD;         // [64][65]  P tile

    const int tid = threadIdx.x;
    const int tx = tid & 15, ty = tid >> 4;
    const int qt = blockIdx.x;
    const int bh = blockIdx.y;
    const int q0 = qt * FQ;
    const int b = bh / NH_, h = bh % NH_;
    const float scale = 0.125f;  // 1/sqrt(64)

    const float* Q = g_q + (size_t)bh * T_ * HD_;
    const float* K = g_k + (size_t)bh * T_ * HD_;
    const float* V = g_v + (size_t)bh * T_ * HD_;

    // load Q tile transposed & pre-scaled: QsT[d][r]
#pragma unroll
    for (int l = 0; l < 16; l++) {
        int idx = l * 256 + tid;
        int rr = idx >> 6, dd = idx & 63;
        QsT[dd * FPAD + rr] = Q[(size_t)(q0 + rr) * HD_ + dd] * scale;
    }

    float acc[4][4];
    float m_i[4], l_i[4];
#pragma unroll
    for (int i = 0; i < 4; i++) {
        m_i[i] = -1e30f; l_i[i] = 0.f;
#pragma unroll
        for (int j = 0; j < 4; j++) acc[i][j] = 0.f;
    }

    const int ktiles = qt + 1;
    for (int kt = 0; kt < ktiles; kt++) {
        const int k0 = kt * FK;
        __syncthreads();   // previous PV done reading Ss/Vs; QK done reading KsT
        // load K transposed, V natural
#pragma unroll
        for (int l = 0; l < 16; l++) {
            int idx = l * 256 + tid;
            int cc = idx >> 6, dd = idx & 63;
            KsT[dd * FPAD + cc] = K[(size_t)(k0 + cc) * HD_ + dd];
            Vs[cc * FPAD + dd]  = V[(size_t)(k0 + cc) * HD_ + dd];
        }
        __syncthreads();

        // S = Q K^T  (Q pre-scaled)
        float sacc[4][4];
#pragma unroll
        for (int i = 0; i < 4; i++)
#pragma unroll
            for (int j = 0; j < 4; j++) sacc[i][j] = 0.f;
#pragma unroll
        for (int dd = 0; dd < 64; dd++) {
            float4 a = *(const float4*)&QsT[dd * FPAD + ty * 4];
            float4 bb = *(const float4*)&KsT[dd * FPAD + tx * 4];
            float av[4] = {a.x, a.y, a.z, a.w};
            float bv[4] = {bb.x, bb.y, bb.z, bb.w};
#pragma unroll
            for (int i = 0; i < 4; i++)
#pragma unroll
                for (int j = 0; j < 4; j++) sacc[i][j] += av[i] * bv[j];
        }

        // causal mask (diag tile only)
        if (kt == qt) {
#pragma unroll
            for (int i = 0; i < 4; i++) {
                int gq = q0 + ty * 4 + i;
#pragma unroll
                for (int j = 0; j < 4; j++) {
                    int gk = k0 + tx * 4 + j;
                    if (gk > gq) sacc[i][j] = -1e30f;
                }
            }
        }

        // parallel online softmax: reduce across the 16-lane tx group (half-warp)
#pragma unroll
        for (int i = 0; i < 4; i++) {
            float rmax = fmaxf(fmaxf(sacc[i][0], sacc[i][1]),
                               fmaxf(sacc[i][2], sacc[i][3]));
#pragma unroll
            for (int off = 1; off < 16; off <<= 1)
                rmax = fmaxf(rmax, __shfl_xor_sync(0xffffffffu, rmax, off));
            float mnew = fmaxf(m_i[i], rmax);
            float alpha = __expf(m_i[i] - mnew);
            float sum = 0.f;
#pragma unroll
            for (int j = 0; j < 4; j++) {
                float p = __expf(sacc[i][j] - mnew);
                Ss[(ty * 4 + i) * SPAD + tx * 4 + j] = p;
                sum += p;
            }
#pragma unroll
            for (int off = 1; off < 16; off <<= 1)
                sum += __shfl_xor_sync(0xffffffffu, sum, off);
            l_i[i] = l_i[i] * alpha + sum;
            m_i[i] = mnew;
#pragma unroll
            for (int j = 0; j < 4; j++) acc[i][j] *= alpha;
        }
        __syncthreads();

        // O += P V
#pragma unroll
        for (int kk = 0; kk < 64; kk++) {
            float4 bv4 = *(const float4*)&Vs[kk * FPAD + tx * 4];
            float bv[4] = {bv4.x, bv4.y, bv4.z, bv4.w};
#pragma unroll
            for (int i = 0; i < 4; i++) {
                float a = Ss[(ty * 4 + i) * SPAD + kk];
#pragma unroll
                for (int j = 0; j < 4; j++) acc[i][j] += a * bv[j];
            }
        }
    }

    // write O into [B*T, 768] layout (normalize by l)
#pragma unroll
    for (int i = 0; i < 4; i++) {
        float inv_l = 1.0f / l_i[i];
        int t = q0 + ty * 4 + i;
        float4 o = make_float4(acc[i][0] * inv_l, acc[i][1] * inv_l,
                               acc[i][2] * inv_l, acc[i][3] * inv_l);
        *(float4*)&g_o[((size_t)(b * T_ + t)) * C_ + h * HD_ + tx * 4] = o;
    }
}

// ---------------- launch ------------------------------------------------------
extern "C" void kernel_launch(void* const* d_in, const int* in_sizes, int n_in,
                              void* d_out, int out_size)
{
    const float* x     = (const float*)d_in[0];   // [4,2048,768]
    const float* w_qkv = (const float*)d_in[1];   // [2304,768]
    const float* w_out = (const float*)d_in[2];   // [768,768]
    float* out = (float*)d_out;                   // [4,2048,768]

    float *qkv_p, *o_p;
    cudaGetSymbolAddress((void**)&qkv_p, g_qkv);
    cudaGetSymbolAddress((void**)&o_p, g_o);

    // 1) QKV GEMM: [8192,768] @ [2304,768]^T -> [8192,2304]
    {
        dim3 grid(NQKV / GBN, M_ / GBM);
        gemm_tn_kernel<<<grid, 256>>>(x, w_qkv, qkv_p, M_, NQKV, C_);
    }

    // 2) RoPE + rearrange
    {
        long long total = 3LL * B_ * NH_ * T_ * HD_;
        int blocks = (int)((total + 255) / 256);
        rope_rearrange_kernel<<<blocks, 256>>>();
    }

    // 3) flash attention
    {
        const int smem = (3 * 64 * FPAD + 64 * SPAD) * sizeof(float);
        cudaFuncSetAttribute(flash_kernel, cudaFuncAttributeMaxDynamicSharedMemorySize, smem);
        dim3 grid(T_ / FQ, B_ * NH_);
        flash_kernel<<<grid, 256, smem>>>();
    }

    // 4) out projection: [8192,768] @ [768,768]^T -> [8192,768]
    {
        dim3 grid(C_ / GBN, M_ / GBM);
        gemm_tn_kernel<<<grid, 256>>>(o_p, w_out, out, M_, C_, C_);
    }
}

// round 4
// speedup vs baseline: 1.0986x; 1.0986x over previous
#include <cuda_runtime.h>
#include <cuda_bf16.h>
#include <cstdint>
#include <math.h>

#define B_  4
#define T_  2048
#define C_  768
#define NH_ 12
#define HD_ 64
#define RD_ 16
#define M_  (B_ * T_)          // 8192
#define NQKV (3 * C_)          // 2304

// ---------------- scratch (device globals; no allocation allowed) ------------
__device__ float g_qkv[M_ * NQKV];               // [B*T, 2304]
__device__ float g_q[B_ * NH_ * T_ * HD_];       // [BH, T, 64]
__device__ float g_k[B_ * NH_ * T_ * HD_];
__device__ float g_v[B_ * NH_ * T_ * HD_];
__device__ float g_o[M_ * C_];                   // [B*T, 768] attention output

// ---------------- GEMM (round-1 version): C = A @ B^T ------------------------
#define GBM 64
#define GBN 64
#define GBK 32
#define GPAD 68

__global__ __launch_bounds__(256) void gemm_tn_kernel(
    const float* __restrict__ A, const float* __restrict__ Bm,
    float* __restrict__ C, int M, int N, int K)
{
    __shared__ float As[GBK * GPAD];  // As[k][m]
    __shared__ float Bs[GBK * GPAD];  // Bs[k][n]

    const int tid = threadIdx.x;
    const int tx = tid & 15;
    const int ty = tid >> 4;
    const int m0 = blockIdx.y * GBM;
    const int n0 = blockIdx.x * GBN;

    float acc[4][4];
#pragma unroll
    for (int i = 0; i < 4; i++)
#pragma unroll
        for (int j = 0; j < 4; j++) acc[i][j] = 0.f;

    for (int k0 = 0; k0 < K; k0 += GBK) {
#pragma unroll
        for (int l = 0; l < 8; l++) {
            int idx = l * 256 + tid;
            int mm = idx >> 5;
            int kk = idx & 31;
            As[kk * GPAD + mm] = A[(size_t)(m0 + mm) * K + k0 + kk];
            Bs[kk * GPAD + mm] = Bm[(size_t)(n0 + mm) * K + k0 + kk];
        }
        __syncthreads();

#pragma unroll
        for (int kk = 0; kk < GBK; kk++) {
            float4 a = *(const float4*)&As[kk * GPAD + ty * 4];
            float4 b = *(const float4*)&Bs[kk * GPAD + tx * 4];
            float av[4] = {a.x, a.y, a.z, a.w};
            float bv[4] = {b.x, b.y, b.z, b.w};
#pragma unroll
            for (int i = 0; i < 4; i++)
#pragma unroll
                for (int j = 0; j < 4; j++) acc[i][j] += av[i] * bv[j];
        }
        __syncthreads();
    }

#pragma unroll
    for (int i = 0; i < 4; i++) {
        float4 o = make_float4(acc[i][0], acc[i][1], acc[i][2], acc[i][3]);
        *(float4*)&C[(size_t)(m0 + ty * 4 + i) * N + n0 + tx * 4] = o;
    }
}

// ---------------- RoPE + rearrange -------------------------------------------
__global__ __launch_bounds__(256) void rope_rearrange_kernel()
{
    const long long total = 3LL * B_ * NH_ * T_ * HD_;
    long long idx = (long long)blockIdx.x * blockDim.x + threadIdx.x;
    if (idx >= total) return;

    int d = (int)(idx & 63);
    long long r = idx >> 6;
    int t = (int)(r % T_); r /= T_;
    int h = (int)(r % NH_); r /= NH_;
    int b = (int)(r % B_);
    int sel = (int)(r / B_);

    const size_t srow = ((size_t)(b * T_ + t)) * NQKV + sel * C_ + h * HD_;
    float val = g_qkv[srow + d];

    if (sel < 2 && d < RD_) {
        int j = (d < 8) ? d : d - 8;
        float freq = __powf(10000.0f, -(float)j / 8.0f);
        float ang = (float)t * freq;
        float c = cosf(ang), s = sinf(ang);
        if (d < 8) {
            float r2 = g_qkv[srow + d + 8];
            val = val * c - r2 * s;
        } else {
            float r1 = g_qkv[srow + d - 8];
            val = val * c + r1 * s;
        }
    }

    float* dst = (sel == 0) ? g_q : (sel == 1) ? g_k : g_v;
    dst[(((size_t)(b * NH_ + h)) * T_ + t) * HD_ + d] = val;
}

// ---------------- Flash attention: pipelined, double-buffered ----------------
#define FQ 64
#define FK 64
#define FPAD 68
#define SPAD 65

__device__ __forceinline__ void cp_async16(unsigned int smem_addr, const void* gptr) {
    asm volatile("cp.async.ca.shared.global [%0], [%1], 16;\n"
                 :: "r"(smem_addr), "l"(gptr));
}
__device__ __forceinline__ void cp_async_commit() {
    asm volatile("cp.async.commit_group;\n" ::: "memory");
}
__device__ __forceinline__ void cp_async_wait_all() {
    asm volatile("cp.async.wait_group 0;\n" ::: "memory");
}

__global__ __launch_bounds__(256) void flash_kernel()
{
    extern __shared__ float sm[];
    float* QsT = sm;                           // [64][68] (QsT[d][r]), pre-scaled
    float* KsT0 = QsT + 64 * FPAD;             // [64][68] (KsT[d][c]) buf 0
    float* KsT1 = KsT0 + 64 * FPAD;            // buf 1
    float* Vs0  = KsT1 + 64 * FPAD;            // [64][68] (Vs[k][d]) buf 0
    float* Vs1  = Vs0 + 64 * FPAD;             // buf 1
    float* Ss   = Vs1 + 64 * FPAD;             // [64][65]

    const int tid = threadIdx.x;
    const int tx = tid & 15, ty = tid >> 4;
    const int qt = blockIdx.x;
    const int bh = blockIdx.y;
    const int q0 = qt * FQ;
    const int b = bh / NH_, h = bh % NH_;
    const float scale = 0.125f;

    const float* Q = g_q + (size_t)bh * T_ * HD_;
    const float* K = g_k + (size_t)bh * T_ * HD_;
    const float* V = g_v + (size_t)bh * T_ * HD_;

    // load Q tile transposed & pre-scaled
#pragma unroll
    for (int l = 0; l < 16; l++) {
        int idx = l * 256 + tid;
        int rr = idx >> 6, dd = idx & 63;
        QsT[dd * FPAD + rr] = Q[(size_t)(q0 + rr) * HD_ + dd] * scale;
    }

    const int k_dd = tid & 63;

    // --- prime tile 0: K via LDG+STS, V via cp.async ---
    {
        float kreg[16];
#pragma unroll
        for (int l = 0; l < 16; l++) {
            int cc = (l * 256 + tid) >> 6;
            kreg[l] = K[(size_t)cc * HD_ + k_dd];
        }
#pragma unroll
        for (int l = 0; l < 16; l++) {
            int cc = (l * 256 + tid) >> 6;
            KsT0[k_dd * FPAD + cc] = kreg[l];
        }
        // V: 4 chunks of 16B per thread
#pragma unroll
        for (int l = 0; l < 4; l++) {
            int slot = l * 256 + tid;          // 0..1023
            int row = slot >> 4, cg = slot & 15;
            unsigned int dst = (unsigned int)__cvta_generic_to_shared(&Vs0[row * FPAD + cg * 4]);
            cp_async16(dst, &V[(size_t)row * HD_ + cg * 4]);
        }
        cp_async_commit();
    }
    cp_async_wait_all();
    __syncthreads();

    float acc[4][4];
    float m_i[4], l_i[4];
#pragma unroll
    for (int i = 0; i < 4; i++) {
        m_i[i] = -1e30f; l_i[i] = 0.f;
#pragma unroll
        for (int j = 0; j < 4; j++) acc[i][j] = 0.f;
    }

    const int ktiles = qt + 1;
    for (int kt = 0; kt < ktiles; kt++) {
        const int k0 = kt * FK;
        float* KsT = (kt & 1) ? KsT1 : KsT0;
        float* Vs  = (kt & 1) ? Vs1  : Vs0;
        float* KsTn = (kt & 1) ? KsT0 : KsT1;
        float* Vsn  = (kt & 1) ? Vs0  : Vs1;
        const bool have_next = (kt + 1 < ktiles);

        // prefetch next K into registers, next V via cp.async (overlaps compute)
        float kreg[16];
        if (have_next) {
            const int kn0 = k0 + FK;
#pragma unroll
            for (int l = 0; l < 16; l++) {
                int cc = (l * 256 + tid) >> 6;
                kreg[l] = K[(size_t)(kn0 + cc) * HD_ + k_dd];
            }
#pragma unroll
            for (int l = 0; l < 4; l++) {
                int slot = l * 256 + tid;
                int row = slot >> 4, cg = slot & 15;
                unsigned int dst = (unsigned int)__cvta_generic_to_shared(&Vsn[row * FPAD + cg * 4]);
                cp_async16(dst, &V[(size_t)(kn0 + row) * HD_ + cg * 4]);
            }
            cp_async_commit();
        }

        // S = Q K^T  (Q pre-scaled)
        float sacc[4][4];
#pragma unroll
        for (int i = 0; i < 4; i++)
#pragma unroll
            for (int j = 0; j < 4; j++) sacc[i][j] = 0.f;
#pragma unroll
        for (int dd = 0; dd < 64; dd++) {
            float4 a = *(const float4*)&QsT[dd * FPAD + ty * 4];
            float4 bb = *(const float4*)&KsT[dd * FPAD + tx * 4];
            float av[4] = {a.x, a.y, a.z, a.w};
            float bv[4] = {bb.x, bb.y, bb.z, bb.w};
#pragma unroll
            for (int i = 0; i < 4; i++)
#pragma unroll
                for (int j = 0; j < 4; j++) sacc[i][j] += av[i] * bv[j];
        }

        // causal mask on diagonal tile
        if (kt == qt) {
#pragma unroll
            for (int i = 0; i < 4; i++) {
                int gq = q0 + ty * 4 + i;
#pragma unroll
                for (int j = 0; j < 4; j++) {
                    int gk = k0 + tx * 4 + j;
                    if (gk > gq) sacc[i][j] = -1e30f;
                }
            }
        }

        // register online softmax, reduce over 16-lane tx group
#pragma unroll
        for (int i = 0; i < 4; i++) {
            float rmax = fmaxf(fmaxf(sacc[i][0], sacc[i][1]),
                               fmaxf(sacc[i][2], sacc[i][3]));
#pragma unroll
            for (int off = 1; off < 16; off <<= 1)
                rmax = fmaxf(rmax, __shfl_xor_sync(0xffffffffu, rmax, off));
            float mnew = fmaxf(m_i[i], rmax);
            float alpha = __expf(m_i[i] - mnew);
            float sum = 0.f;
#pragma unroll
            for (int j = 0; j < 4; j++) {
                float p = __expf(sacc[i][j] - mnew);
                Ss[(ty * 4 + i) * SPAD + tx * 4 + j] = p;
                sum += p;
            }
#pragma unroll
            for (int off = 1; off < 16; off <<= 1)
                sum += __shfl_xor_sync(0xffffffffu, sum, off);
            l_i[i] = l_i[i] * alpha + sum;
            m_i[i] = mnew;
#pragma unroll
            for (int j = 0; j < 4; j++) acc[i][j] *= alpha;
        }
        __syncthreads();   // Ss visible; all threads finished prior-iter work

        // O += P V
#pragma unroll
        for (int kk = 0; kk < 64; kk++) {
            float4 bv4 = *(const float4*)&Vs[kk * FPAD + tx * 4];
            float bv[4] = {bv4.x, bv4.y, bv4.z, bv4.w};
#pragma unroll
            for (int i = 0; i < 4; i++) {
                float a = Ss[(ty * 4 + i) * SPAD + kk];
#pragma unroll
                for (int j = 0; j < 4; j++) acc[i][j] += a * bv[j];
            }
        }

        if (have_next) {
            // store prefetched K (safe: barrier above proves everyone is past
            // reading the alternate buffers)
#pragma unroll
            for (int l = 0; l < 16; l++) {
                int cc = (l * 256 + tid) >> 6;
                KsTn[k_dd * FPAD + cc] = kreg[l];
            }
            cp_async_wait_all();
        }
        __syncthreads();   // next buffers (K STS + V cp.async) visible; Ss/Vs free
    }

    // write O (normalize by l)
#pragma unroll
    for (int i = 0; i < 4; i++) {
        float inv_l = 1.0f / l_i[i];
        int t = q0 + ty * 4 + i;
        float4 o = make_float4(acc[i][0] * inv_l, acc[i][1] * inv_l,
                               acc[i][2] * inv_l, acc[i][3] * inv_l);
        *(float4*)&g_o[((size_t)(b * T_ + t)) * C_ + h * HD_ + tx * 4] = o;
    }
}

// ---------------- launch ------------------------------------------------------
extern "C" void kernel_launch(void* const* d_in, const int* in_sizes, int n_in,
                              void* d_out, int out_size)
{
    const float* x     = (const float*)d_in[0];
    const float* w_qkv = (const float*)d_in[1];
    const float* w_out = (const float*)d_in[2];
    float* out = (float*)d_out;

    float *qkv_p, *o_p;
    cudaGetSymbolAddress((void**)&qkv_p, g_qkv);
    cudaGetSymbolAddress((void**)&o_p, g_o);

    // 1) QKV GEMM
    {
        dim3 grid(NQKV / GBN, M_ / GBM);
        gemm_tn_kernel<<<grid, 256>>>(x, w_qkv, qkv_p, M_, NQKV, C_);
    }

    // 2) RoPE + rearrange
    {
        long long total = 3LL * B_ * NH_ * T_ * HD_;
        int blocks = (int)((total + 255) / 256);
        rope_rearrange_kernel<<<blocks, 256>>>();
    }

    // 3) flash attention (pipelined)
    {
        const int smem = (5 * 64 * FPAD + 64 * SPAD) * sizeof(float);
        cudaFuncSetAttribute(flash_kernel, cudaFuncAttributeMaxDynamicSharedMemorySize, smem);
        dim3 grid(T_ / FQ, B_ * NH_);
        flash_kernel<<<grid, 256, smem>>>();
    }

    // 4) out projection
    {
        dim3 grid(C_ / GBN, M_ / GBM);
        gemm_tn_kernel<<<grid, 256>>>(o_p, w_out, out, M_, C_, C_);
    }
}

// round 5
// speedup vs baseline: 1.4318x; 1.3033x over previous
#include <cuda_runtime.h>
#include <cuda_bf16.h>
#include <cstdint>
#include <math.h>

#define B_  4
#define T_  2048
#define C_  768
#define NH_ 12
#define HD_ 64
#define RD_ 16
#define M_  (B_ * T_)          // 8192
#define NQKV (3 * C_)          // 2304

// ---------------- scratch ----------------------------------------------------
__device__ float g_qkv[M_ * NQKV];               // [B*T, 2304]
__device__ float g_q[B_ * NH_ * T_ * HD_];       // [BH, T, 64]  tf32-rounded, pre-scaled
__device__ float g_k[B_ * NH_ * T_ * HD_];       // tf32-rounded
__device__ float g_v[B_ * NH_ * T_ * HD_];       // tf32-rounded
__device__ float g_o[M_ * C_];                   // [B*T, 768] attention out (fp32)

// ---------------- helpers -----------------------------------------------------
__device__ __forceinline__ float f2tf32(float x) {
    unsigned u;
    asm("cvt.rna.tf32.f32 %0, %1;" : "=r"(u) : "f"(x));
    return __uint_as_float(u);
}

__device__ __forceinline__ void mma_tf32(float* c,
    float a0, float a1, float a2, float a3, float b0, float b1)
{
    asm volatile(
        "mma.sync.aligned.m16n8k8.row.col.f32.tf32.tf32.f32 "
        "{%0,%1,%2,%3}, {%4,%5,%6,%7}, {%8,%9}, {%0,%1,%2,%3};"
        : "+f"(c[0]), "+f"(c[1]), "+f"(c[2]), "+f"(c[3])
        : "r"(__float_as_uint(a0)), "r"(__float_as_uint(a1)),
          "r"(__float_as_uint(a2)), "r"(__float_as_uint(a3)),
          "r"(__float_as_uint(b0)), "r"(__float_as_uint(b1)));
}

__device__ __forceinline__ void cp_async16(unsigned int smem_addr, const void* gptr) {
    asm volatile("cp.async.ca.shared.global [%0], [%1], 16;\n"
                 :: "r"(smem_addr), "l"(gptr));
}
__device__ __forceinline__ void cp_async_commit() {
    asm volatile("cp.async.commit_group;\n" ::: "memory");
}
__device__ __forceinline__ void cp_async_wait0() {
    asm volatile("cp.async.wait_group 0;\n" ::: "memory");
}
__device__ __forceinline__ void cp_async_wait1() {
    asm volatile("cp.async.wait_group 1;\n" ::: "memory");
}

// ---------------- GEMM (known-good round-1): C = A @ B^T ---------------------
#define GBM 64
#define GBN 64
#define GBK 32
#define GPAD 68

__global__ __launch_bounds__(256) void gemm_tn_kernel(
    const float* __restrict__ A, const float* __restrict__ Bm,
    float* __restrict__ C, int M, int N, int K)
{
    __shared__ float As[GBK * GPAD];
    __shared__ float Bs[GBK * GPAD];

    const int tid = threadIdx.x;
    const int tx = tid & 15;
    const int ty = tid >> 4;
    const int m0 = blockIdx.y * GBM;
    const int n0 = blockIdx.x * GBN;

    float acc[4][4];
#pragma unroll
    for (int i = 0; i < 4; i++)
#pragma unroll
        for (int j = 0; j < 4; j++) acc[i][j] = 0.f;

    for (int k0 = 0; k0 < K; k0 += GBK) {
#pragma unroll
        for (int l = 0; l < 8; l++) {
            int idx = l * 256 + tid;
            int mm = idx >> 5;
            int kk = idx & 31;
            As[kk * GPAD + mm] = A[(size_t)(m0 + mm) * K + k0 + kk];
            Bs[kk * GPAD + mm] = Bm[(size_t)(n0 + mm) * K + k0 + kk];
        }
        __syncthreads();

#pragma unroll
        for (int kk = 0; kk < GBK; kk++) {
            float4 a = *(const float4*)&As[kk * GPAD + ty * 4];
            float4 b = *(const float4*)&Bs[kk * GPAD + tx * 4];
            float av[4] = {a.x, a.y, a.z, a.w};
            float bv[4] = {b.x, b.y, b.z, b.w};
#pragma unroll
            for (int i = 0; i < 4; i++)
#pragma unroll
                for (int j = 0; j < 4; j++) acc[i][j] += av[i] * bv[j];
        }
        __syncthreads();
    }

#pragma unroll
    for (int i = 0; i < 4; i++) {
        float4 o = make_float4(acc[i][0], acc[i][1], acc[i][2], acc[i][3]);
        *(float4*)&C[(size_t)(m0 + ty * 4 + i) * N + n0 + tx * 4] = o;
    }
}

// ---------------- RoPE + rearrange + tf32 rounding ----------------------------
__global__ __launch_bounds__(256) void rope_rearrange_kernel()
{
    const long long total = 3LL * B_ * NH_ * T_ * HD_;
    long long idx = (long long)blockIdx.x * blockDim.x + threadIdx.x;
    if (idx >= total) return;

    int d = (int)(idx & 63);
    long long r = idx >> 6;
    int t = (int)(r % T_); r /= T_;
    int h = (int)(r % NH_); r /= NH_;
    int b = (int)(r % B_);
    int sel = (int)(r / B_);

    const size_t srow = ((size_t)(b * T_ + t)) * NQKV + sel * C_ + h * HD_;
    float val = g_qkv[srow + d];

    if (sel < 2 && d < RD_) {
        int j = (d < 8) ? d : d - 8;
        float freq = __powf(10000.0f, -(float)j / 8.0f);
        float ang = (float)t * freq;
        float c = cosf(ang), s = sinf(ang);
        if (d < 8) {
            float r2 = g_qkv[srow + d + 8];
            val = val * c - r2 * s;
        } else {
            float r1 = g_qkv[srow + d - 8];
            val = val * c + r1 * s;
        }
    }

    if (sel == 0) val *= 0.125f;        // fold softmax scale into q
    val = f2tf32(val);                  // round for tensor-core consumption

    float* dst = (sel == 0) ? g_q : (sel == 1) ? g_k : g_v;
    dst[(((size_t)(b * NH_ + h)) * T_ + t) * HD_ + d] = val;
}

// ---------------- Flash attention: TF32 mma.sync ------------------------------
// 128 threads = 4 warps; warp w owns q rows [q0+16w, q0+16w+16).
// K/V tiles 64x64 row-major in smem (PAD=72 -> conflict-free fragment gathers),
// double-buffered via cp.async.
#define FPAD 72

__global__ __launch_bounds__(128) void flash_kernel()
{
    extern __shared__ float sm[];
    float* Ks0 = sm;                   // [64][72]
    float* Ks1 = Ks0 + 64 * FPAD;
    float* Vs0 = Ks1 + 64 * FPAD;
    float* Vs1 = Vs0 + 64 * FPAD;

    const int tid = threadIdx.x;
    const int warp = tid >> 5;
    const int lane = tid & 31;
    const int rA = lane >> 2;          // 0..7
    const int cq = lane & 3;           // 0..3

    const int qt = blockIdx.x;
    const int bh = blockIdx.y;
    const int q0 = qt * 64;
    const int b = bh / NH_, h = bh % NH_;

    const float* Q = g_q + (size_t)bh * T_ * HD_;
    const float* K = g_k + (size_t)bh * T_ * HD_;
    const float* V = g_v + (size_t)bh * T_ * HD_;

    // --- load Q fragments (persistent in registers) ---
    const int qrow = q0 + warp * 16 + rA;
    float qa[8][4];
#pragma unroll
    for (int kb = 0; kb < 8; kb++) {
        qa[kb][0] = Q[(size_t)qrow * HD_ + 8 * kb + cq];
        qa[kb][1] = Q[(size_t)(qrow + 8) * HD_ + 8 * kb + cq];
        qa[kb][2] = Q[(size_t)qrow * HD_ + 8 * kb + cq + 4];
        qa[kb][3] = Q[(size_t)(qrow + 8) * HD_ + 8 * kb + cq + 4];
    }

    float o[8][4];
#pragma unroll
    for (int i = 0; i < 8; i++)
#pragma unroll
        for (int j = 0; j < 4; j++) o[i][j] = 0.f;
    float mA = -1e30f, mB = -1e30f, lA = 0.f, lB = 0.f;

    // --- cp.async tile issue: K and V, 8 chunks each per thread ---
    auto issue_tile = [&](int kt, float* Ksb, float* Vsb) {
        const int k0 = kt * 64;
#pragma unroll
        for (int l = 0; l < 8; l++) {
            int slot = l * 128 + tid;          // 0..1023
            int row = slot >> 4, ch = slot & 15;
            unsigned int dk = (unsigned int)__cvta_generic_to_shared(&Ksb[row * FPAD + ch * 4]);
            cp_async16(dk, &K[(size_t)(k0 + row) * HD_ + ch * 4]);
            unsigned int dv = (unsigned int)__cvta_generic_to_shared(&Vsb[row * FPAD + ch * 4]);
            cp_async16(dv, &V[(size_t)(k0 + row) * HD_ + ch * 4]);
        }
        cp_async_commit();
    };

    issue_tile(0, Ks0, Vs0);

    const int srcA = (lane & ~3) | (cq >> 1);
    const int srcB = srcA + 2;
    const bool par = (cq & 1);

    for (int kt = 0; kt <= qt; kt++) {
        float* Ks = (kt & 1) ? Ks1 : Ks0;
        float* Vs = (kt & 1) ? Vs1 : Vs0;
        const bool have_next = (kt < qt);
        if (have_next) {
            issue_tile(kt + 1, (kt & 1) ? Ks0 : Ks1, (kt & 1) ? Vs0 : Vs1);
            cp_async_wait1();
        } else {
            cp_async_wait0();
        }
        __syncthreads();

        // --- S = Q K^T : 64 MMAs (kb outer -> 8 independent chains) ---
        float s[8][4];
#pragma unroll
        for (int nb = 0; nb < 8; nb++)
#pragma unroll
            for (int j = 0; j < 4; j++) s[nb][j] = 0.f;
#pragma unroll
        for (int kb = 0; kb < 8; kb++) {
#pragma unroll
            for (int nb = 0; nb < 8; nb++) {
                float b0 = Ks[(8 * nb + rA) * FPAD + 8 * kb + cq];
                float b1 = Ks[(8 * nb + rA) * FPAD + 8 * kb + cq + 4];
                mma_tf32(s[nb], qa[kb][0], qa[kb][1], qa[kb][2], qa[kb][3], b0, b1);
            }
        }

        // --- causal mask on the diagonal tile ---
        if (kt == qt) {
            const int k0 = kt * 64;
#pragma unroll
            for (int nb = 0; nb < 8; nb++) {
                int col = k0 + 8 * nb + 2 * cq;
                if (col > qrow)     s[nb][0] = -1e30f;
                if (col + 1 > qrow) s[nb][1] = -1e30f;
                if (col > qrow + 8)     s[nb][2] = -1e30f;
                if (col + 1 > qrow + 8) s[nb][3] = -1e30f;
            }
        }

        // --- online softmax (rows: A = lane>>2, B = +8) ---
        float rmaxA = -1e30f, rmaxB = -1e30f;
#pragma unroll
        for (int nb = 0; nb < 8; nb++) {
            rmaxA = fmaxf(rmaxA, fmaxf(s[nb][0], s[nb][1]));
            rmaxB = fmaxf(rmaxB, fmaxf(s[nb][2], s[nb][3]));
        }
        rmaxA = fmaxf(rmaxA, __shfl_xor_sync(0xffffffffu, rmaxA, 1));
        rmaxA = fmaxf(rmaxA, __shfl_xor_sync(0xffffffffu, rmaxA, 2));
        rmaxB = fmaxf(rmaxB, __shfl_xor_sync(0xffffffffu, rmaxB, 1));
        rmaxB = fmaxf(rmaxB, __shfl_xor_sync(0xffffffffu, rmaxB, 2));

        float mnA = fmaxf(mA, rmaxA), mnB = fmaxf(mB, rmaxB);
        float alA = __expf(mA - mnA), alB = __expf(mB - mnB);
        mA = mnA; mB = mnB;

        float sumA = 0.f, sumB = 0.f;
#pragma unroll
        for (int nb = 0; nb < 8; nb++) {
            s[nb][0] = __expf(s[nb][0] - mA); sumA += s[nb][0];
            s[nb][1] = __expf(s[nb][1] - mA); sumA += s[nb][1];
            s[nb][2] = __expf(s[nb][2] - mB); sumB += s[nb][2];
            s[nb][3] = __expf(s[nb][3] - mB); sumB += s[nb][3];
        }
        sumA += __shfl_xor_sync(0xffffffffu, sumA, 1);
        sumA += __shfl_xor_sync(0xffffffffu, sumA, 2);
        sumB += __shfl_xor_sync(0xffffffffu, sumB, 1);
        sumB += __shfl_xor_sync(0xffffffffu, sumB, 2);
        lA = lA * alA + sumA;
        lB = lB * alB + sumB;

#pragma unroll
        for (int nb = 0; nb < 8; nb++) {
            o[nb][0] *= alA; o[nb][1] *= alA;
            o[nb][2] *= alB; o[nb][3] *= alB;
        }

        // tf32-round P
#pragma unroll
        for (int nb = 0; nb < 8; nb++)
#pragma unroll
            for (int j = 0; j < 4; j++) s[nb][j] = f2tf32(s[nb][j]);

        // --- O += P V : per seq k-block, shuffle P C-layout -> A-layout ---
#pragma unroll
        for (int kb2 = 0; kb2 < 8; kb2++) {
            float t0, t1;
            t0 = __shfl_sync(0xffffffffu, s[kb2][0], srcA);
            t1 = __shfl_sync(0xffffffffu, s[kb2][1], srcA);
            float pa0 = par ? t1 : t0;
            t0 = __shfl_sync(0xffffffffu, s[kb2][0], srcB);
            t1 = __shfl_sync(0xffffffffu, s[kb2][1], srcB);
            float pa2 = par ? t1 : t0;
            t0 = __shfl_sync(0xffffffffu, s[kb2][2], srcA);
            t1 = __shfl_sync(0xffffffffu, s[kb2][3], srcA);
            float pa1 = par ? t1 : t0;
            t0 = __shfl_sync(0xffffffffu, s[kb2][2], srcB);
            t1 = __shfl_sync(0xffffffffu, s[kb2][3], srcB);
            float pa3 = par ? t1 : t0;

#pragma unroll
            for (int nb2 = 0; nb2 < 8; nb2++) {
                float b0 = Vs[(8 * kb2 + cq) * FPAD + 8 * nb2 + rA];
                float b1 = Vs[(8 * kb2 + cq + 4) * FPAD + 8 * nb2 + rA];
                mma_tf32(o[nb2], pa0, pa1, pa2, pa3, b0, b1);
            }
        }
        __syncthreads();   // all reads of Ks/Vs done before next-next overwrite
    }

    // --- epilogue: normalize & write to [B*T, 768] ---
    float invA = 1.f / lA, invB = 1.f / lB;
    const size_t rowA_off = ((size_t)(b * T_ + qrow)) * C_ + h * HD_;
    const size_t rowB_off = ((size_t)(b * T_ + qrow + 8)) * C_ + h * HD_;
#pragma unroll
    for (int nb2 = 0; nb2 < 8; nb2++) {
        int col = 8 * nb2 + 2 * cq;
        g_o[rowA_off + col]     = o[nb2][0] * invA;
        g_o[rowA_off + col + 1] = o[nb2][1] * invA;
        g_o[rowB_off + col]     = o[nb2][2] * invB;
        g_o[rowB_off + col + 1] = o[nb2][3] * invB;
    }
}

// ---------------- launch ------------------------------------------------------
extern "C" void kernel_launch(void* const* d_in, const int* in_sizes, int n_in,
                              void* d_out, int out_size)
{
    const float* x     = (const float*)d_in[0];
    const float* w_qkv = (const float*)d_in[1];
    const float* w_out = (const float*)d_in[2];
    float* out = (float*)d_out;

    float *qkv_p, *o_p;
    cudaGetSymbolAddress((void**)&qkv_p, g_qkv);
    cudaGetSymbolAddress((void**)&o_p, g_o);

    // 1) QKV GEMM
    {
        dim3 grid(NQKV / GBN, M_ / GBM);
        gemm_tn_kernel<<<grid, 256>>>(x, w_qkv, qkv_p, M_, NQKV, C_);
    }

    // 2) RoPE + rearrange (+ tf32 rounding, q pre-scale)
    {
        long long total = 3LL * B_ * NH_ * T_ * HD_;
        int blocks = (int)((total + 255) / 256);
        rope_rearrange_kernel<<<blocks, 256>>>();
    }

    // 3) flash attention (tf32 tensor cores)
    {
        const int smem = 4 * 64 * FPAD * sizeof(float);
        cudaFuncSetAttribute(flash_kernel, cudaFuncAttributeMaxDynamicSharedMemorySize, smem);
        dim3 grid(T_ / 64, B_ * NH_);
        flash_kernel<<<grid, 128, smem>>>();
    }

    // 4) out projection
    {
        dim3 grid(C_ / GBN, M_ / GBM);
        gemm_tn_kernel<<<grid, 256>>>(o_p, w_out, out, M_, C_, C_);
    }
}

// round 6
// speedup vs baseline: 3.3774x; 2.3588x over previous
#include <cuda_runtime.h>
#include <cuda_bf16.h>
#include <cstdint>
#include <math.h>

#define B_  4
#define T_  2048
#define C_  768
#define NH_ 12
#define HD_ 64
#define RD_ 16
#define M_  (B_ * T_)          // 8192
#define NQKV (3 * C_)          // 2304

// ---------------- scratch ----------------------------------------------------
__device__ float g_qkv[M_ * NQKV];               // [B*T, 2304]
__device__ float g_q[B_ * NH_ * T_ * HD_];       // tf32, pre-scaled
__device__ float g_k[B_ * NH_ * T_ * HD_];       // tf32
__device__ float g_v[B_ * NH_ * T_ * HD_];       // tf32
__device__ float g_o[M_ * C_];                   // [B*T, 768] attn out (tf32-rounded)
__device__ float g_xr[M_ * C_];                  // x rounded to tf32
__device__ float g_wqr[NQKV * C_];               // w_qkv rounded
__device__ float g_wor[C_ * C_];                 // w_out rounded

// ---------------- helpers -----------------------------------------------------
__device__ __forceinline__ float f2tf32(float x) {
    unsigned u;
    asm("cvt.rna.tf32.f32 %0, %1;" : "=r"(u) : "f"(x));
    return __uint_as_float(u);
}

__device__ __forceinline__ void mma_tf32(float* c,
    float a0, float a1, float a2, float a3, float b0, float b1)
{
    asm volatile(
        "mma.sync.aligned.m16n8k8.row.col.f32.tf32.tf32.f32 "
        "{%0,%1,%2,%3}, {%4,%5,%6,%7}, {%8,%9}, {%0,%1,%2,%3};"
        : "+f"(c[0]), "+f"(c[1]), "+f"(c[2]), "+f"(c[3])
        : "r"(__float_as_uint(a0)), "r"(__float_as_uint(a1)),
          "r"(__float_as_uint(a2)), "r"(__float_as_uint(a3)),
          "r"(__float_as_uint(b0)), "r"(__float_as_uint(b1)));
}

__device__ __forceinline__ void cp_async16(unsigned int smem_addr, const void* gptr) {
    asm volatile("cp.async.ca.shared.global [%0], [%1], 16;\n"
                 :: "r"(smem_addr), "l"(gptr));
}
__device__ __forceinline__ void cp_async_commit() {
    asm volatile("cp.async.commit_group;\n" ::: "memory");
}
__device__ __forceinline__ void cp_async_wait0() {
    asm volatile("cp.async.wait_group 0;\n" ::: "memory");
}
__device__ __forceinline__ void cp_async_wait1() {
    asm volatile("cp.async.wait_group 1;\n" ::: "memory");
}

// ---------------- tf32 rounding prep ------------------------------------------
__global__ __launch_bounds__(256) void round_tf32_kernel(
    const float* __restrict__ src, float* __restrict__ dst, int n)
{
    int i = blockIdx.x * 256 + threadIdx.x;
    int stride = gridDim.x * 256;
    for (; i < n; i += stride) dst[i] = f2tf32(src[i]);
}

// ---------------- TF32 tensor-core GEMM: C = A @ B^T ---------------------------
// A[M,K], B[N,K] row-major, all tf32-rounded fp32. BM=BN=128, BK=32.
// 256 threads = 8 warps (2 m-groups x 4 n-groups), warp tile 64x32.
#define TPAD 36

__global__ __launch_bounds__(256) void gemm_tf32_kernel(
    const float* __restrict__ A, const float* __restrict__ Bm,
    float* __restrict__ C, int M, int N, int K)
{
    extern __shared__ float smg[];
    float* As0 = smg;                    // [128][36]
    float* As1 = As0 + 128 * TPAD;
    float* Bs0 = As1 + 128 * TPAD;
    float* Bs1 = Bs0 + 128 * TPAD;

    const int tid = threadIdx.x;
    const int warp = tid >> 5;
    const int lane = tid & 31;
    const int rA = lane >> 2;            // 0..7
    const int cq = lane & 3;             // 0..3
    const int warp_m = warp & 1;         // 0..1 (64 rows each)
    const int warp_n = warp >> 1;        // 0..3 (32 cols each)

    const int m0 = blockIdx.y * 128;
    const int n0 = blockIdx.x * 128;

    float acc[4][4][4];                  // [mb][nb][c]
#pragma unroll
    for (int a = 0; a < 4; a++)
#pragma unroll
        for (int b = 0; b < 4; b++)
#pragma unroll
            for (int c = 0; c < 4; c++) acc[a][b][c] = 0.f;

    auto issue = [&](int k0, float* Asb, float* Bsb) {
#pragma unroll
        for (int l = 0; l < 4; l++) {
            int slot = l * 256 + tid;    // 0..1023
            int row = slot >> 3, ch = slot & 7;
            unsigned int da = (unsigned int)__cvta_generic_to_shared(&Asb[row * TPAD + ch * 4]);
            cp_async16(da, &A[(size_t)(m0 + row) * K + k0 + ch * 4]);
            unsigned int db = (unsigned int)__cvta_generic_to_shared(&Bsb[row * TPAD + ch * 4]);
            cp_async16(db, &Bm[(size_t)(n0 + row) * K + k0 + ch * 4]);
        }
        cp_async_commit();
    };

    const int niter = K / 32;
    issue(0, As0, Bs0);

    for (int it = 0; it < niter; it++) {
        float* As = (it & 1) ? As1 : As0;
        float* Bs = (it & 1) ? Bs1 : Bs0;
        if (it + 1 < niter) {
            issue((it + 1) * 32, (it & 1) ? As0 : As1, (it & 1) ? Bs0 : Bs1);
            cp_async_wait1();
        } else {
            cp_async_wait0();
        }
        __syncthreads();

#pragma unroll
        for (int ks = 0; ks < 4; ks++) {
            const int k = ks * 8;
            float af[4][4];
#pragma unroll
            for (int mb = 0; mb < 4; mb++) {
                int row = warp_m * 64 + mb * 16 + rA;
                af[mb][0] = As[row * TPAD + k + cq];
                af[mb][1] = As[(row + 8) * TPAD + k + cq];
                af[mb][2] = As[row * TPAD + k + cq + 4];
                af[mb][3] = As[(row + 8) * TPAD + k + cq + 4];
            }
            float bf[4][2];
#pragma unroll
            for (int nb = 0; nb < 4; nb++) {
                int n = warp_n * 32 + nb * 8 + rA;
                bf[nb][0] = Bs[n * TPAD + k + cq];
                bf[nb][1] = Bs[n * TPAD + k + cq + 4];
            }
#pragma unroll
            for (int mb = 0; mb < 4; mb++)
#pragma unroll
                for (int nb = 0; nb < 4; nb++)
                    mma_tf32(acc[mb][nb], af[mb][0], af[mb][1], af[mb][2], af[mb][3],
                             bf[nb][0], bf[nb][1]);
        }
        __syncthreads();
    }

    // epilogue
#pragma unroll
    for (int mb = 0; mb < 4; mb++) {
        int row = m0 + warp_m * 64 + mb * 16 + rA;
#pragma unroll
        for (int nb = 0; nb < 4; nb++) {
            int col = n0 + warp_n * 32 + nb * 8 + 2 * cq;
            *(float2*)&C[(size_t)row * N + col] =
                make_float2(acc[mb][nb][0], acc[mb][nb][1]);
            *(float2*)&C[(size_t)(row + 8) * N + col] =
                make_float2(acc[mb][nb][2], acc[mb][nb][3]);
        }
    }
}

// ---------------- RoPE + rearrange + tf32 rounding ----------------------------
__global__ __launch_bounds__(256) void rope_rearrange_kernel()
{
    const long long total = 3LL * B_ * NH_ * T_ * HD_;
    long long idx = (long long)blockIdx.x * blockDim.x + threadIdx.x;
    if (idx >= total) return;

    int d = (int)(idx & 63);
    long long r = idx >> 6;
    int t = (int)(r % T_); r /= T_;
    int h = (int)(r % NH_); r /= NH_;
    int b = (int)(r % B_);
    int sel = (int)(r / B_);

    const size_t srow = ((size_t)(b * T_ + t)) * NQKV + sel * C_ + h * HD_;
    float val = g_qkv[srow + d];

    if (sel < 2 && d < RD_) {
        int j = (d < 8) ? d : d - 8;
        float freq = __powf(10000.0f, -(float)j / 8.0f);
        float ang = (float)t * freq;
        float c = cosf(ang), s = sinf(ang);
        if (d < 8) {
            float r2 = g_qkv[srow + d + 8];
            val = val * c - r2 * s;
        } else {
            float r1 = g_qkv[srow + d - 8];
            val = val * c + r1 * s;
        }
    }

    if (sel == 0) val *= 0.125f;
    val = f2tf32(val);

    float* dst = (sel == 0) ? g_q : (sel == 1) ? g_k : g_v;
    dst[(((size_t)(b * NH_ + h)) * T_ + t) * HD_ + d] = val;
}

// ---------------- Flash attention: TF32 mma.sync -------------------------------
#define FPAD 72

__global__ __launch_bounds__(128) void flash_kernel()
{
    extern __shared__ float sm[];
    float* Ks0 = sm;
    float* Ks1 = Ks0 + 64 * FPAD;
    float* Vs0 = Ks1 + 64 * FPAD;
    float* Vs1 = Vs0 + 64 * FPAD;

    const int tid = threadIdx.x;
    const int warp = tid >> 5;
    const int lane = tid & 31;
    const int rA = lane >> 2;
    const int cq = lane & 3;

    const int qt = (int)gridDim.x - 1 - (int)blockIdx.x;  // longest first
    const int bh = blockIdx.y;
    const int q0 = qt * 64;
    const int b = bh / NH_, h = bh % NH_;

    const float* Q = g_q + (size_t)bh * T_ * HD_;
    const float* K = g_k + (size_t)bh * T_ * HD_;
    const float* V = g_v + (size_t)bh * T_ * HD_;

    const int qrow = q0 + warp * 16 + rA;
    float qa[8][4];
#pragma unroll
    for (int kb = 0; kb < 8; kb++) {
        qa[kb][0] = Q[(size_t)qrow * HD_ + 8 * kb + cq];
        qa[kb][1] = Q[(size_t)(qrow + 8) * HD_ + 8 * kb + cq];
        qa[kb][2] = Q[(size_t)qrow * HD_ + 8 * kb + cq + 4];
        qa[kb][3] = Q[(size_t)(qrow + 8) * HD_ + 8 * kb + cq + 4];
    }

    float o[8][4];
#pragma unroll
    for (int i = 0; i < 8; i++)
#pragma unroll
        for (int j = 0; j < 4; j++) o[i][j] = 0.f;
    float mA = -1e30f, mB = -1e30f, lA = 0.f, lB = 0.f;

    auto issue_tile = [&](int kt, float* Ksb, float* Vsb) {
        const int k0 = kt * 64;
#pragma unroll
        for (int l = 0; l < 8; l++) {
            int slot = l * 128 + tid;
            int row = slot >> 4, ch = slot & 15;
            unsigned int dk = (unsigned int)__cvta_generic_to_shared(&Ksb[row * FPAD + ch * 4]);
            cp_async16(dk, &K[(size_t)(k0 + row) * HD_ + ch * 4]);
            unsigned int dv = (unsigned int)__cvta_generic_to_shared(&Vsb[row * FPAD + ch * 4]);
            cp_async16(dv, &V[(size_t)(k0 + row) * HD_ + ch * 4]);
        }
        cp_async_commit();
    };

    issue_tile(0, Ks0, Vs0);

    const int srcA = (lane & ~3) | (cq >> 1);
    const int srcB = srcA + 2;
    const bool par = (cq & 1);

    for (int kt = 0; kt <= qt; kt++) {
        float* Ks = (kt & 1) ? Ks1 : Ks0;
        float* Vs = (kt & 1) ? Vs1 : Vs0;
        const bool have_next = (kt < qt);
        if (have_next) {
            issue_tile(kt + 1, (kt & 1) ? Ks0 : Ks1, (kt & 1) ? Vs0 : Vs1);
            cp_async_wait1();
        } else {
            cp_async_wait0();
        }
        __syncthreads();

        float s[8][4];
#pragma unroll
        for (int nb = 0; nb < 8; nb++)
#pragma unroll
            for (int j = 0; j < 4; j++) s[nb][j] = 0.f;
#pragma unroll
        for (int kb = 0; kb < 8; kb++) {
#pragma unroll
            for (int nb = 0; nb < 8; nb++) {
                float b0 = Ks[(8 * nb + rA) * FPAD + 8 * kb + cq];
                float b1 = Ks[(8 * nb + rA) * FPAD + 8 * kb + cq + 4];
                mma_tf32(s[nb], qa[kb][0], qa[kb][1], qa[kb][2], qa[kb][3], b0, b1);
            }
        }

        if (kt == qt) {
            const int k0 = kt * 64;
#pragma unroll
            for (int nb = 0; nb < 8; nb++) {
                int col = k0 + 8 * nb + 2 * cq;
                if (col > qrow)     s[nb][0] = -1e30f;
                if (col + 1 > qrow) s[nb][1] = -1e30f;
                if (col > qrow + 8)     s[nb][2] = -1e30f;
                if (col + 1 > qrow + 8) s[nb][3] = -1e30f;
            }
        }

        float rmaxA = -1e30f, rmaxB = -1e30f;
#pragma unroll
        for (int nb = 0; nb < 8; nb++) {
            rmaxA = fmaxf(rmaxA, fmaxf(s[nb][0], s[nb][1]));
            rmaxB = fmaxf(rmaxB, fmaxf(s[nb][2], s[nb][3]));
        }
        rmaxA = fmaxf(rmaxA, __shfl_xor_sync(0xffffffffu, rmaxA, 1));
        rmaxA = fmaxf(rmaxA, __shfl_xor_sync(0xffffffffu, rmaxA, 2));
        rmaxB = fmaxf(rmaxB, __shfl_xor_sync(0xffffffffu, rmaxB, 1));
        rmaxB = fmaxf(rmaxB, __shfl_xor_sync(0xffffffffu, rmaxB, 2));

        float mnA = fmaxf(mA, rmaxA), mnB = fmaxf(mB, rmaxB);
        float alA = __expf(mA - mnA), alB = __expf(mB - mnB);
        mA = mnA; mB = mnB;

        float sumA = 0.f, sumB = 0.f;
#pragma unroll
        for (int nb = 0; nb < 8; nb++) {
            s[nb][0] = __expf(s[nb][0] - mA); sumA += s[nb][0];
            s[nb][1] = __expf(s[nb][1] - mA); sumA += s[nb][1];
            s[nb][2] = __expf(s[nb][2] - mB); sumB += s[nb][2];
            s[nb][3] = __expf(s[nb][3] - mB); sumB += s[nb][3];
        }
        sumA += __shfl_xor_sync(0xffffffffu, sumA, 1);
        sumA += __shfl_xor_sync(0xffffffffu, sumA, 2);
        sumB += __shfl_xor_sync(0xffffffffu, sumB, 1);
        sumB += __shfl_xor_sync(0xffffffffu, sumB, 2);
        lA = lA * alA + sumA;
        lB = lB * alB + sumB;

#pragma unroll
        for (int nb = 0; nb < 8; nb++) {
            o[nb][0] *= alA; o[nb][1] *= alA;
            o[nb][2] *= alB; o[nb][3] *= alB;
        }

#pragma unroll
        for (int nb = 0; nb < 8; nb++)
#pragma unroll
            for (int j = 0; j < 4; j++) s[nb][j] = f2tf32(s[nb][j]);

#pragma unroll
        for (int kb2 = 0; kb2 < 8; kb2++) {
            float t0, t1;
            t0 = __shfl_sync(0xffffffffu, s[kb2][0], srcA);
            t1 = __shfl_sync(0xffffffffu, s[kb2][1], srcA);
            float pa0 = par ? t1 : t0;
            t0 = __shfl_sync(0xffffffffu, s[kb2][0], srcB);
            t1 = __shfl_sync(0xffffffffu, s[kb2][1], srcB);
            float pa2 = par ? t1 : t0;
            t0 = __shfl_sync(0xffffffffu, s[kb2][2], srcA);
            t1 = __shfl_sync(0xffffffffu, s[kb2][3], srcA);
            float pa1 = par ? t1 : t0;
            t0 = __shfl_sync(0xffffffffu, s[kb2][2], srcB);
            t1 = __shfl_sync(0xffffffffu, s[kb2][3], srcB);
            float pa3 = par ? t1 : t0;

#pragma unroll
            for (int nb2 = 0; nb2 < 8; nb2++) {
                float b0 = Vs[(8 * kb2 + cq) * FPAD + 8 * nb2 + rA];
                float b1 = Vs[(8 * kb2 + cq + 4) * FPAD + 8 * nb2 + rA];
                mma_tf32(o[nb2], pa0, pa1, pa2, pa3, b0, b1);
            }
        }
        __syncthreads();
    }

    // epilogue: normalize, tf32-round (out-proj consumes via MMA), write
    float invA = 1.f / lA, invB = 1.f / lB;
    const size_t rowA_off = ((size_t)(b * T_ + qrow)) * C_ + h * HD_;
    const size_t rowB_off = ((size_t)(b * T_ + qrow + 8)) * C_ + h * HD_;
#pragma unroll
    for (int nb2 = 0; nb2 < 8; nb2++) {
        int col = 8 * nb2 + 2 * cq;
        g_o[rowA_off + col]     = f2tf32(o[nb2][0] * invA);
        g_o[rowA_off + col + 1] = f2tf32(o[nb2][1] * invA);
        g_o[rowB_off + col]     = f2tf32(o[nb2][2] * invB);
        g_o[rowB_off + col + 1] = f2tf32(o[nb2][3] * invB);
    }
}

// ---------------- launch ------------------------------------------------------
extern "C" void kernel_launch(void* const* d_in, const int* in_sizes, int n_in,
                              void* d_out, int out_size)
{
    const float* x     = (const float*)d_in[0];
    const float* w_qkv = (const float*)d_in[1];
    const float* w_out = (const float*)d_in[2];
    float* out = (float*)d_out;

    float *qkv_p, *o_p, *xr_p, *wqr_p, *wor_p;
    cudaGetSymbolAddress((void**)&qkv_p, g_qkv);
    cudaGetSymbolAddress((void**)&o_p, g_o);
    cudaGetSymbolAddress((void**)&xr_p, g_xr);
    cudaGetSymbolAddress((void**)&wqr_p, g_wqr);
    cudaGetSymbolAddress((void**)&wor_p, g_wor);

    // 0) tf32-round inputs
    round_tf32_kernel<<<2048, 256>>>(x, xr_p, M_ * C_);
    round_tf32_kernel<<<1024, 256>>>(w_qkv, wqr_p, NQKV * C_);
    round_tf32_kernel<<<512, 256>>>(w_out, wor_p, C_ * C_);

    const int gsmem = 4 * 128 * TPAD * sizeof(float);
    cudaFuncSetAttribute(gemm_tf32_kernel, cudaFuncAttributeMaxDynamicSharedMemorySize, gsmem);

    // 1) QKV GEMM (tf32 MMA)
    {
        dim3 grid(NQKV / 128, M_ / 128);
        gemm_tf32_kernel<<<grid, 256, gsmem>>>(xr_p, wqr_p, qkv_p, M_, NQKV, C_);
    }

    // 2) RoPE + rearrange (+ tf32 rounding, q pre-scale)
    {
        long long total = 3LL * B_ * NH_ * T_ * HD_;
        int blocks = (int)((total + 255) / 256);
        rope_rearrange_kernel<<<blocks, 256>>>();
    }

    // 3) flash attention (tf32 tensor cores)
    {
        const int smem = 4 * 64 * FPAD * sizeof(float);
        cudaFuncSetAttribute(flash_kernel, cudaFuncAttributeMaxDynamicSharedMemorySize, smem);
        dim3 grid(T_ / 64, B_ * NH_);
        flash_kernel<<<grid, 128, smem>>>();
    }

    // 4) out projection (tf32 MMA)
    {
        dim3 grid(C_ / 128, M_ / 128);
        gemm_tf32_kernel<<<grid, 256, gsmem>>>(o_p, wor_p, out, M_, C_, C_);
    }
}

// round 7
// speedup vs baseline: 3.4415x; 1.0190x over previous
#include <cuda_runtime.h>
#include <cuda_bf16.h>
#include <cstdint>
#include <math.h>

#define B_  4
#define T_  2048
#define C_  768
#define NH_ 12
#define HD_ 64
#define RD_ 16
#define M_  (B_ * T_)          // 8192
#define NQKV (3 * C_)          // 2304

// ---------------- scratch ----------------------------------------------------
__device__ float g_qkv[M_ * NQKV];               // [B*T, 2304]
__device__ float g_q[B_ * NH_ * T_ * HD_];       // tf32, pre-scaled
__device__ float g_k[B_ * NH_ * T_ * HD_];       // tf32
__device__ float g_v[B_ * NH_ * T_ * HD_];       // tf32
__device__ float g_o[M_ * C_];                   // [B*T, 768] attn out (tf32-rounded)

// ---------------- helpers -----------------------------------------------------
__device__ __forceinline__ float f2tf32(float x) {
    unsigned u;
    asm("cvt.rna.tf32.f32 %0, %1;" : "=r"(u) : "f"(x));
    return __uint_as_float(u);
}

__device__ __forceinline__ void mma_tf32(float* c,
    float a0, float a1, float a2, float a3, float b0, float b1)
{
    asm volatile(
        "mma.sync.aligned.m16n8k8.row.col.f32.tf32.tf32.f32 "
        "{%0,%1,%2,%3}, {%4,%5,%6,%7}, {%8,%9}, {%0,%1,%2,%3};"
        : "+f"(c[0]), "+f"(c[1]), "+f"(c[2]), "+f"(c[3])
        : "r"(__float_as_uint(a0)), "r"(__float_as_uint(a1)),
          "r"(__float_as_uint(a2)), "r"(__float_as_uint(a3)),
          "r"(__float_as_uint(b0)), "r"(__float_as_uint(b1)));
}

__device__ __forceinline__ void cp_async16(unsigned int smem_addr, const void* gptr) {
    asm volatile("cp.async.ca.shared.global [%0], [%1], 16;\n"
                 :: "r"(smem_addr), "l"(gptr));
}
__device__ __forceinline__ void cp_async_commit() {
    asm volatile("cp.async.commit_group;\n" ::: "memory");
}
__device__ __forceinline__ void cp_async_wait0() {
    asm volatile("cp.async.wait_group 0;\n" ::: "memory");
}
__device__ __forceinline__ void cp_async_wait1() {
    asm volatile("cp.async.wait_group 1;\n" ::: "memory");
}

// ---------------- TF32 tensor-core GEMM: C = A @ B^T ---------------------------
// A[M,K], B[N,K] row-major raw fp32; fragments tf32-rounded in registers.
// BM=BN=128, BK=32. 256 threads = 8 warps (2m x 4n), warp tile 64x32.
#define TPAD 36

__global__ __launch_bounds__(256, 2) void gemm_tf32_kernel(
    const float* __restrict__ A, const float* __restrict__ Bm,
    float* __restrict__ C, int M, int N, int K)
{
    extern __shared__ float smg[];
    float* As0 = smg;                    // [128][36]
    float* As1 = As0 + 128 * TPAD;
    float* Bs0 = As1 + 128 * TPAD;
    float* Bs1 = Bs0 + 128 * TPAD;

    const int tid = threadIdx.x;
    const int warp = tid >> 5;
    const int lane = tid & 31;
    const int rA = lane >> 2;            // 0..7
    const int cq = lane & 3;             // 0..3
    const int warp_m = warp & 1;
    const int warp_n = warp >> 1;

    const int m0 = blockIdx.y * 128;
    const int n0 = blockIdx.x * 128;

    float acc[4][4][4];
#pragma unroll
    for (int a = 0; a < 4; a++)
#pragma unroll
        for (int b = 0; b < 4; b++)
#pragma unroll
            for (int c = 0; c < 4; c++) acc[a][b][c] = 0.f;

    auto issue = [&](int k0, float* Asb, float* Bsb) {
#pragma unroll
        for (int l = 0; l < 4; l++) {
            int slot = l * 256 + tid;    // 0..1023
            int row = slot >> 3, ch = slot & 7;
            unsigned int da = (unsigned int)__cvta_generic_to_shared(&Asb[row * TPAD + ch * 4]);
            cp_async16(da, &A[(size_t)(m0 + row) * K + k0 + ch * 4]);
            unsigned int db = (unsigned int)__cvta_generic_to_shared(&Bsb[row * TPAD + ch * 4]);
            cp_async16(db, &Bm[(size_t)(n0 + row) * K + k0 + ch * 4]);
        }
        cp_async_commit();
    };

    const int niter = K / 32;
    issue(0, As0, Bs0);

    for (int it = 0; it < niter; it++) {
        float* As = (it & 1) ? As1 : As0;
        float* Bs = (it & 1) ? Bs1 : Bs0;
        if (it + 1 < niter) {
            issue((it + 1) * 32, (it & 1) ? As0 : As1, (it & 1) ? Bs0 : Bs1);
            cp_async_wait1();
        } else {
            cp_async_wait0();
        }
        __syncthreads();

#pragma unroll
        for (int ks = 0; ks < 4; ks++) {
            const int k = ks * 8;
            float af[4][4];
#pragma unroll
            for (int mb = 0; mb < 4; mb++) {
                int row = warp_m * 64 + mb * 16 + rA;
                af[mb][0] = f2tf32(As[row * TPAD + k + cq]);
                af[mb][1] = f2tf32(As[(row + 8) * TPAD + k + cq]);
                af[mb][2] = f2tf32(As[row * TPAD + k + cq + 4]);
                af[mb][3] = f2tf32(As[(row + 8) * TPAD + k + cq + 4]);
            }
            float bf[4][2];
#pragma unroll
            for (int nb = 0; nb < 4; nb++) {
                int n = warp_n * 32 + nb * 8 + rA;
                bf[nb][0] = f2tf32(Bs[n * TPAD + k + cq]);
                bf[nb][1] = f2tf32(Bs[n * TPAD + k + cq + 4]);
            }
#pragma unroll
            for (int mb = 0; mb < 4; mb++)
#pragma unroll
                for (int nb = 0; nb < 4; nb++)
                    mma_tf32(acc[mb][nb], af[mb][0], af[mb][1], af[mb][2], af[mb][3],
                             bf[nb][0], bf[nb][1]);
        }
        __syncthreads();
    }

#pragma unroll
    for (int mb = 0; mb < 4; mb++) {
        int row = m0 + warp_m * 64 + mb * 16 + rA;
#pragma unroll
        for (int nb = 0; nb < 4; nb++) {
            int col = n0 + warp_n * 32 + nb * 8 + 2 * cq;
            *(float2*)&C[(size_t)row * N + col] =
                make_float2(acc[mb][nb][0], acc[mb][nb][1]);
            *(float2*)&C[(size_t)(row + 8) * N + col] =
                make_float2(acc[mb][nb][2], acc[mb][nb][3]);
        }
    }
}

// ---------------- RoPE + rearrange + tf32 rounding ----------------------------
__global__ __launch_bounds__(256) void rope_rearrange_kernel()
{
    const long long total = 3LL * B_ * NH_ * T_ * HD_;
    long long idx = (long long)blockIdx.x * blockDim.x + threadIdx.x;
    if (idx >= total) return;

    int d = (int)(idx & 63);
    long long r = idx >> 6;
    int t = (int)(r % T_); r /= T_;
    int h = (int)(r % NH_); r /= NH_;
    int b = (int)(r % B_);
    int sel = (int)(r / B_);

    const size_t srow = ((size_t)(b * T_ + t)) * NQKV + sel * C_ + h * HD_;
    float val = g_qkv[srow + d];

    if (sel < 2 && d < RD_) {
        int j = (d < 8) ? d : d - 8;
        float freq = __powf(10000.0f, -(float)j / 8.0f);
        float ang = (float)t * freq;
        float c = cosf(ang), s = sinf(ang);
        if (d < 8) {
            float r2 = g_qkv[srow + d + 8];
            val = val * c - r2 * s;
        } else {
            float r1 = g_qkv[srow + d - 8];
            val = val * c + r1 * s;
        }
    }

    if (sel == 0) val *= 0.125f;
    val = f2tf32(val);

    float* dst = (sel == 0) ? g_q : (sel == 1) ? g_k : g_v;
    dst[(((size_t)(b * NH_ + h)) * T_ + t) * HD_ + d] = val;
}

// ---------------- Flash attention: TF32 mma.sync -------------------------------
#define FPAD 72

__global__ __launch_bounds__(128) void flash_kernel()
{
    extern __shared__ float sm[];
    float* Ks0 = sm;
    float* Ks1 = Ks0 + 64 * FPAD;
    float* Vs0 = Ks1 + 64 * FPAD;
    float* Vs1 = Vs0 + 64 * FPAD;

    const int tid = threadIdx.x;
    const int warp = tid >> 5;
    const int lane = tid & 31;
    const int rA = lane >> 2;
    const int cq = lane & 3;

    const int qt = (int)gridDim.x - 1 - (int)blockIdx.x;  // longest first
    const int bh = blockIdx.y;
    const int q0 = qt * 64;
    const int b = bh / NH_, h = bh % NH_;

    const float* Q = g_q + (size_t)bh * T_ * HD_;
    const float* K = g_k + (size_t)bh * T_ * HD_;
    const float* V = g_v + (size_t)bh * T_ * HD_;

    const int qrow = q0 + warp * 16 + rA;
    float qa[8][4];
#pragma unroll
    for (int kb = 0; kb < 8; kb++) {
        qa[kb][0] = Q[(size_t)qrow * HD_ + 8 * kb + cq];
        qa[kb][1] = Q[(size_t)(qrow + 8) * HD_ + 8 * kb + cq];
        qa[kb][2] = Q[(size_t)qrow * HD_ + 8 * kb + cq + 4];
        qa[kb][3] = Q[(size_t)(qrow + 8) * HD_ + 8 * kb + cq + 4];
    }

    float o[8][4];
#pragma unroll
    for (int i = 0; i < 8; i++)
#pragma unroll
        for (int j = 0; j < 4; j++) o[i][j] = 0.f;
    float mA = -1e30f, mB = -1e30f, lA = 0.f, lB = 0.f;

    auto issue_tile = [&](int kt, float* Ksb, float* Vsb) {
        const int k0 = kt * 64;
#pragma unroll
        for (int l = 0; l < 8; l++) {
            int slot = l * 128 + tid;
            int row = slot >> 4, ch = slot & 15;
            unsigned int dk = (unsigned int)__cvta_generic_to_shared(&Ksb[row * FPAD + ch * 4]);
            cp_async16(dk, &K[(size_t)(k0 + row) * HD_ + ch * 4]);
            unsigned int dv = (unsigned int)__cvta_generic_to_shared(&Vsb[row * FPAD + ch * 4]);
            cp_async16(dv, &V[(size_t)(k0 + row) * HD_ + ch * 4]);
        }
        cp_async_commit();
    };

    issue_tile(0, Ks0, Vs0);

    const int srcA = (lane & ~3) | (cq >> 1);
    const int srcB = srcA + 2;
    const bool par = (cq & 1);

    for (int kt = 0; kt <= qt; kt++) {
        float* Ks = (kt & 1) ? Ks1 : Ks0;
        float* Vs = (kt & 1) ? Vs1 : Vs0;
        const bool have_next = (kt < qt);
        if (have_next) {
            issue_tile(kt + 1, (kt & 1) ? Ks0 : Ks1, (kt & 1) ? Vs0 : Vs1);
            cp_async_wait1();
        } else {
            cp_async_wait0();
        }
        __syncthreads();

        float s[8][4];
#pragma unroll
        for (int nb = 0; nb < 8; nb++)
#pragma unroll
            for (int j = 0; j < 4; j++) s[nb][j] = 0.f;
#pragma unroll
        for (int kb = 0; kb < 8; kb++) {
#pragma unroll
            for (int nb = 0; nb < 8; nb++) {
                float b0 = Ks[(8 * nb + rA) * FPAD + 8 * kb + cq];
                float b1 = Ks[(8 * nb + rA) * FPAD + 8 * kb + cq + 4];
                mma_tf32(s[nb], qa[kb][0], qa[kb][1], qa[kb][2], qa[kb][3], b0, b1);
            }
        }

        if (kt == qt) {
            const int k0 = kt * 64;
#pragma unroll
            for (int nb = 0; nb < 8; nb++) {
                int col = k0 + 8 * nb + 2 * cq;
                if (col > qrow)     s[nb][0] = -1e30f;
                if (col + 1 > qrow) s[nb][1] = -1e30f;
                if (col > qrow + 8)     s[nb][2] = -1e30f;
                if (col + 1 > qrow + 8) s[nb][3] = -1e30f;
            }
        }

        float rmaxA = -1e30f, rmaxB = -1e30f;
#pragma unroll
        for (int nb = 0; nb < 8; nb++) {
            rmaxA = fmaxf(rmaxA, fmaxf(s[nb][0], s[nb][1]));
            rmaxB = fmaxf(rmaxB, fmaxf(s[nb][2], s[nb][3]));
        }
        rmaxA = fmaxf(rmaxA, __shfl_xor_sync(0xffffffffu, rmaxA, 1));
        rmaxA = fmaxf(rmaxA, __shfl_xor_sync(0xffffffffu, rmaxA, 2));
        rmaxB = fmaxf(rmaxB, __shfl_xor_sync(0xffffffffu, rmaxB, 1));
        rmaxB = fmaxf(rmaxB, __shfl_xor_sync(0xffffffffu, rmaxB, 2));

        float mnA = fmaxf(mA, rmaxA), mnB = fmaxf(mB, rmaxB);
        float alA = __expf(mA - mnA), alB = __expf(mB - mnB);
        mA = mnA; mB = mnB;

        float sumA = 0.f, sumB = 0.f;
#pragma unroll
        for (int nb = 0; nb < 8; nb++) {
            s[nb][0] = __expf(s[nb][0] - mA); sumA += s[nb][0];
            s[nb][1] = __expf(s[nb][1] - mA); sumA += s[nb][1];
            s[nb][2] = __expf(s[nb][2] - mB); sumB += s[nb][2];
            s[nb][3] = __expf(s[nb][3] - mB); sumB += s[nb][3];
        }
        sumA += __shfl_xor_sync(0xffffffffu, sumA, 1);
        sumA += __shfl_xor_sync(0xffffffffu, sumA, 2);
        sumB += __shfl_xor_sync(0xffffffffu, sumB, 1);
        sumB += __shfl_xor_sync(0xffffffffu, sumB, 2);
        lA = lA * alA + sumA;
        lB = lB * alB + sumB;

#pragma unroll
        for (int nb = 0; nb < 8; nb++) {
            o[nb][0] *= alA; o[nb][1] *= alA;
            o[nb][2] *= alB; o[nb][3] *= alB;
        }

#pragma unroll
        for (int nb = 0; nb < 8; nb++)
#pragma unroll
            for (int j = 0; j < 4; j++) s[nb][j] = f2tf32(s[nb][j]);

#pragma unroll
        for (int kb2 = 0; kb2 < 8; kb2++) {
            float t0, t1;
            t0 = __shfl_sync(0xffffffffu, s[kb2][0], srcA);
            t1 = __shfl_sync(0xffffffffu, s[kb2][1], srcA);
            float pa0 = par ? t1 : t0;
            t0 = __shfl_sync(0xffffffffu, s[kb2][0], srcB);
            t1 = __shfl_sync(0xffffffffu, s[kb2][1], srcB);
            float pa2 = par ? t1 : t0;
            t0 = __shfl_sync(0xffffffffu, s[kb2][2], srcA);
            t1 = __shfl_sync(0xffffffffu, s[kb2][3], srcA);
            float pa1 = par ? t1 : t0;
            t0 = __shfl_sync(0xffffffffu, s[kb2][2], srcB);
            t1 = __shfl_sync(0xffffffffu, s[kb2][3], srcB);
            float pa3 = par ? t1 : t0;

#pragma unroll
            for (int nb2 = 0; nb2 < 8; nb2++) {
                float b0 = Vs[(8 * kb2 + cq) * FPAD + 8 * nb2 + rA];
                float b1 = Vs[(8 * kb2 + cq + 4) * FPAD + 8 * nb2 + rA];
                mma_tf32(o[nb2], pa0, pa1, pa2, pa3, b0, b1);
            }
        }
        __syncthreads();
    }

    float invA = 1.f / lA, invB = 1.f / lB;
    const size_t rowA_off = ((size_t)(b * T_ + qrow)) * C_ + h * HD_;
    const size_t rowB_off = ((size_t)(b * T_ + qrow + 8)) * C_ + h * HD_;
#pragma unroll
    for (int nb2 = 0; nb2 < 8; nb2++) {
        int col = 8 * nb2 + 2 * cq;
        g_o[rowA_off + col]     = f2tf32(o[nb2][0] * invA);
        g_o[rowA_off + col + 1] = f2tf32(o[nb2][1] * invA);
        g_o[rowB_off + col]     = f2tf32(o[nb2][2] * invB);
        g_o[rowB_off + col + 1] = f2tf32(o[nb2][3] * invB);
    }
}

// ---------------- launch ------------------------------------------------------
extern "C" void kernel_launch(void* const* d_in, const int* in_sizes, int n_in,
                              void* d_out, int out_size)
{
    const float* x     = (const float*)d_in[0];
    const float* w_qkv = (const float*)d_in[1];
    const float* w_out = (const float*)d_in[2];
    float* out = (float*)d_out;

    float *qkv_p, *o_p;
    cudaGetSymbolAddress((void**)&qkv_p, g_qkv);
    cudaGetSymbolAddress((void**)&o_p, g_o);

    const int gsmem = 4 * 128 * TPAD * sizeof(float);
    cudaFuncSetAttribute(gemm_tf32_kernel, cudaFuncAttributeMaxDynamicSharedMemorySize, gsmem);

    // 1) QKV GEMM (tf32 MMA, in-register rounding)
    {
        dim3 grid(NQKV / 128, M_ / 128);
        gemm_tf32_kernel<<<grid, 256, gsmem>>>(x, w_qkv, qkv_p, M_, NQKV, C_);
    }

    // 2) RoPE + rearrange (+ tf32 rounding, q pre-scale)
    {
        long long total = 3LL * B_ * NH_ * T_ * HD_;
        int blocks = (int)((total + 255) / 256);
        rope_rearrange_kernel<<<blocks, 256>>>();
    }

    // 3) flash attention (tf32 tensor cores)
    {
        const int smem = 4 * 64 * FPAD * sizeof(float);
        cudaFuncSetAttribute(flash_kernel, cudaFuncAttributeMaxDynamicSharedMemorySize, smem);
        dim3 grid(T_ / 64, B_ * NH_);
        flash_kernel<<<grid, 128, smem>>>();
    }

    // 4) out projection (tf32 MMA)
    {
        dim3 grid(C_ / 128, M_ / 128);
        gemm_tf32_kernel<<<grid, 256, gsmem>>>(o_p, w_out, out, M_, C_, C_);
    }
}

// round 8
// speedup vs baseline: 3.5232x; 1.0237x over previous
#include <cuda_runtime.h>
#include <cuda_bf16.h>
#include <cstdint>
#include <math.h>

#define B_  4
#define T_  2048
#define C_  768
#define NH_ 12
#define HD_ 64
#define RD_ 16
#define M_  (B_ * T_)          // 8192
#define NQKV (3 * C_)          // 2304

// ---------------- scratch ----------------------------------------------------
__device__ float g_qkv[M_ * NQKV];               // [B*T, 2304]
__device__ float g_q[B_ * NH_ * T_ * HD_];       // tf32, pre-scaled
__device__ float g_k[B_ * NH_ * T_ * HD_];       // tf32
__device__ float g_v[B_ * NH_ * T_ * HD_];       // tf32
__device__ float g_o[M_ * C_];                   // attn out (tf32-rounded)
__device__ float g_wqr[NQKV * C_];               // w_qkv tf32-rounded
__device__ float g_wor[C_ * C_];                 // w_out tf32-rounded

// ---------------- helpers -----------------------------------------------------
__device__ __forceinline__ float f2tf32(float x) {
    unsigned u;
    asm("cvt.rna.tf32.f32 %0, %1;" : "=r"(u) : "f"(x));
    return __uint_as_float(u);
}

__device__ __forceinline__ void mma_tf32(float* c,
    float a0, float a1, float a2, float a3, float b0, float b1)
{
    asm volatile(
        "mma.sync.aligned.m16n8k8.row.col.f32.tf32.tf32.f32 "
        "{%0,%1,%2,%3}, {%4,%5,%6,%7}, {%8,%9}, {%0,%1,%2,%3};"
        : "+f"(c[0]), "+f"(c[1]), "+f"(c[2]), "+f"(c[3])
        : "r"(__float_as_uint(a0)), "r"(__float_as_uint(a1)),
          "r"(__float_as_uint(a2)), "r"(__float_as_uint(a3)),
          "r"(__float_as_uint(b0)), "r"(__float_as_uint(b1)));
}

__device__ __forceinline__ void cp_async16(unsigned int smem_addr, const void* gptr) {
    asm volatile("cp.async.ca.shared.global [%0], [%1], 16;\n"
                 :: "r"(smem_addr), "l"(gptr));
}
__device__ __forceinline__ void cp_async_commit() {
    asm volatile("cp.async.commit_group;\n" ::: "memory");
}
__device__ __forceinline__ void cp_async_wait0() {
    asm volatile("cp.async.wait_group 0;\n" ::: "memory");
}
__device__ __forceinline__ void cp_async_wait1() {
    asm volatile("cp.async.wait_group 1;\n" ::: "memory");
}

// ---------------- weight rounding prep -----------------------------------------
__global__ __launch_bounds__(256) void round_weights_kernel(
    const float* __restrict__ wq, const float* __restrict__ wo)
{
    int i = blockIdx.x * 256 + threadIdx.x;
    int stride = gridDim.x * 256;
    for (int j = i; j < NQKV * C_; j += stride) g_wqr[j] = f2tf32(wq[j]);
    for (int j = i; j < C_ * C_; j += stride)   g_wor[j] = f2tf32(wo[j]);
}

// ---------------- TF32 tensor-core GEMM: C = A @ B^T ---------------------------
// A raw fp32 (cvt in register); B pre-rounded tf32. BM=BN=128, BK=32.
#define TPAD 36

__global__ __launch_bounds__(256, 2) void gemm_tf32_kernel(
    const float* __restrict__ A, const float* __restrict__ Bm,
    float* __restrict__ C, int M, int N, int K)
{
    extern __shared__ float smg[];
    float* As0 = smg;                    // [128][36]
    float* As1 = As0 + 128 * TPAD;
    float* Bs0 = As1 + 128 * TPAD;
    float* Bs1 = Bs0 + 128 * TPAD;

    const int tid = threadIdx.x;
    const int warp = tid >> 5;
    const int lane = tid & 31;
    const int rA = lane >> 2;
    const int cq = lane & 3;
    const int warp_m = warp & 1;
    const int warp_n = warp >> 1;

    const int m0 = blockIdx.y * 128;
    const int n0 = blockIdx.x * 128;

    float acc[4][4][4];
#pragma unroll
    for (int a = 0; a < 4; a++)
#pragma unroll
        for (int b = 0; b < 4; b++)
#pragma unroll
            for (int c = 0; c < 4; c++) acc[a][b][c] = 0.f;

    auto issue = [&](int k0, float* Asb, float* Bsb) {
#pragma unroll
        for (int l = 0; l < 4; l++) {
            int slot = l * 256 + tid;
            int row = slot >> 3, ch = slot & 7;
            unsigned int da = (unsigned int)__cvta_generic_to_shared(&Asb[row * TPAD + ch * 4]);
            cp_async16(da, &A[(size_t)(m0 + row) * K + k0 + ch * 4]);
            unsigned int db = (unsigned int)__cvta_generic_to_shared(&Bsb[row * TPAD + ch * 4]);
            cp_async16(db, &Bm[(size_t)(n0 + row) * K + k0 + ch * 4]);
        }
        cp_async_commit();
    };

    const int niter = K / 32;
    issue(0, As0, Bs0);

    for (int it = 0; it < niter; it++) {
        float* As = (it & 1) ? As1 : As0;
        float* Bs = (it & 1) ? Bs1 : Bs0;
        if (it + 1 < niter) {
            issue((it + 1) * 32, (it & 1) ? As0 : As1, (it & 1) ? Bs0 : Bs1);
            cp_async_wait1();
        } else {
            cp_async_wait0();
        }
        __syncthreads();

#pragma unroll
        for (int ks = 0; ks < 4; ks++) {
            const int k = ks * 8;
            float af[4][4];
#pragma unroll
            for (int mb = 0; mb < 4; mb++) {
                int row = warp_m * 64 + mb * 16 + rA;
                af[mb][0] = f2tf32(As[row * TPAD + k + cq]);
                af[mb][1] = f2tf32(As[(row + 8) * TPAD + k + cq]);
                af[mb][2] = f2tf32(As[row * TPAD + k + cq + 4]);
                af[mb][3] = f2tf32(As[(row + 8) * TPAD + k + cq + 4]);
            }
            float bf[4][2];
#pragma unroll
            for (int nb = 0; nb < 4; nb++) {
                int n = warp_n * 32 + nb * 8 + rA;
                bf[nb][0] = Bs[n * TPAD + k + cq];       // pre-rounded
                bf[nb][1] = Bs[n * TPAD + k + cq + 4];
            }
#pragma unroll
            for (int mb = 0; mb < 4; mb++)
#pragma unroll
                for (int nb = 0; nb < 4; nb++)
                    mma_tf32(acc[mb][nb], af[mb][0], af[mb][1], af[mb][2], af[mb][3],
                             bf[nb][0], bf[nb][1]);
        }
        __syncthreads();
    }

#pragma unroll
    for (int mb = 0; mb < 4; mb++) {
        int row = m0 + warp_m * 64 + mb * 16 + rA;
#pragma unroll
        for (int nb = 0; nb < 4; nb++) {
            int col = n0 + warp_n * 32 + nb * 8 + 2 * cq;
            *(float2*)&C[(size_t)row * N + col] =
                make_float2(acc[mb][nb][0], acc[mb][nb][1]);
            *(float2*)&C[(size_t)(row + 8) * N + col] =
                make_float2(acc[mb][nb][2], acc[mb][nb][3]);
        }
    }
}

// ---------------- RoPE + rearrange + tf32 rounding ----------------------------
__global__ __launch_bounds__(256) void rope_rearrange_kernel()
{
    const long long total = 3LL * B_ * NH_ * T_ * HD_;
    long long idx = (long long)blockIdx.x * blockDim.x + threadIdx.x;
    if (idx >= total) return;

    int d = (int)(idx & 63);
    long long r = idx >> 6;
    int t = (int)(r % T_); r /= T_;
    int h = (int)(r % NH_); r /= NH_;
    int b = (int)(r % B_);
    int sel = (int)(r / B_);

    const size_t srow = ((size_t)(b * T_ + t)) * NQKV + sel * C_ + h * HD_;
    float val = g_qkv[srow + d];

    if (sel < 2 && d < RD_) {
        int j = (d < 8) ? d : d - 8;
        float freq = __powf(10000.0f, -(float)j / 8.0f);
        float ang = (float)t * freq;
        float c = cosf(ang), s = sinf(ang);
        if (d < 8) {
            float r2 = g_qkv[srow + d + 8];
            val = val * c - r2 * s;
        } else {
            float r1 = g_qkv[srow + d - 8];
            val = val * c + r1 * s;
        }
    }

    if (sel == 0) val *= 0.125f;
    val = f2tf32(val);

    float* dst = (sel == 0) ? g_q : (sel == 1) ? g_k : g_v;
    dst[(((size_t)(b * NH_ + h)) * T_ + t) * HD_ + d] = val;
}

// ---------------- Flash attention: TF32 mma.sync, FQ=128 -----------------------
// 256 threads = 8 warps, warp w owns q rows [q0+16w, q0+16w+16).
// K/V tiles 64x64, double-buffered cp.async.
#define FPAD 72

__global__ __launch_bounds__(256) void flash_kernel()
{
    extern __shared__ float sm[];
    float* Ks0 = sm;
    float* Ks1 = Ks0 + 64 * FPAD;
    float* Vs0 = Ks1 + 64 * FPAD;
    float* Vs1 = Vs0 + 64 * FPAD;

    const int tid = threadIdx.x;
    const int warp = tid >> 5;
    const int lane = tid & 31;
    const int rA = lane >> 2;
    const int cq = lane & 3;

    const int qt = (int)gridDim.x - 1 - (int)blockIdx.x;  // longest first
    const int bh = blockIdx.y;
    const int q0 = qt * 128;
    const int b = bh / NH_, h = bh % NH_;

    const float* Q = g_q + (size_t)bh * T_ * HD_;
    const float* K = g_k + (size_t)bh * T_ * HD_;
    const float* V = g_v + (size_t)bh * T_ * HD_;

    const int qrow = q0 + warp * 16 + rA;
    float qa[8][4];
#pragma unroll
    for (int kb = 0; kb < 8; kb++) {
        qa[kb][0] = Q[(size_t)qrow * HD_ + 8 * kb + cq];
        qa[kb][1] = Q[(size_t)(qrow + 8) * HD_ + 8 * kb + cq];
        qa[kb][2] = Q[(size_t)qrow * HD_ + 8 * kb + cq + 4];
        qa[kb][3] = Q[(size_t)(qrow + 8) * HD_ + 8 * kb + cq + 4];
    }

    float o[8][4];
#pragma unroll
    for (int i = 0; i < 8; i++)
#pragma unroll
        for (int j = 0; j < 4; j++) o[i][j] = 0.f;
    float mA = -1e30f, mB = -1e30f, lA = 0.f, lB = 0.f;

    auto issue_tile = [&](int kt, float* Ksb, float* Vsb) {
        const int k0 = kt * 64;
#pragma unroll
        for (int l = 0; l < 4; l++) {
            int slot = l * 256 + tid;           // 0..1023
            int row = slot >> 4, ch = slot & 15;
            unsigned int dk = (unsigned int)__cvta_generic_to_shared(&Ksb[row * FPAD + ch * 4]);
            cp_async16(dk, &K[(size_t)(k0 + row) * HD_ + ch * 4]);
            unsigned int dv = (unsigned int)__cvta_generic_to_shared(&Vsb[row * FPAD + ch * 4]);
            cp_async16(dv, &V[(size_t)(k0 + row) * HD_ + ch * 4]);
        }
        cp_async_commit();
    };

    issue_tile(0, Ks0, Vs0);

    const int srcA = (lane & ~3) | (cq >> 1);
    const int srcB = srcA + 2;
    const bool par = (cq & 1);

    const int ktiles = 2 * qt + 2;              // k rows [0, q0+128)
    for (int kt = 0; kt < ktiles; kt++) {
        float* Ks = (kt & 1) ? Ks1 : Ks0;
        float* Vs = (kt & 1) ? Vs1 : Vs0;
        const bool have_next = (kt + 1 < ktiles);
        if (have_next) {
            issue_tile(kt + 1, (kt & 1) ? Ks0 : Ks1, (kt & 1) ? Vs0 : Vs1);
            cp_async_wait1();
        } else {
            cp_async_wait0();
        }
        __syncthreads();

        float s[8][4];
#pragma unroll
        for (int nb = 0; nb < 8; nb++)
#pragma unroll
            for (int j = 0; j < 4; j++) s[nb][j] = 0.f;
#pragma unroll
        for (int kb = 0; kb < 8; kb++) {
#pragma unroll
            for (int nb = 0; nb < 8; nb++) {
                float b0 = Ks[(8 * nb + rA) * FPAD + 8 * kb + cq];
                float b1 = Ks[(8 * nb + rA) * FPAD + 8 * kb + cq + 4];
                mma_tf32(s[nb], qa[kb][0], qa[kb][1], qa[kb][2], qa[kb][3], b0, b1);
            }
        }

        // causal mask for tiles that can cross this thread's rows
        const int k0 = kt * 64;
        if (k0 + 63 > qrow) {
#pragma unroll
            for (int nb = 0; nb < 8; nb++) {
                int col = k0 + 8 * nb + 2 * cq;
                if (col > qrow)     s[nb][0] = -1e30f;
                if (col + 1 > qrow) s[nb][1] = -1e30f;
                if (col > qrow + 8)     s[nb][2] = -1e30f;
                if (col + 1 > qrow + 8) s[nb][3] = -1e30f;
            }
        }

        float rmaxA = -1e30f, rmaxB = -1e30f;
#pragma unroll
        for (int nb = 0; nb < 8; nb++) {
            rmaxA = fmaxf(rmaxA, fmaxf(s[nb][0], s[nb][1]));
            rmaxB = fmaxf(rmaxB, fmaxf(s[nb][2], s[nb][3]));
        }
        rmaxA = fmaxf(rmaxA, __shfl_xor_sync(0xffffffffu, rmaxA, 1));
        rmaxA = fmaxf(rmaxA, __shfl_xor_sync(0xffffffffu, rmaxA, 2));
        rmaxB = fmaxf(rmaxB, __shfl_xor_sync(0xffffffffu, rmaxB, 1));
        rmaxB = fmaxf(rmaxB, __shfl_xor_sync(0xffffffffu, rmaxB, 2));

        float mnA = fmaxf(mA, rmaxA), mnB = fmaxf(mB, rmaxB);
        float alA = __expf(mA - mnA), alB = __expf(mB - mnB);
        mA = mnA; mB = mnB;

        float sumA = 0.f, sumB = 0.f;
#pragma unroll
        for (int nb = 0; nb < 8; nb++) {
            s[nb][0] = __expf(s[nb][0] - mA); sumA += s[nb][0];
            s[nb][1] = __expf(s[nb][1] - mA); sumA += s[nb][1];
            s[nb][2] = __expf(s[nb][2] - mB); sumB += s[nb][2];
            s[nb][3] = __expf(s[nb][3] - mB); sumB += s[nb][3];
        }
        sumA += __shfl_xor_sync(0xffffffffu, sumA, 1);
        sumA += __shfl_xor_sync(0xffffffffu, sumA, 2);
        sumB += __shfl_xor_sync(0xffffffffu, sumB, 1);
        sumB += __shfl_xor_sync(0xffffffffu, sumB, 2);
        lA = lA * alA + sumA;
        lB = lB * alB + sumB;

#pragma unroll
        for (int nb = 0; nb < 8; nb++) {
            o[nb][0] *= alA; o[nb][1] *= alA;
            o[nb][2] *= alB; o[nb][3] *= alB;
        }

#pragma unroll
        for (int nb = 0; nb < 8; nb++)
#pragma unroll
            for (int j = 0; j < 4; j++) s[nb][j] = f2tf32(s[nb][j]);

#pragma unroll
        for (int kb2 = 0; kb2 < 8; kb2++) {
            float t0, t1;
            t0 = __shfl_sync(0xffffffffu, s[kb2][0], srcA);
            t1 = __shfl_sync(0xffffffffu, s[kb2][1], srcA);
            float pa0 = par ? t1 : t0;
            t0 = __shfl_sync(0xffffffffu, s[kb2][0], srcB);
            t1 = __shfl_sync(0xffffffffu, s[kb2][1], srcB);
            float pa2 = par ? t1 : t0;
            t0 = __shfl_sync(0xffffffffu, s[kb2][2], srcA);
            t1 = __shfl_sync(0xffffffffu, s[kb2][3], srcA);
            float pa1 = par ? t1 : t0;
            t0 = __shfl_sync(0xffffffffu, s[kb2][2], srcB);
            t1 = __shfl_sync(0xffffffffu, s[kb2][3], srcB);
            float pa3 = par ? t1 : t0;

#pragma unroll
            for (int nb2 = 0; nb2 < 8; nb2++) {
                float b0 = Vs[(8 * kb2 + cq) * FPAD + 8 * nb2 + rA];
                float b1 = Vs[(8 * kb2 + cq + 4) * FPAD + 8 * nb2 + rA];
                mma_tf32(o[nb2], pa0, pa1, pa2, pa3, b0, b1);
            }
        }
        __syncthreads();
    }

    float invA = 1.f / lA, invB = 1.f / lB;
    const size_t rowA_off = ((size_t)(b * T_ + qrow)) * C_ + h * HD_;
    const size_t rowB_off = ((size_t)(b * T_ + qrow + 8)) * C_ + h * HD_;
#pragma unroll
    for (int nb2 = 0; nb2 < 8; nb2++) {
        int col = 8 * nb2 + 2 * cq;
        g_o[rowA_off + col]     = f2tf32(o[nb2][0] * invA);
        g_o[rowA_off + col + 1] = f2tf32(o[nb2][1] * invA);
        g_o[rowB_off + col]     = f2tf32(o[nb2][2] * invB);
        g_o[rowB_off + col + 1] = f2tf32(o[nb2][3] * invB);
    }
}

// ---------------- launch ------------------------------------------------------
extern "C" void kernel_launch(void* const* d_in, const int* in_sizes, int n_in,
                              void* d_out, int out_size)
{
    const float* x     = (const float*)d_in[0];
    const float* w_qkv = (const float*)d_in[1];
    const float* w_out = (const float*)d_in[2];
    float* out = (float*)d_out;

    float *qkv_p, *o_p, *wqr_p, *wor_p;
    cudaGetSymbolAddress((void**)&qkv_p, g_qkv);
    cudaGetSymbolAddress((void**)&o_p, g_o);
    cudaGetSymbolAddress((void**)&wqr_p, g_wqr);
    cudaGetSymbolAddress((void**)&wor_p, g_wor);

    // 0) round weights to tf32 (tiny, reused by both GEMMs)
    round_weights_kernel<<<512, 256>>>(w_qkv, w_out);

    const int gsmem = 4 * 128 * TPAD * sizeof(float);
    cudaFuncSetAttribute(gemm_tf32_kernel, cudaFuncAttributeMaxDynamicSharedMemorySize, gsmem);

    // 1) QKV GEMM
    {
        dim3 grid(NQKV / 128, M_ / 128);
        gemm_tf32_kernel<<<grid, 256, gsmem>>>(x, wqr_p, qkv_p, M_, NQKV, C_);
    }

    // 2) RoPE + rearrange
    {
        long long total = 3LL * B_ * NH_ * T_ * HD_;
        int blocks = (int)((total + 255) / 256);
        rope_rearrange_kernel<<<blocks, 256>>>();
    }

    // 3) flash attention (FQ=128, 8 warps)
    {
        const int smem = 4 * 64 * FPAD * sizeof(float);
        cudaFuncSetAttribute(flash_kernel, cudaFuncAttributeMaxDynamicSharedMemorySize, smem);
        dim3 grid(T_ / 128, B_ * NH_);
        flash_kernel<<<grid, 256, smem>>>();
    }

    // 4) out projection
    {
        dim3 grid(C_ / 128, M_ / 128);
        gemm_tf32_kernel<<<grid, 256, gsmem>>>(o_p, wor_p, out, M_, C_, C_);
    }
}

// round 9
// speedup vs baseline: 3.9292x; 1.1152x over previous
#include <cuda_runtime.h>
#include <cuda_bf16.h>
#include <cstdint>
#include <math.h>

#define B_  4
#define T_  2048
#define C_  768
#define NH_ 12
#define HD_ 64
#define RD_ 16
#define M_  (B_ * T_)          // 8192
#define NQKV (3 * C_)          // 2304

// ---------------- scratch ----------------------------------------------------
__device__ float g_qkv[M_ * NQKV];               // [B*T, 2304]
__device__ float g_qf[B_ * NH_ * T_ * HD_];      // Q, fragment order, tf32, pre-scaled
__device__ float g_kf[B_ * NH_ * T_ * HD_];      // K, fragment order, tf32
__device__ float g_vf[B_ * NH_ * T_ * HD_];      // V, fragment order, tf32
__device__ float g_o[M_ * C_];                   // attn out (tf32-rounded)
__device__ float g_wqr[NQKV * C_];               // w_qkv tf32-rounded
__device__ float g_wor[C_ * C_];                 // w_out tf32-rounded

// ---------------- helpers -----------------------------------------------------
__device__ __forceinline__ float f2tf32(float x) {
    unsigned u;
    asm("cvt.rna.tf32.f32 %0, %1;" : "=r"(u) : "f"(x));
    return __uint_as_float(u);
}

__device__ __forceinline__ void mma_tf32(float* c,
    float a0, float a1, float a2, float a3, float b0, float b1)
{
    asm volatile(
        "mma.sync.aligned.m16n8k8.row.col.f32.tf32.tf32.f32 "
        "{%0,%1,%2,%3}, {%4,%5,%6,%7}, {%8,%9}, {%0,%1,%2,%3};"
        : "+f"(c[0]), "+f"(c[1]), "+f"(c[2]), "+f"(c[3])
        : "r"(__float_as_uint(a0)), "r"(__float_as_uint(a1)),
          "r"(__float_as_uint(a2)), "r"(__float_as_uint(a3)),
          "r"(__float_as_uint(b0)), "r"(__float_as_uint(b1)));
}

__device__ __forceinline__ void cp_async16(unsigned int smem_addr, const void* gptr) {
    asm volatile("cp.async.ca.shared.global [%0], [%1], 16;\n"
                 :: "r"(smem_addr), "l"(gptr));
}
__device__ __forceinline__ void cp_async_commit() {
    asm volatile("cp.async.commit_group;\n" ::: "memory");
}
__device__ __forceinline__ void cp_async_wait0() {
    asm volatile("cp.async.wait_group 0;\n" ::: "memory");
}
__device__ __forceinline__ void cp_async_wait1() {
    asm volatile("cp.async.wait_group 1;\n" ::: "memory");
}

// ---------------- weight rounding prep -----------------------------------------
__global__ __launch_bounds__(256) void round_weights_kernel(
    const float* __restrict__ wq, const float* __restrict__ wo)
{
    int i = blockIdx.x * 256 + threadIdx.x;
    int stride = gridDim.x * 256;
    for (int j = i; j < NQKV * C_; j += stride) g_wqr[j] = f2tf32(wq[j]);
    for (int j = i; j < C_ * C_; j += stride)   g_wor[j] = f2tf32(wo[j]);
}

// ---------------- TF32 tensor-core GEMM: C = A @ B^T ---------------------------
#define TPAD 36

__global__ __launch_bounds__(256, 2) void gemm_tf32_kernel(
    const float* __restrict__ A, const float* __restrict__ Bm,
    float* __restrict__ C, int M, int N, int K)
{
    extern __shared__ float smg[];
    float* As0 = smg;
    float* As1 = As0 + 128 * TPAD;
    float* Bs0 = As1 + 128 * TPAD;
    float* Bs1 = Bs0 + 128 * TPAD;

    const int tid = threadIdx.x;
    const int warp = tid >> 5;
    const int lane = tid & 31;
    const int rA = lane >> 2;
    const int cq = lane & 3;
    const int warp_m = warp & 1;
    const int warp_n = warp >> 1;

    const int m0 = blockIdx.y * 128;
    const int n0 = blockIdx.x * 128;

    float acc[4][4][4];
#pragma unroll
    for (int a = 0; a < 4; a++)
#pragma unroll
        for (int b = 0; b < 4; b++)
#pragma unroll
            for (int c = 0; c < 4; c++) acc[a][b][c] = 0.f;

    auto issue = [&](int k0, float* Asb, float* Bsb) {
#pragma unroll
        for (int l = 0; l < 4; l++) {
            int slot = l * 256 + tid;
            int row = slot >> 3, ch = slot & 7;
            unsigned int da = (unsigned int)__cvta_generic_to_shared(&Asb[row * TPAD + ch * 4]);
            cp_async16(da, &A[(size_t)(m0 + row) * K + k0 + ch * 4]);
            unsigned int db = (unsigned int)__cvta_generic_to_shared(&Bsb[row * TPAD + ch * 4]);
            cp_async16(db, &Bm[(size_t)(n0 + row) * K + k0 + ch * 4]);
        }
        cp_async_commit();
    };

    const int niter = K / 32;
    issue(0, As0, Bs0);

    for (int it = 0; it < niter; it++) {
        float* As = (it & 1) ? As1 : As0;
        float* Bs = (it & 1) ? Bs1 : Bs0;
        if (it + 1 < niter) {
            issue((it + 1) * 32, (it & 1) ? As0 : As1, (it & 1) ? Bs0 : Bs1);
            cp_async_wait1();
        } else {
            cp_async_wait0();
        }
        __syncthreads();

#pragma unroll
        for (int ks = 0; ks < 4; ks++) {
            const int k = ks * 8;
            float af[4][4];
#pragma unroll
            for (int mb = 0; mb < 4; mb++) {
                int row = warp_m * 64 + mb * 16 + rA;
                af[mb][0] = f2tf32(As[row * TPAD + k + cq]);
                af[mb][1] = f2tf32(As[(row + 8) * TPAD + k + cq]);
                af[mb][2] = f2tf32(As[row * TPAD + k + cq + 4]);
                af[mb][3] = f2tf32(As[(row + 8) * TPAD + k + cq + 4]);
            }
            float bf[4][2];
#pragma unroll
            for (int nb = 0; nb < 4; nb++) {
                int n = warp_n * 32 + nb * 8 + rA;
                bf[nb][0] = Bs[n * TPAD + k + cq];
                bf[nb][1] = Bs[n * TPAD + k + cq + 4];
            }
#pragma unroll
            for (int mb = 0; mb < 4; mb++)
#pragma unroll
                for (int nb = 0; nb < 4; nb++)
                    mma_tf32(acc[mb][nb], af[mb][0], af[mb][1], af[mb][2], af[mb][3],
                             bf[nb][0], bf[nb][1]);
        }
        __syncthreads();
    }

#pragma unroll
    for (int mb = 0; mb < 4; mb++) {
        int row = m0 + warp_m * 64 + mb * 16 + rA;
#pragma unroll
        for (int nb = 0; nb < 4; nb++) {
            int col = n0 + warp_n * 32 + nb * 8 + 2 * cq;
            *(float2*)&C[(size_t)row * N + col] =
                make_float2(acc[mb][nb][0], acc[mb][nb][1]);
            *(float2*)&C[(size_t)(row + 8) * N + col] =
                make_float2(acc[mb][nb][2], acc[mb][nb][3]);
        }
    }
}

// ---------------- RoPE + rearrange into FRAGMENT layouts ----------------------
// Q frag: value(a-reg) = Q[16g + hi*8 + rA][8kb + cq + 4*reg]
//   off = ((bh*128 + g)*8 + kb)*128 + (rA*4+cq)*4 + hi + 2*reg
// K frag (per 64-row tile kt): b-reg = K[kt*64 + 8nb + rA][8kb + cq + 4*reg]
//   off = (bh*32+kt)*4096 + ((nb*4 + kb/2)*32 + rA*4+cq)*4 + (kb&1)*2 + reg
// V frag: b-reg = V[kt*64 + 8kb2 + cq + 4*reg][8nb2 + rA]
//   off = (bh*32+kt)*4096 + ((kb2*4 + nb2/2)*32 + rA*4+cq)*4 + (nb2&1)*2 + reg
__global__ __launch_bounds__(256) void rope_rearrange_kernel()
{
    const long long total = 3LL * B_ * NH_ * T_ * HD_;
    long long idx = (long long)blockIdx.x * blockDim.x + threadIdx.x;
    if (idx >= total) return;

    int d = (int)(idx & 63);
    long long r = idx >> 6;
    int t = (int)(r % T_); r /= T_;
    int h = (int)(r % NH_); r /= NH_;
    int b = (int)(r % B_);
    int sel = (int)(r / B_);

    const size_t srow = ((size_t)(b * T_ + t)) * NQKV + sel * C_ + h * HD_;
    float val = g_qkv[srow + d];

    if (sel < 2 && d < RD_) {
        int j = (d < 8) ? d : d - 8;
        float freq = __powf(10000.0f, -(float)j / 8.0f);
        float ang = (float)t * freq;
        float c = cosf(ang), s = sinf(ang);
        if (d < 8) {
            float r2 = g_qkv[srow + d + 8];
            val = val * c - r2 * s;
        } else {
            float r1 = g_qkv[srow + d - 8];
            val = val * c + r1 * s;
        }
    }

    if (sel == 0) val *= 0.125f;
    val = f2tf32(val);

    const int bh = b * NH_ + h;
    if (sel == 0) {
        int g = t >> 4, tl = t & 15;
        int hi = tl >> 3, rA = tl & 7;
        int kb = d >> 3, c = d & 7, reg = c >> 2, cq = c & 3;
        size_t off = (((size_t)bh * 128 + g) * 8 + kb) * 128 + (rA * 4 + cq) * 4 + hi + 2 * reg;
        g_qf[off] = val;
    } else if (sel == 1) {
        int kt = t >> 6, tl = t & 63;
        int nb = tl >> 3, rA = tl & 7;
        int kb = d >> 3, c = d & 7, reg = c >> 2, cq = c & 3;
        size_t off = ((size_t)bh * 32 + kt) * 4096
                   + ((nb * 4 + (kb >> 1)) * 32 + rA * 4 + cq) * 4 + (kb & 1) * 2 + reg;
        g_kf[off] = val;
    } else {
        int kt = t >> 6, tl = t & 63;
        int kb2 = tl >> 3, c = tl & 7, reg = c >> 2, cq = c & 3;
        int nb2 = d >> 3, rA = d & 7;
        size_t off = ((size_t)bh * 32 + kt) * 4096
                   + ((kb2 * 4 + (nb2 >> 1)) * 32 + rA * 4 + cq) * 4 + (nb2 & 1) * 2 + reg;
        g_vf[off] = val;
    }
}

// ---------------- Flash attention: TF32 mma.sync, fragment-order smem ----------
// 256 threads = 8 warps, FQ=128, K/V tiles 64 rows, double-buffered cp.async.
// smem tiles are raw fragment streams: 1024 float4 per tile.
__global__ __launch_bounds__(256) void flash_kernel()
{
    extern __shared__ float4 smf[];
    float4* Ksf0 = smf;                 // 1024 float4
    float4* Ksf1 = Ksf0 + 1024;
    float4* Vsf0 = Ksf1 + 1024;
    float4* Vsf1 = Vsf0 + 1024;

    const int tid = threadIdx.x;
    const int warp = tid >> 5;
    const int lane = tid & 31;
    const int rA = lane >> 2;
    const int cq = lane & 3;

    const int qt = (int)gridDim.x - 1 - (int)blockIdx.x;  // longest first
    const int bh = blockIdx.y;
    const int q0 = qt * 128;

    const int b = bh / NH_, h = bh % NH_;
    const int qrow = q0 + warp * 16 + rA;

    // Q fragments: 8 x LDG.128
    const float4* Qf = (const float4*)g_qf;
    float qa[8][4];
#pragma unroll
    for (int kb = 0; kb < 8; kb++) {
        float4 f = Qf[(((size_t)bh * 128 + 8 * qt + warp) * 8 + kb) * 32 + lane];
        qa[kb][0] = f.x; qa[kb][1] = f.y; qa[kb][2] = f.z; qa[kb][3] = f.w;
    }

    float o[8][4];
#pragma unroll
    for (int i = 0; i < 8; i++)
#pragma unroll
        for (int j = 0; j < 4; j++) o[i][j] = 0.f;
    float mA = -1e30f, mB = -1e30f, lA = 0.f, lB = 0.f;

    const float4* Kf = (const float4*)g_kf;
    const float4* Vf = (const float4*)g_vf;

    auto issue_tile = [&](int kt, float4* Ksb, float4* Vsb) {
        const size_t tb = ((size_t)bh * 32 + kt) * 1024;
#pragma unroll
        for (int l = 0; l < 4; l++) {
            int slot = l * 256 + tid;           // 0..1023
            unsigned int dk = (unsigned int)__cvta_generic_to_shared(&Ksb[slot]);
            cp_async16(dk, &Kf[tb + slot]);
            unsigned int dv = (unsigned int)__cvta_generic_to_shared(&Vsb[slot]);
            cp_async16(dv, &Vf[tb + slot]);
        }
        cp_async_commit();
    };

    issue_tile(0, Ksf0, Vsf0);

    const int srcA = (lane & ~3) | (cq >> 1);
    const int srcB = srcA + 2;
    const bool par = (cq & 1);

    const int ktiles = 2 * qt + 2;
    for (int kt = 0; kt < ktiles; kt++) {
        float4* Ksf = (kt & 1) ? Ksf1 : Ksf0;
        float4* Vsf = (kt & 1) ? Vsf1 : Vsf0;
        const bool have_next = (kt + 1 < ktiles);
        if (have_next) {
            issue_tile(kt + 1, (kt & 1) ? Ksf0 : Ksf1, (kt & 1) ? Vsf0 : Vsf1);
            cp_async_wait1();
        } else {
            cp_async_wait0();
        }
        __syncthreads();

        // --- S = Q K^T : fragment float4 = B-frags of two consecutive kb ---
        float s[8][4];
#pragma unroll
        for (int nb = 0; nb < 8; nb++)
#pragma unroll
            for (int j = 0; j < 4; j++) s[nb][j] = 0.f;
#pragma unroll
        for (int kbp = 0; kbp < 4; kbp++) {
#pragma unroll
            for (int nb = 0; nb < 8; nb++) {
                float4 f = Ksf[(nb * 4 + kbp) * 32 + lane];
                mma_tf32(s[nb], qa[2 * kbp][0], qa[2 * kbp][1], qa[2 * kbp][2], qa[2 * kbp][3], f.x, f.y);
                mma_tf32(s[nb], qa[2 * kbp + 1][0], qa[2 * kbp + 1][1], qa[2 * kbp + 1][2], qa[2 * kbp + 1][3], f.z, f.w);
            }
        }

        // causal mask
        const int k0 = kt * 64;
        if (k0 + 63 > qrow) {
#pragma unroll
            for (int nb = 0; nb < 8; nb++) {
                int col = k0 + 8 * nb + 2 * cq;
                if (col > qrow)     s[nb][0] = -1e30f;
                if (col + 1 > qrow) s[nb][1] = -1e30f;
                if (col > qrow + 8)     s[nb][2] = -1e30f;
                if (col + 1 > qrow + 8) s[nb][3] = -1e30f;
            }
        }

        // online softmax
        float rmaxA = -1e30f, rmaxB = -1e30f;
#pragma unroll
        for (int nb = 0; nb < 8; nb++) {
            rmaxA = fmaxf(rmaxA, fmaxf(s[nb][0], s[nb][1]));
            rmaxB = fmaxf(rmaxB, fmaxf(s[nb][2], s[nb][3]));
        }
        rmaxA = fmaxf(rmaxA, __shfl_xor_sync(0xffffffffu, rmaxA, 1));
        rmaxA = fmaxf(rmaxA, __shfl_xor_sync(0xffffffffu, rmaxA, 2));
        rmaxB = fmaxf(rmaxB, __shfl_xor_sync(0xffffffffu, rmaxB, 1));
        rmaxB = fmaxf(rmaxB, __shfl_xor_sync(0xffffffffu, rmaxB, 2));

        float mnA = fmaxf(mA, rmaxA), mnB = fmaxf(mB, rmaxB);
        float alA = __expf(mA - mnA), alB = __expf(mB - mnB);
        mA = mnA; mB = mnB;

        float sumA = 0.f, sumB = 0.f;
#pragma unroll
        for (int nb = 0; nb < 8; nb++) {
            s[nb][0] = __expf(s[nb][0] - mA); sumA += s[nb][0];
            s[nb][1] = __expf(s[nb][1] - mA); sumA += s[nb][1];
            s[nb][2] = __expf(s[nb][2] - mB); sumB += s[nb][2];
            s[nb][3] = __expf(s[nb][3] - mB); sumB += s[nb][3];
        }
        sumA += __shfl_xor_sync(0xffffffffu, sumA, 1);
        sumA += __shfl_xor_sync(0xffffffffu, sumA, 2);
        sumB += __shfl_xor_sync(0xffffffffu, sumB, 1);
        sumB += __shfl_xor_sync(0xffffffffu, sumB, 2);
        lA = lA * alA + sumA;
        lB = lB * alB + sumB;

#pragma unroll
        for (int nb = 0; nb < 8; nb++) {
            o[nb][0] *= alA; o[nb][1] *= alA;
            o[nb][2] *= alB; o[nb][3] *= alB;
        }

#pragma unroll
        for (int nb = 0; nb < 8; nb++)
#pragma unroll
            for (int j = 0; j < 4; j++) s[nb][j] = f2tf32(s[nb][j]);

        // --- O += P V : float4 = V-frags of two consecutive nb2 ---
#pragma unroll
        for (int kb2 = 0; kb2 < 8; kb2++) {
            float t0, t1;
            t0 = __shfl_sync(0xffffffffu, s[kb2][0], srcA);
            t1 = __shfl_sync(0xffffffffu, s[kb2][1], srcA);
            float pa0 = par ? t1 : t0;
            t0 = __shfl_sync(0xffffffffu, s[kb2][0], srcB);
            t1 = __shfl_sync(0xffffffffu, s[kb2][1], srcB);
            float pa2 = par ? t1 : t0;
            t0 = __shfl_sync(0xffffffffu, s[kb2][2], srcA);
            t1 = __shfl_sync(0xffffffffu, s[kb2][3], srcA);
            float pa1 = par ? t1 : t0;
            t0 = __shfl_sync(0xffffffffu, s[kb2][2], srcB);
            t1 = __shfl_sync(0xffffffffu, s[kb2][3], srcB);
            float pa3 = par ? t1 : t0;

#pragma unroll
            for (int nb2p = 0; nb2p < 4; nb2p++) {
                float4 f = Vsf[(kb2 * 4 + nb2p) * 32 + lane];
                mma_tf32(o[2 * nb2p],     pa0, pa1, pa2, pa3, f.x, f.y);
                mma_tf32(o[2 * nb2p + 1], pa0, pa1, pa2, pa3, f.z, f.w);
            }
        }
        __syncthreads();
    }

    // epilogue
    float invA = 1.f / lA, invB = 1.f / lB;
    const size_t rowA_off = ((size_t)(b * T_ + qrow)) * C_ + h * HD_;
    const size_t rowB_off = ((size_t)(b * T_ + qrow + 8)) * C_ + h * HD_;
#pragma unroll
    for (int nb2 = 0; nb2 < 8; nb2++) {
        int col = 8 * nb2 + 2 * cq;
        g_o[rowA_off + col]     = f2tf32(o[nb2][0] * invA);
        g_o[rowA_off + col + 1] = f2tf32(o[nb2][1] * invA);
        g_o[rowB_off + col]     = f2tf32(o[nb2][2] * invB);
        g_o[rowB_off + col + 1] = f2tf32(o[nb2][3] * invB);
    }
}

// ---------------- launch ------------------------------------------------------
extern "C" void kernel_launch(void* const* d_in, const int* in_sizes, int n_in,
                              void* d_out, int out_size)
{
    const float* x     = (const float*)d_in[0];
    const float* w_qkv = (const float*)d_in[1];
    const float* w_out = (const float*)d_in[2];
    float* out = (float*)d_out;

    float *qkv_p, *o_p, *wqr_p, *wor_p;
    cudaGetSymbolAddress((void**)&qkv_p, g_qkv);
    cudaGetSymbolAddress((void**)&o_p, g_o);
    cudaGetSymbolAddress((void**)&wqr_p, g_wqr);
    cudaGetSymbolAddress((void**)&wor_p, g_wor);

    // 0) round weights
    round_weights_kernel<<<512, 256>>>(w_qkv, w_out);

    const int gsmem = 4 * 128 * TPAD * sizeof(float);
    cudaFuncSetAttribute(gemm_tf32_kernel, cudaFuncAttributeMaxDynamicSharedMemorySize, gsmem);

    // 1) QKV GEMM
    {
        dim3 grid(NQKV / 128, M_ / 128);
        gemm_tf32_kernel<<<grid, 256, gsmem>>>(x, wqr_p, qkv_p, M_, NQKV, C_);
    }

    // 2) RoPE + rearrange into fragment layouts
    {
        long long total = 3LL * B_ * NH_ * T_ * HD_;
        int blocks = (int)((total + 255) / 256);
        rope_rearrange_kernel<<<blocks, 256>>>();
    }

    // 3) flash attention
    {
        const int smem = 4 * 1024 * sizeof(float4);   // 64 KB
        cudaFuncSetAttribute(flash_kernel, cudaFuncAttributeMaxDynamicSharedMemorySize, smem);
        dim3 grid(T_ / 128, B_ * NH_);
        flash_kernel<<<grid, 256, smem>>>();
    }

    // 4) out projection
    {
        dim3 grid(C_ / 128, M_ / 128);
        gemm_tf32_kernel<<<grid, 256, gsmem>>>(o_p, wor_p, out, M_, C_, C_);
    }
}

// round 10
// speedup vs baseline: 3.9886x; 1.0151x over previous
#include <cuda_runtime.h>
#include <cuda_bf16.h>
#include <cstdint>
#include <math.h>

#define B_  4
#define T_  2048
#define C_  768
#define NH_ 12
#define HD_ 64
#define RD_ 16
#define M_  (B_ * T_)          // 8192
#define NQKV (3 * C_)          // 2304

// ---------------- scratch ----------------------------------------------------
__device__ float g_qkv[M_ * NQKV];               // [B*T, 2304]
__device__ float g_qf[B_ * NH_ * T_ * HD_];      // Q frag order, tf32, scale*log2e folded
__device__ float g_kf[B_ * NH_ * T_ * HD_];      // K frag order, tf32
__device__ float g_vf[B_ * NH_ * T_ * HD_];      // V frag order, tf32
__device__ float g_o[M_ * C_];                   // attn out (tf32-rounded)
__device__ float g_wqr[NQKV * C_];               // w_qkv tf32-rounded
__device__ float g_wor[C_ * C_];                 // w_out tf32-rounded

// ---------------- helpers -----------------------------------------------------
__device__ __forceinline__ float f2tf32(float x) {
    unsigned u;
    asm("cvt.rna.tf32.f32 %0, %1;" : "=r"(u) : "f"(x));
    return __uint_as_float(u);
}

__device__ __forceinline__ void mma_tf32(float* c,
    float a0, float a1, float a2, float a3, float b0, float b1)
{
    asm volatile(
        "mma.sync.aligned.m16n8k8.row.col.f32.tf32.tf32.f32 "
        "{%0,%1,%2,%3}, {%4,%5,%6,%7}, {%8,%9}, {%0,%1,%2,%3};"
        : "+f"(c[0]), "+f"(c[1]), "+f"(c[2]), "+f"(c[3])
        : "r"(__float_as_uint(a0)), "r"(__float_as_uint(a1)),
          "r"(__float_as_uint(a2)), "r"(__float_as_uint(a3)),
          "r"(__float_as_uint(b0)), "r"(__float_as_uint(b1)));
}

__device__ __forceinline__ void cp_async16(unsigned int smem_addr, const void* gptr) {
    asm volatile("cp.async.ca.shared.global [%0], [%1], 16;\n"
                 :: "r"(smem_addr), "l"(gptr));
}
__device__ __forceinline__ void cp_async_commit() {
    asm volatile("cp.async.commit_group;\n" ::: "memory");
}
__device__ __forceinline__ void cp_async_wait0() {
    asm volatile("cp.async.wait_group 0;\n" ::: "memory");
}
__device__ __forceinline__ void cp_async_wait1() {
    asm volatile("cp.async.wait_group 1;\n" ::: "memory");
}

// ---------------- weight rounding prep -----------------------------------------
__global__ __launch_bounds__(256) void round_weights_kernel(
    const float* __restrict__ wq, const float* __restrict__ wo)
{
    int i = blockIdx.x * 256 + threadIdx.x;
    int stride = gridDim.x * 256;
    for (int j = i; j < NQKV * C_; j += stride) g_wqr[j] = f2tf32(wq[j]);
    for (int j = i; j < C_ * C_; j += stride)   g_wor[j] = f2tf32(wo[j]);
}

// ---------------- TF32 tensor-core GEMM: C = A @ B^T ---------------------------
#define TPAD 36

__global__ __launch_bounds__(256, 2) void gemm_tf32_kernel(
    const float* __restrict__ A, const float* __restrict__ Bm,
    float* __restrict__ C, int M, int N, int K)
{
    extern __shared__ float smg[];
    float* As0 = smg;
    float* As1 = As0 + 128 * TPAD;
    float* Bs0 = As1 + 128 * TPAD;
    float* Bs1 = Bs0 + 128 * TPAD;

    const int tid = threadIdx.x;
    const int warp = tid >> 5;
    const int lane = tid & 31;
    const int rA = lane >> 2;
    const int cq = lane & 3;
    const int warp_m = warp & 1;
    const int warp_n = warp >> 1;

    const int m0 = blockIdx.y * 128;
    const int n0 = blockIdx.x * 128;

    float acc[4][4][4];
#pragma unroll
    for (int a = 0; a < 4; a++)
#pragma unroll
        for (int b = 0; b < 4; b++)
#pragma unroll
            for (int c = 0; c < 4; c++) acc[a][b][c] = 0.f;

    auto issue = [&](int k0, float* Asb, float* Bsb) {
#pragma unroll
        for (int l = 0; l < 4; l++) {
            int slot = l * 256 + tid;
            int row = slot >> 3, ch = slot & 7;
            unsigned int da = (unsigned int)__cvta_generic_to_shared(&Asb[row * TPAD + ch * 4]);
            cp_async16(da, &A[(size_t)(m0 + row) * K + k0 + ch * 4]);
            unsigned int db = (unsigned int)__cvta_generic_to_shared(&Bsb[row * TPAD + ch * 4]);
            cp_async16(db, &Bm[(size_t)(n0 + row) * K + k0 + ch * 4]);
        }
        cp_async_commit();
    };

    const int niter = K / 32;
    issue(0, As0, Bs0);

    for (int it = 0; it < niter; it++) {
        float* As = (it & 1) ? As1 : As0;
        float* Bs = (it & 1) ? Bs1 : Bs0;
        if (it + 1 < niter) {
            issue((it + 1) * 32, (it & 1) ? As0 : As1, (it & 1) ? Bs0 : Bs1);
            cp_async_wait1();
        } else {
            cp_async_wait0();
        }
        __syncthreads();

#pragma unroll
        for (int ks = 0; ks < 4; ks++) {
            const int k = ks * 8;
            float af[4][4];
#pragma unroll
            for (int mb = 0; mb < 4; mb++) {
                int row = warp_m * 64 + mb * 16 + rA;
                af[mb][0] = f2tf32(As[row * TPAD + k + cq]);
                af[mb][1] = f2tf32(As[(row + 8) * TPAD + k + cq]);
                af[mb][2] = f2tf32(As[row * TPAD + k + cq + 4]);
                af[mb][3] = f2tf32(As[(row + 8) * TPAD + k + cq + 4]);
            }
            float bf[4][2];
#pragma unroll
            for (int nb = 0; nb < 4; nb++) {
                int n = warp_n * 32 + nb * 8 + rA;
                bf[nb][0] = Bs[n * TPAD + k + cq];
                bf[nb][1] = Bs[n * TPAD + k + cq + 4];
            }
#pragma unroll
            for (int mb = 0; mb < 4; mb++)
#pragma unroll
                for (int nb = 0; nb < 4; nb++)
                    mma_tf32(acc[mb][nb], af[mb][0], af[mb][1], af[mb][2], af[mb][3],
                             bf[nb][0], bf[nb][1]);
        }
        __syncthreads();
    }

#pragma unroll
    for (int mb = 0; mb < 4; mb++) {
        int row = m0 + warp_m * 64 + mb * 16 + rA;
#pragma unroll
        for (int nb = 0; nb < 4; nb++) {
            int col = n0 + warp_n * 32 + nb * 8 + 2 * cq;
            *(float2*)&C[(size_t)row * N + col] =
                make_float2(acc[mb][nb][0], acc[mb][nb][1]);
            *(float2*)&C[(size_t)(row + 8) * N + col] =
                make_float2(acc[mb][nb][2], acc[mb][nb][3]);
        }
    }
}

// ---------------- RoPE + rearrange into FRAGMENT layouts ----------------------
__global__ __launch_bounds__(256) void rope_rearrange_kernel()
{
    const long long total = 3LL * B_ * NH_ * T_ * HD_;
    long long idx = (long long)blockIdx.x * blockDim.x + threadIdx.x;
    if (idx >= total) return;

    int d = (int)(idx & 63);
    long long r = idx >> 6;
    int t = (int)(r % T_); r /= T_;
    int h = (int)(r % NH_); r /= NH_;
    int b = (int)(r % B_);
    int sel = (int)(r / B_);

    const size_t srow = ((size_t)(b * T_ + t)) * NQKV + sel * C_ + h * HD_;
    float val = g_qkv[srow + d];

    if (sel < 2 && d < RD_) {
        int j = (d < 8) ? d : d - 8;
        float freq = __powf(10000.0f, -(float)j / 8.0f);
        float ang = (float)t * freq;
        float c = cosf(ang), s = sinf(ang);
        if (d < 8) {
            float r2 = g_qkv[srow + d + 8];
            val = val * c - r2 * s;
        } else {
            float r1 = g_qkv[srow + d - 8];
            val = val * c + r1 * s;
        }
    }

    // fold softmax scale AND log2(e) into q so flash can use exp2
    if (sel == 0) val *= 0.125f * 1.4426950408889634f;
    val = f2tf32(val);

    const int bh = b * NH_ + h;
    if (sel == 0) {
        int g = t >> 4, tl = t & 15;
        int hi = tl >> 3, rA = tl & 7;
        int kb = d >> 3, c = d & 7, reg = c >> 2, cq = c & 3;
        size_t off = (((size_t)bh * 128 + g) * 8 + kb) * 128 + (rA * 4 + cq) * 4 + hi + 2 * reg;
        g_qf[off] = val;
    } else if (sel == 1) {
        int kt = t >> 6, tl = t & 63;
        int nb = tl >> 3, rA = tl & 7;
        int kb = d >> 3, c = d & 7, reg = c >> 2, cq = c & 3;
        size_t off = ((size_t)bh * 32 + kt) * 4096
                   + ((nb * 4 + (kb >> 1)) * 32 + rA * 4 + cq) * 4 + (kb & 1) * 2 + reg;
        g_kf[off] = val;
    } else {
        int kt = t >> 6, tl = t & 63;
        int kb2 = tl >> 3, c = tl & 7, reg = c >> 2, cq = c & 3;
        int nb2 = d >> 3, rA = d & 7;
        size_t off = ((size_t)bh * 32 + kt) * 4096
                   + ((kb2 * 4 + (nb2 >> 1)) * 32 + rA * 4 + cq) * 4 + (nb2 & 1) * 2 + reg;
        g_vf[off] = val;
    }
}

// ---------------- Flash attention: TF32 mma.sync, 2 CTAs/SM --------------------
__global__ __launch_bounds__(256, 2) void flash_kernel()
{
    extern __shared__ float4 smf[];
    float4* Ksf0 = smf;                 // 1024 float4
    float4* Ksf1 = Ksf0 + 1024;
    float4* Vsf0 = Ksf1 + 1024;
    float4* Vsf1 = Vsf0 + 1024;

    const int tid = threadIdx.x;
    const int warp = tid >> 5;
    const int lane = tid & 31;
    const int rA = lane >> 2;
    const int cq = lane & 3;

    const int qt = (int)gridDim.x - 1 - (int)blockIdx.x;  // longest first
    const int bh = blockIdx.y;
    const int q0 = qt * 128;

    const int b = bh / NH_, h = bh % NH_;
    const int qrow = q0 + warp * 16 + rA;

    const float4* Qf = (const float4*)g_qf;
    float qa[8][4];
#pragma unroll
    for (int kb = 0; kb < 8; kb++) {
        float4 f = Qf[(((size_t)bh * 128 + 8 * qt + warp) * 8 + kb) * 32 + lane];
        qa[kb][0] = f.x; qa[kb][1] = f.y; qa[kb][2] = f.z; qa[kb][3] = f.w;
    }

    float o[8][4];
#pragma unroll
    for (int i = 0; i < 8; i++)
#pragma unroll
        for (int j = 0; j < 4; j++) o[i][j] = 0.f;
    float mA = -1e30f, mB = -1e30f, lA = 0.f, lB = 0.f;

    const float4* Kf = (const float4*)g_kf;
    const float4* Vf = (const float4*)g_vf;

    auto issue_tile = [&](int kt, float4* Ksb, float4* Vsb) {
        const size_t tb = ((size_t)bh * 32 + kt) * 1024;
#pragma unroll
        for (int l = 0; l < 4; l++) {
            int slot = l * 256 + tid;
            unsigned int dk = (unsigned int)__cvta_generic_to_shared(&Ksb[slot]);
            cp_async16(dk, &Kf[tb + slot]);
            unsigned int dv = (unsigned int)__cvta_generic_to_shared(&Vsb[slot]);
            cp_async16(dv, &Vf[tb + slot]);
        }
        cp_async_commit();
    };

    issue_tile(0, Ksf0, Vsf0);

    const int srcA = (lane & ~3) | (cq >> 1);
    const int srcB = srcA + 2;
    const bool par = (cq & 1);

    const int ktiles = 2 * qt + 2;
    for (int kt = 0; kt < ktiles; kt++) {
        float4* Ksf = (kt & 1) ? Ksf1 : Ksf0;
        float4* Vsf = (kt & 1) ? Vsf1 : Vsf0;
        const bool have_next = (kt + 1 < ktiles);
        if (have_next) {
            issue_tile(kt + 1, (kt & 1) ? Ksf0 : Ksf1, (kt & 1) ? Vsf0 : Vsf1);
            cp_async_wait1();
        } else {
            cp_async_wait0();
        }
        __syncthreads();

        float s[8][4];
#pragma unroll
        for (int nb = 0; nb < 8; nb++)
#pragma unroll
            for (int j = 0; j < 4; j++) s[nb][j] = 0.f;
#pragma unroll
        for (int kbp = 0; kbp < 4; kbp++) {
#pragma unroll
            for (int nb = 0; nb < 8; nb++) {
                float4 f = Ksf[(nb * 4 + kbp) * 32 + lane];
                mma_tf32(s[nb], qa[2 * kbp][0], qa[2 * kbp][1], qa[2 * kbp][2], qa[2 * kbp][3], f.x, f.y);
                mma_tf32(s[nb], qa[2 * kbp + 1][0], qa[2 * kbp + 1][1], qa[2 * kbp + 1][2], qa[2 * kbp + 1][3], f.z, f.w);
            }
        }

        const int k0 = kt * 64;
        if (k0 + 63 > qrow) {
#pragma unroll
            for (int nb = 0; nb < 8; nb++) {
                int col = k0 + 8 * nb + 2 * cq;
                if (col > qrow)     s[nb][0] = -1e30f;
                if (col + 1 > qrow) s[nb][1] = -1e30f;
                if (col > qrow + 8)     s[nb][2] = -1e30f;
                if (col + 1 > qrow + 8) s[nb][3] = -1e30f;
            }
        }

        float rmaxA = -1e30f, rmaxB = -1e30f;
#pragma unroll
        for (int nb = 0; nb < 8; nb++) {
            rmaxA = fmaxf(rmaxA, fmaxf(s[nb][0], s[nb][1]));
            rmaxB = fmaxf(rmaxB, fmaxf(s[nb][2], s[nb][3]));
        }
        rmaxA = fmaxf(rmaxA, __shfl_xor_sync(0xffffffffu, rmaxA, 1));
        rmaxA = fmaxf(rmaxA, __shfl_xor_sync(0xffffffffu, rmaxA, 2));
        rmaxB = fmaxf(rmaxB, __shfl_xor_sync(0xffffffffu, rmaxB, 1));
        rmaxB = fmaxf(rmaxB, __shfl_xor_sync(0xffffffffu, rmaxB, 2));

        float mnA = fmaxf(mA, rmaxA), mnB = fmaxf(mB, rmaxB);
        float alA = exp2f(mA - mnA), alB = exp2f(mB - mnB);
        mA = mnA; mB = mnB;

        float sumA = 0.f, sumB = 0.f;
#pragma unroll
        for (int nb = 0; nb < 8; nb++) {
            s[nb][0] = exp2f(s[nb][0] - mA); sumA += s[nb][0];
            s[nb][1] = exp2f(s[nb][1] - mA); sumA += s[nb][1];
            s[nb][2] = exp2f(s[nb][2] - mB); sumB += s[nb][2];
            s[nb][3] = exp2f(s[nb][3] - mB); sumB += s[nb][3];
        }
        sumA += __shfl_xor_sync(0xffffffffu, sumA, 1);
        sumA += __shfl_xor_sync(0xffffffffu, sumA, 2);
        sumB += __shfl_xor_sync(0xffffffffu, sumB, 1);
        sumB += __shfl_xor_sync(0xffffffffu, sumB, 2);
        lA = lA * alA + sumA;
        lB = lB * alB + sumB;

#pragma unroll
        for (int nb = 0; nb < 8; nb++) {
            o[nb][0] *= alA; o[nb][1] *= alA;
            o[nb][2] *= alB; o[nb][3] *= alB;
        }

#pragma unroll
        for (int nb = 0; nb < 8; nb++)
#pragma unroll
            for (int j = 0; j < 4; j++) s[nb][j] = f2tf32(s[nb][j]);

#pragma unroll
        for (int kb2 = 0; kb2 < 8; kb2++) {
            float t0, t1;
            t0 = __shfl_sync(0xffffffffu, s[kb2][0], srcA);
            t1 = __shfl_sync(0xffffffffu, s[kb2][1], srcA);
            float pa0 = par ? t1 : t0;
            t0 = __shfl_sync(0xffffffffu, s[kb2][0], srcB);
            t1 = __shfl_sync(0xffffffffu, s[kb2][1], srcB);
            float pa2 = par ? t1 : t0;
            t0 = __shfl_sync(0xffffffffu, s[kb2][2], srcA);
            t1 = __shfl_sync(0xffffffffu, s[kb2][3], srcA);
            float pa1 = par ? t1 : t0;
            t0 = __shfl_sync(0xffffffffu, s[kb2][2], srcB);
            t1 = __shfl_sync(0xffffffffu, s[kb2][3], srcB);
            float pa3 = par ? t1 : t0;

#pragma unroll
            for (int nb2p = 0; nb2p < 4; nb2p++) {
                float4 f = Vsf[(kb2 * 4 + nb2p) * 32 + lane];
                mma_tf32(o[2 * nb2p],     pa0, pa1, pa2, pa3, f.x, f.y);
                mma_tf32(o[2 * nb2p + 1], pa0, pa1, pa2, pa3, f.z, f.w);
            }
        }
        __syncthreads();
    }

    float invA = 1.f / lA, invB = 1.f / lB;
    const size_t rowA_off = ((size_t)(b * T_ + qrow)) * C_ + h * HD_;
    const size_t rowB_off = ((size_t)(b * T_ + qrow + 8)) * C_ + h * HD_;
#pragma unroll
    for (int nb2 = 0; nb2 < 8; nb2++) {
        int col = 8 * nb2 + 2 * cq;
        g_o[rowA_off + col]     = f2tf32(o[nb2][0] * invA);
        g_o[rowA_off + col + 1] = f2tf32(o[nb2][1] * invA);
        g_o[rowB_off + col]     = f2tf32(o[nb2][2] * invB);
        g_o[rowB_off + col + 1] = f2tf32(o[nb2][3] * invB);
    }
}

// ---------------- launch ------------------------------------------------------
extern "C" void kernel_launch(void* const* d_in, const int* in_sizes, int n_in,
                              void* d_out, int out_size)
{
    const float* x     = (const float*)d_in[0];
    const float* w_qkv = (const float*)d_in[1];
    const float* w_out = (const float*)d_in[2];
    float* out = (float*)d_out;

    float *qkv_p, *o_p, *wqr_p, *wor_p;
    cudaGetSymbolAddress((void**)&qkv_p, g_qkv);
    cudaGetSymbolAddress((void**)&o_p, g_o);
    cudaGetSymbolAddress((void**)&wqr_p, g_wqr);
    cudaGetSymbolAddress((void**)&wor_p, g_wor);

    round_weights_kernel<<<512, 256>>>(w_qkv, w_out);

    const int gsmem = 4 * 128 * TPAD * sizeof(float);
    cudaFuncSetAttribute(gemm_tf32_kernel, cudaFuncAttributeMaxDynamicSharedMemorySize, gsmem);

    // 1) QKV GEMM
    {
        dim3 grid(NQKV / 128, M_ / 128);
        gemm_tf32_kernel<<<grid, 256, gsmem>>>(x, wqr_p, qkv_p, M_, NQKV, C_);
    }

    // 2) RoPE + rearrange into fragment layouts
    {
        long long total = 3LL * B_ * NH_ * T_ * HD_;
        int blocks = (int)((total + 255) / 256);
        rope_rearrange_kernel<<<blocks, 256>>>();
    }

    // 3) flash attention
    {
        const int smem = 4 * 1024 * sizeof(float4);   // 64 KB
        cudaFuncSetAttribute(flash_kernel, cudaFuncAttributeMaxDynamicSharedMemorySize, smem);
        dim3 grid(T_ / 128, B_ * NH_);
        flash_kernel<<<grid, 256, smem>>>();
    }

    // 4) out projection
    {
        dim3 grid(C_ / 128, M_ / 128);
        gemm_tf32_kernel<<<grid, 256, gsmem>>>(o_p, wor_p, out, M_, C_, C_);
    }
}

// round 12
// speedup vs baseline: 4.0742x; 1.0215x over previous
#include <cuda_runtime.h>
#include <cuda_bf16.h>
#include <cstdint>
#include <math.h>

#define B_  4
#define T_  2048
#define C_  768
#define NH_ 12
#define HD_ 64
#define RD_ 16
#define M_  (B_ * T_)          // 8192
#define NQKV (3 * C_)          // 2304

// ---------------- scratch ----------------------------------------------------
__device__ float g_qf[B_ * NH_ * T_ * HD_];      // Q frag order, tf32, scale*log2e folded
__device__ float g_kf[B_ * NH_ * T_ * HD_];      // K frag order, tf32
__device__ float g_vf[B_ * NH_ * T_ * HD_];      // V frag order, tf32
__device__ float g_o[M_ * C_];                   // attn out (tf32-rounded)
__device__ float g_wqr[NQKV * C_];               // w_qkv tf32-rounded
__device__ float g_wor[C_ * C_];                 // w_out tf32-rounded

// ---------------- helpers -----------------------------------------------------
__device__ __forceinline__ float f2tf32(float x) {
    unsigned u;
    asm("cvt.rna.tf32.f32 %0, %1;" : "=r"(u) : "f"(x));
    return __uint_as_float(u);
}

__device__ __forceinline__ void mma_tf32(float* c,
    float a0, float a1, float a2, float a3, float b0, float b1)
{
    asm volatile(
        "mma.sync.aligned.m16n8k8.row.col.f32.tf32.tf32.f32 "
        "{%0,%1,%2,%3}, {%4,%5,%6,%7}, {%8,%9}, {%0,%1,%2,%3};"
        : "+f"(c[0]), "+f"(c[1]), "+f"(c[2]), "+f"(c[3])
        : "r"(__float_as_uint(a0)), "r"(__float_as_uint(a1)),
          "r"(__float_as_uint(a2)), "r"(__float_as_uint(a3)),
          "r"(__float_as_uint(b0)), "r"(__float_as_uint(b1)));
}

__device__ __forceinline__ void cp_async16(unsigned int smem_addr, const void* gptr) {
    asm volatile("cp.async.ca.shared.global [%0], [%1], 16;\n"
                 :: "r"(smem_addr), "l"(gptr));
}
__device__ __forceinline__ void cp_async_commit() {
    asm volatile("cp.async.commit_group;\n" ::: "memory");
}
__device__ __forceinline__ void cp_async_wait0() {
    asm volatile("cp.async.wait_group 0;\n" ::: "memory");
}
__device__ __forceinline__ void cp_async_wait1() {
    asm volatile("cp.async.wait_group 1;\n" ::: "memory");
}
__device__ __forceinline__ unsigned int smem_u32(const void* p) {
    return (unsigned int)__cvta_generic_to_shared(p);
}

// ---------------- weight rounding prep -----------------------------------------
__global__ __launch_bounds__(256) void round_weights_kernel(
    const float* __restrict__ wq, const float* __restrict__ wo)
{
    int i = blockIdx.x * 256 + threadIdx.x;
    int stride = gridDim.x * 256;
    for (int j = i; j < NQKV * C_; j += stride) g_wqr[j] = f2tf32(wq[j]);
    for (int j = i; j < C_ * C_; j += stride)   g_wor[j] = f2tf32(wo[j]);
}

// ---------------- TF32 tensor-core GEMM: C = A @ B^T ---------------------------
// A raw fp32 (cvt in register); B pre-rounded tf32. BM=BN=128, BK=32.
// fuse_rope == 0: plain row-major write to C.
// fuse_rope == 1: RoPE + tf32-round + fragment-order scatter to g_qf/g_kf/g_vf.
#define TPAD 36
#define EPAD 132

__global__ __launch_bounds__(256, 2) void gemm_tf32_kernel(
    const float* __restrict__ A, const float* __restrict__ Bm,
    float* __restrict__ C, int M, int N, int K, int fuse_rope)
{
    extern __shared__ float smg[];
    float* As0 = smg;                    // [128][36]
    float* As1 = As0 + 128 * TPAD;
    float* Bs0 = As1 + 128 * TPAD;
    float* Bs1 = Bs0 + 128 * TPAD;

    const int tid = threadIdx.x;
    const int warp = tid >> 5;
    const int lane = tid & 31;
    const int rA = lane >> 2;
    const int cq = lane & 3;
    const int warp_m = warp & 1;
    const int warp_n = warp >> 1;

    const int m0 = blockIdx.y * 128;
    const int n0 = blockIdx.x * 128;

    float acc[4][4][4];
#pragma unroll
    for (int a = 0; a < 4; a++)
#pragma unroll
        for (int b = 0; b < 4; b++)
#pragma unroll
            for (int c = 0; c < 4; c++) acc[a][b][c] = 0.f;

    auto issue = [&](int k0, float* Asb, float* Bsb) {
#pragma unroll
        for (int l = 0; l < 4; l++) {
            int slot = l * 256 + tid;
            int row = slot >> 3, ch = slot & 7;
            cp_async16(smem_u32(&Asb[row * TPAD + ch * 4]),
                       &A[(size_t)(m0 + row) * K + k0 + ch * 4]);
            cp_async16(smem_u32(&Bsb[row * TPAD + ch * 4]),
                       &Bm[(size_t)(n0 + row) * K + k0 + ch * 4]);
        }
        cp_async_commit();
    };

    const int niter = K / 32;
    issue(0, As0, Bs0);

    for (int it = 0; it < niter; it++) {
        float* As = (it & 1) ? As1 : As0;
        float* Bs = (it & 1) ? Bs1 : Bs0;
        if (it + 1 < niter) {
            issue((it + 1) * 32, (it & 1) ? As0 : As1, (it & 1) ? Bs0 : Bs1);
            cp_async_wait1();
        } else {
            cp_async_wait0();
        }
        __syncthreads();

#pragma unroll
        for (int ks = 0; ks < 4; ks++) {
            const int k = ks * 8;
            float af[4][4];
#pragma unroll
            for (int mb = 0; mb < 4; mb++) {
                int row = warp_m * 64 + mb * 16 + rA;
                af[mb][0] = f2tf32(As[row * TPAD + k + cq]);
                af[mb][1] = f2tf32(As[(row + 8) * TPAD + k + cq]);
                af[mb][2] = f2tf32(As[row * TPAD + k + cq + 4]);
                af[mb][3] = f2tf32(As[(row + 8) * TPAD + k + cq + 4]);
            }
            float bf[4][2];
#pragma unroll
            for (int nb = 0; nb < 4; nb++) {
                int n = warp_n * 32 + nb * 8 + rA;
                bf[nb][0] = Bs[n * TPAD + k + cq];
                bf[nb][1] = Bs[n * TPAD + k + cq + 4];
            }
#pragma unroll
            for (int mb = 0; mb < 4; mb++)
#pragma unroll
                for (int nb = 0; nb < 4; nb++)
                    mma_tf32(acc[mb][nb], af[mb][0], af[mb][1], af[mb][2], af[mb][3],
                             bf[nb][0], bf[nb][1]);
        }
        __syncthreads();
    }

    if (!fuse_rope) {
#pragma unroll
        for (int mb = 0; mb < 4; mb++) {
            int row = m0 + warp_m * 64 + mb * 16 + rA;
#pragma unroll
            for (int nb = 0; nb < 4; nb++) {
                int col = n0 + warp_n * 32 + nb * 8 + 2 * cq;
                *(float2*)&C[(size_t)row * N + col] =
                    make_float2(acc[mb][nb][0], acc[mb][nb][1]);
                *(float2*)&C[(size_t)(row + 8) * N + col] =
                    make_float2(acc[mb][nb][2], acc[mb][nb][3]);
            }
        }
        return;
    }

    // --- fused RoPE + fragment scatter epilogue (QKV GEMM only) ---
    // Stage C tile into smem overlay (pipeline buffers are dead now).
    float* ep = smg;                     // [128][132]
#pragma unroll
    for (int mb = 0; mb < 4; mb++) {
        int row = warp_m * 64 + mb * 16 + rA;
#pragma unroll
        for (int nb = 0; nb < 4; nb++) {
            int col = warp_n * 32 + nb * 8 + 2 * cq;
            *(float2*)&ep[row * EPAD + col] = make_float2(acc[mb][nb][0], acc[mb][nb][1]);
            *(float2*)&ep[(row + 8) * EPAD + col] = make_float2(acc[mb][nb][2], acc[mb][nb][3]);
        }
    }
    __syncthreads();

    const int sel = n0 / C_;             // tile entirely within q/k/v (128 | 768)
    const int cbase = n0 % C_;

#pragma unroll 4
    for (int e = 0; e < 64; e++) {
        int elem = e * 256 + tid;
        int r = elem >> 7, c = elem & 127;
        float val = ep[r * EPAD + c];

        int cc = cbase + c;
        int h = cc >> 6, d = cc & 63;
        int m = m0 + r;
        int b = m >> 11, t = m & (T_ - 1);

        if (sel < 2 && d < RD_) {
            int j = (d < 8) ? d : d - 8;
            float freq = __powf(10000.0f, -(float)j / 8.0f);
            float ang = (float)t * freq;
            float cs = cosf(ang), sn = sinf(ang);
            float partner = ep[r * EPAD + ((d < 8) ? c + 8 : c - 8)];
            val = (d < 8) ? (val * cs - partner * sn) : (val * cs + partner * sn);
        }
        if (sel == 0) val *= 0.125f * 1.4426950408889634f;
        val = f2tf32(val);

        const int bh = b * NH_ + h;
        if (sel == 0) {
            int g = t >> 4, tl = t & 15;
            int hi = tl >> 3, ra = tl & 7;
            int kb = d >> 3, c7 = d & 7, reg = c7 >> 2, q4 = c7 & 3;
            size_t off = (((size_t)bh * 128 + g) * 8 + kb) * 128 + (ra * 4 + q4) * 4 + hi + 2 * reg;
            g_qf[off] = val;
        } else if (sel == 1) {
            int kt = t >> 6, tl = t & 63;
            int nb = tl >> 3, ra = tl & 7;
            int kb = d >> 3, c7 = d & 7, reg = c7 >> 2, q4 = c7 & 3;
            size_t off = ((size_t)bh * 32 + kt) * 4096
                       + ((nb * 4 + (kb >> 1)) * 32 + ra * 4 + q4) * 4 + (kb & 1) * 2 + reg;
            g_kf[off] = val;
        } else {
            int kt = t >> 6, tl = t & 63;
            int kb2 = tl >> 3, c7 = tl & 7, reg = c7 >> 2, q4 = c7 & 3;
            int nb2 = d >> 3, ra = d & 7;
            size_t off = ((size_t)bh * 32 + kt) * 4096
                       + ((kb2 * 4 + (nb2 >> 1)) * 32 + ra * 4 + q4) * 4 + (nb2 & 1) * 2 + reg;
            g_vf[off] = val;
        }
    }
}

// ---------------- Flash attention: TF32 mma.sync, 2 CTAs/SM --------------------
__global__ __launch_bounds__(256, 2) void flash_kernel()
{
    extern __shared__ float4 smf[];
    float4* Ksf0 = smf;
    float4* Ksf1 = Ksf0 + 1024;
    float4* Vsf0 = Ksf1 + 1024;
    float4* Vsf1 = Vsf0 + 1024;

    const int tid = threadIdx.x;
    const int warp = tid >> 5;
    const int lane = tid & 31;
    const int rA = lane >> 2;
    const int cq = lane & 3;

    const int qt = (int)gridDim.x - 1 - (int)blockIdx.x;
    const int bh = blockIdx.y;
    const int q0 = qt * 128;

    const int b = bh / NH_, h = bh % NH_;
    const int qrow = q0 + warp * 16 + rA;

    const float4* Qf = (const float4*)g_qf;
    float qa[8][4];
#pragma unroll
    for (int kb = 0; kb < 8; kb++) {
        float4 f = Qf[(((size_t)bh * 128 + 8 * qt + warp) * 8 + kb) * 32 + lane];
        qa[kb][0] = f.x; qa[kb][1] = f.y; qa[kb][2] = f.z; qa[kb][3] = f.w;
    }

    float o[8][4];
#pragma unroll
    for (int i = 0; i < 8; i++)
#pragma unroll
        for (int j = 0; j < 4; j++) o[i][j] = 0.f;
    float mA = -1e30f, mB = -1e30f, lA = 0.f, lB = 0.f;

    const float4* Kf = (const float4*)g_kf;
    const float4* Vf = (const float4*)g_vf;

    auto issue_tile = [&](int kt, float4* Ksb, float4* Vsb) {
        const size_t tb = ((size_t)bh * 32 + kt) * 1024;
#pragma unroll
        for (int l = 0; l < 4; l++) {
            int slot = l * 256 + tid;
            cp_async16(smem_u32(&Ksb[slot]), &Kf[tb + slot]);
            cp_async16(smem_u32(&Vsb[slot]), &Vf[tb + slot]);
        }
        cp_async_commit();
    };

    issue_tile(0, Ksf0, Vsf0);

    const int srcA = (lane & ~3) | (cq >> 1);
    const int srcB = srcA + 2;
    const bool par = (cq & 1);

    const int ktiles = 2 * qt + 2;
    for (int kt = 0; kt < ktiles; kt++) {
        float4* Ksf = (kt & 1) ? Ksf1 : Ksf0;
        float4* Vsf = (kt & 1) ? Vsf1 : Vsf0;
        const bool have_next = (kt + 1 < ktiles);
        if (have_next) {
            issue_tile(kt + 1, (kt & 1) ? Ksf0 : Ksf1, (kt & 1) ? Vsf0 : Vsf1);
            cp_async_wait1();
        } else {
            cp_async_wait0();
        }
        __syncthreads();

        float s[8][4];
#pragma unroll
        for (int nb = 0; nb < 8; nb++)
#pragma unroll
            for (int j = 0; j < 4; j++) s[nb][j] = 0.f;
#pragma unroll
        for (int kbp = 0; kbp < 4; kbp++) {
#pragma unroll
            for (int nb = 0; nb < 8; nb++) {
                float4 f = Ksf[(nb * 4 + kbp) * 32 + lane];
                mma_tf32(s[nb], qa[2 * kbp][0], qa[2 * kbp][1], qa[2 * kbp][2], qa[2 * kbp][3], f.x, f.y);
                mma_tf32(s[nb], qa[2 * kbp + 1][0], qa[2 * kbp + 1][1], qa[2 * kbp + 1][2], qa[2 * kbp + 1][3], f.z, f.w);
            }
        }

        const int k0 = kt * 64;
        if (k0 + 63 > qrow) {
#pragma unroll
            for (int nb = 0; nb < 8; nb++) {
                int col = k0 + 8 * nb + 2 * cq;
                if (col > qrow)     s[nb][0] = -1e30f;
                if (col + 1 > qrow) s[nb][1] = -1e30f;
                if (col > qrow + 8)     s[nb][2] = -1e30f;
                if (col + 1 > qrow + 8) s[nb][3] = -1e30f;
            }
        }

        float rmaxA = -1e30f, rmaxB = -1e30f;
#pragma unroll
        for (int nb = 0; nb < 8; nb++) {
            rmaxA = fmaxf(rmaxA, fmaxf(s[nb][0], s[nb][1]));
            rmaxB = fmaxf(rmaxB, fmaxf(s[nb][2], s[nb][3]));
        }
        rmaxA = fmaxf(rmaxA, __shfl_xor_sync(0xffffffffu, rmaxA, 1));
        rmaxA = fmaxf(rmaxA, __shfl_xor_sync(0xffffffffu, rmaxA, 2));
        rmaxB = fmaxf(rmaxB, __shfl_xor_sync(0xffffffffu, rmaxB, 1));
        rmaxB = fmaxf(rmaxB, __shfl_xor_sync(0xffffffffu, rmaxB, 2));

        float mnA = fmaxf(mA, rmaxA), mnB = fmaxf(mB, rmaxB);
        float alA = exp2f(mA - mnA), alB = exp2f(mB - mnB);
        mA = mnA; mB = mnB;

        float sumA = 0.f, sumB = 0.f;
#pragma unroll
        for (int nb = 0; nb < 8; nb++) {
            s[nb][0] = exp2f(s[nb][0] - mA); sumA += s[nb][0];
            s[nb][1] = exp2f(s[nb][1] - mA); sumA += s[nb][1];
            s[nb][2] = exp2f(s[nb][2] - mB); sumB += s[nb][2];
            s[nb][3] = exp2f(s[nb][3] - mB); sumB += s[nb][3];
        }
        sumA += __shfl_xor_sync(0xffffffffu, sumA, 1);
        sumA += __shfl_xor_sync(0xffffffffu, sumA, 2);
        sumB += __shfl_xor_sync(0xffffffffu, sumB, 1);
        sumB += __shfl_xor_sync(0xffffffffu, sumB, 2);
        lA = lA * alA + sumA;
        lB = lB * alB + sumB;

#pragma unroll
        for (int nb = 0; nb < 8; nb++) {
            o[nb][0] *= alA; o[nb][1] *= alA;
            o[nb][2] *= alB; o[nb][3] *= alB;
        }

#pragma unroll
        for (int nb = 0; nb < 8; nb++)
#pragma unroll
            for (int j = 0; j < 4; j++) s[nb][j] = f2tf32(s[nb][j]);

#pragma unroll
        for (int kb2 = 0; kb2 < 8; kb2++) {
            float t0, t1;
            t0 = __shfl_sync(0xffffffffu, s[kb2][0], srcA);
            t1 = __shfl_sync(0xffffffffu, s[kb2][1], srcA);
            float pa0 = par ? t1 : t0;
            t0 = __shfl_sync(0xffffffffu, s[kb2][0], srcB);
            t1 = __shfl_sync(0xffffffffu, s[kb2][1], srcB);
            float pa2 = par ? t1 : t0;
            t0 = __shfl_sync(0xffffffffu, s[kb2][2], srcA);
            t1 = __shfl_sync(0xffffffffu, s[kb2][3], srcA);
            float pa1 = par ? t1 : t0;
            t0 = __shfl_sync(0xffffffffu, s[kb2][2], srcB);
            t1 = __shfl_sync(0xffffffffu, s[kb2][3], srcB);
            float pa3 = par ? t1 : t0;

#pragma unroll
            for (int nb2p = 0; nb2p < 4; nb2p++) {
                float4 f = Vsf[(kb2 * 4 + nb2p) * 32 + lane];
                mma_tf32(o[2 * nb2p],     pa0, pa1, pa2, pa3, f.x, f.y);
                mma_tf32(o[2 * nb2p + 1], pa0, pa1, pa2, pa3, f.z, f.w);
            }
        }
        __syncthreads();
    }

    float invA = 1.f / lA, invB = 1.f / lB;
    const size_t rowA_off = ((size_t)(b * T_ + qrow)) * C_ + h * HD_;
    const size_t rowB_off = ((size_t)(b * T_ + qrow + 8)) * C_ + h * HD_;
#pragma unroll
    for (int nb2 = 0; nb2 < 8; nb2++) {
        int col = 8 * nb2 + 2 * cq;
        g_o[rowA_off + col]     = f2tf32(o[nb2][0] * invA);
        g_o[rowA_off + col + 1] = f2tf32(o[nb2][1] * invA);
        g_o[rowB_off + col]     = f2tf32(o[nb2][2] * invB);
        g_o[rowB_off + col + 1] = f2tf32(o[nb2][3] * invB);
    }
}

// ---------------- launch ------------------------------------------------------
extern "C" void kernel_launch(void* const* d_in, const int* in_sizes, int n_in,
                              void* d_out, int out_size)
{
    const float* x     = (const float*)d_in[0];
    const float* w_qkv = (const float*)d_in[1];
    const float* w_out = (const float*)d_in[2];
    float* out = (float*)d_out;

    float *o_p, *wqr_p, *wor_p;
    cudaGetSymbolAddress((void**)&o_p, g_o);
    cudaGetSymbolAddress((void**)&wqr_p, g_wqr);
    cudaGetSymbolAddress((void**)&wor_p, g_wor);

    // 0) round weights
    round_weights_kernel<<<512, 256>>>(w_qkv, w_out);

    const int gsmem = 4 * 128 * TPAD * sizeof(float);   // 73728 B (>= ep overlay 67584)
    cudaFuncSetAttribute(gemm_tf32_kernel, cudaFuncAttributeMaxDynamicSharedMemorySize, gsmem);

    // 1) QKV GEMM with fused RoPE + fragment scatter (no g_qkv, no rope kernel)
    {
        dim3 grid(NQKV / 128, M_ / 128);
        gemm_tf32_kernel<<<grid, 256, gsmem>>>(x, wqr_p, nullptr, M_, NQKV, C_, 1);
    }

    // 2) flash attention
    {
        const int smem = 4 * 1024 * sizeof(float4);     // 64 KB
        cudaFuncSetAttribute(flash_kernel, cudaFuncAttributeMaxDynamicSharedMemorySize, smem);
        dim3 grid(T_ / 128, B_ * NH_);
        flash_kernel<<<grid, 256, smem>>>();
    }

    // 3) out projection (plain epilogue)
    {
        dim3 grid(C_ / 128, M_ / 128);
        gemm_tf32_kernel<<<grid, 256, gsmem>>>(o_p, wor_p, out, M_, C_, C_, 0);
    }
}

// round 13
// speedup vs baseline: 4.2617x; 1.0460x over previous
#include <cuda_runtime.h>
#include <cuda_bf16.h>
#include <cstdint>
#include <math.h>

#define B_  4
#define T_  2048
#define C_  768
#define NH_ 12
#define HD_ 64
#define RD_ 16
#define M_  (B_ * T_)          // 8192
#define NQKV (3 * C_)          // 2304
#define KB24 24                // 768 / 32

// ---------------- scratch ----------------------------------------------------
__device__ float g_qf[B_ * NH_ * T_ * HD_];      // Q frag order, tf32, scale*log2e folded
__device__ float g_kf[B_ * NH_ * T_ * HD_];      // K frag order, tf32
__device__ float g_vf[B_ * NH_ * T_ * HD_];      // V frag order, tf32
__device__ float g_of[M_ * C_];                  // attn out, A-fragment order, tf32
__device__ float g_xf[M_ * C_];                  // x, A-fragment order, tf32
__device__ float g_wqf[NQKV * C_];               // w_qkv, B-fragment order, tf32
__device__ float g_wof[C_ * C_];                 // w_out, B-fragment order, tf32

// ---------------- helpers -----------------------------------------------------
__device__ __forceinline__ float f2tf32(float x) {
    unsigned u;
    asm("cvt.rna.tf32.f32 %0, %1;" : "=r"(u) : "f"(x));
    return __uint_as_float(u);
}

__device__ __forceinline__ void mma_tf32(float* c,
    float a0, float a1, float a2, float a3, float b0, float b1)
{
    asm volatile(
        "mma.sync.aligned.m16n8k8.row.col.f32.tf32.tf32.f32 "
        "{%0,%1,%2,%3}, {%4,%5,%6,%7}, {%8,%9}, {%0,%1,%2,%3};"
        : "+f"(c[0]), "+f"(c[1]), "+f"(c[2]), "+f"(c[3])
        : "r"(__float_as_uint(a0)), "r"(__float_as_uint(a1)),
          "r"(__float_as_uint(a2)), "r"(__float_as_uint(a3)),
          "r"(__float_as_uint(b0)), "r"(__float_as_uint(b1)));
}

__device__ __forceinline__ void cp_async16(unsigned int smem_addr, const void* gptr) {
    asm volatile("cp.async.ca.shared.global [%0], [%1], 16;\n"
                 :: "r"(smem_addr), "l"(gptr));
}
__device__ __forceinline__ void cp_async_commit() {
    asm volatile("cp.async.commit_group;\n" ::: "memory");
}
__device__ __forceinline__ void cp_async_wait0() {
    asm volatile("cp.async.wait_group 0;\n" ::: "memory");
}
__device__ __forceinline__ void cp_async_wait1() {
    asm volatile("cp.async.wait_group 1;\n" ::: "memory");
}
__device__ __forceinline__ unsigned int smem_u32(const void* p) {
    return (unsigned int)__cvta_generic_to_shared(p);
}

// ---------------- prep: tf32-round + fragment reorder x / weights ---------------
__global__ __launch_bounds__(256) void prep_kernel(
    const float* __restrict__ x, const float* __restrict__ wq, const float* __restrict__ wo)
{
    int i = blockIdx.x * 256 + threadIdx.x;
    int stride = gridDim.x * 256;

    // x -> A-fragment order
    for (int j = i; j < M_ * C_; j += stride) {
        int m = j / C_, k = j - m * C_;
        float v = f2tf32(x[j]);
        int mblk = m >> 7, mi = m & 127;
        int wm = mi >> 6, mb = (mi >> 4) & 3, hi = (mi >> 3) & 1, ra = mi & 7;
        int it = k >> 5, kin = k & 31, ks = kin >> 3, c7 = kin & 7, half = c7 >> 2, cq = c7 & 3;
        size_t idx = (((size_t)(mblk * KB24 + it) * 8 + (wm * 4 + mb)) * 4 + ks) * 32 + (ra * 4 + cq);
        g_xf[idx * 4 + half * 2 + hi] = v;
    }
    // w_qkv -> B-fragment order
    for (int j = i; j < NQKV * C_; j += stride) {
        int n = j / C_, k = j - n * C_;
        float v = f2tf32(wq[j]);
        int nblk = n >> 7, ni = n & 127;
        int wn = ni >> 5, nb = (ni >> 3) & 3, ra = ni & 7;
        int p = nb >> 1, pb = nb & 1;
        int it = k >> 5, kin = k & 31, ks = kin >> 3, c7 = kin & 7, half = c7 >> 2, cq = c7 & 3;
        size_t idx = (((size_t)(nblk * KB24 + it) * 8 + (wn * 2 + p)) * 4 + ks) * 32 + (ra * 4 + cq);
        g_wqf[idx * 4 + pb * 2 + half] = v;
    }
    // w_out -> B-fragment order
    for (int j = i; j < C_ * C_; j += stride) {
        int n = j / C_, k = j - n * C_;
        float v = f2tf32(wo[j]);
        int nblk = n >> 7, ni = n & 127;
        int wn = ni >> 5, nb = (ni >> 3) & 3, ra = ni & 7;
        int p = nb >> 1, pb = nb & 1;
        int it = k >> 5, kin = k & 31, ks = kin >> 3, c7 = kin & 7, half = c7 >> 2, cq = c7 & 3;
        size_t idx = (((size_t)(nblk * KB24 + it) * 8 + (wn * 2 + p)) * 4 + ks) * 32 + (ra * 4 + cq);
        g_wof[idx * 4 + pb * 2 + half] = v;
    }
}

// ---------------- TF32 MMA GEMM on fragment-ordered operands -------------------
// C = A @ B^T. A/B pre-rounded tf32 in fragment order. 128x128 tile, BK=32.
// fuse_rope == 0: plain row-major write to C.
// fuse_rope == 1: RoPE + fragment scatter to g_qf/g_kf/g_vf.
#define EPAD 132
#define GEMM_SMEM (128 * EPAD * 4)   // 67584 >= pipeline 65536

__global__ __launch_bounds__(256, 2) void gemm_tf32_kernel(
    const float4* __restrict__ Af, const float4* __restrict__ Bf,
    float* __restrict__ C, int KB, int N, int fuse_rope)
{
    extern __shared__ float4 sg4[];
    float4* As0 = sg4;           // 1024 float4 (16 KB)
    float4* Bs0 = As0 + 1024;
    float4* As1 = Bs0 + 1024;
    float4* Bs1 = As1 + 1024;

    const int tid = threadIdx.x;
    const int warp = tid >> 5;
    const int lane = tid & 31;
    const int rA = lane >> 2;
    const int cq = lane & 3;
    const int warp_m = warp & 1;
    const int warp_n = warp >> 1;

    float acc[4][4][4];
#pragma unroll
    for (int a = 0; a < 4; a++)
#pragma unroll
        for (int b = 0; b < 4; b++)
#pragma unroll
            for (int c = 0; c < 4; c++) acc[a][b][c] = 0.f;

    auto issue = [&](int it, int buf) {
        const float4* ga = Af + (size_t)(blockIdx.y * KB + it) * 1024;
        const float4* gb = Bf + (size_t)(blockIdx.x * KB + it) * 1024;
        float4* da = buf ? As1 : As0;
        float4* db = buf ? Bs1 : Bs0;
#pragma unroll
        for (int l = 0; l < 4; l++) {
            int slot = l * 256 + tid;
            cp_async16(smem_u32(&da[slot]), &ga[slot]);
            cp_async16(smem_u32(&db[slot]), &gb[slot]);
        }
        cp_async_commit();
    };

    issue(0, 0);

    for (int it = 0; it < KB; it++) {
        float4* As = (it & 1) ? As1 : As0;
        float4* Bs = (it & 1) ? Bs1 : Bs0;
        if (it + 1 < KB) {
            issue(it + 1, (it & 1) ^ 1);
            cp_async_wait1();
        } else {
            cp_async_wait0();
        }
        __syncthreads();

#pragma unroll
        for (int ks = 0; ks < 4; ks++) {
            float4 a4[4];
#pragma unroll
            for (int mb = 0; mb < 4; mb++)
                a4[mb] = As[((warp_m * 4 + mb) * 4 + ks) * 32 + lane];
            float4 b4[2];
#pragma unroll
            for (int p = 0; p < 2; p++)
                b4[p] = Bs[((warp_n * 2 + p) * 4 + ks) * 32 + lane];
#pragma unroll
            for (int mb = 0; mb < 4; mb++) {
                mma_tf32(acc[mb][0], a4[mb].x, a4[mb].y, a4[mb].z, a4[mb].w, b4[0].x, b4[0].y);
                mma_tf32(acc[mb][1], a4[mb].x, a4[mb].y, a4[mb].z, a4[mb].w, b4[0].z, b4[0].w);
                mma_tf32(acc[mb][2], a4[mb].x, a4[mb].y, a4[mb].z, a4[mb].w, b4[1].x, b4[1].y);
                mma_tf32(acc[mb][3], a4[mb].x, a4[mb].y, a4[mb].z, a4[mb].w, b4[1].z, b4[1].w);
            }
        }
        __syncthreads();
    }

    const int m0 = blockIdx.y * 128;
    const int n0 = blockIdx.x * 128;

    if (!fuse_rope) {
#pragma unroll
        for (int mb = 0; mb < 4; mb++) {
            int row = m0 + warp_m * 64 + mb * 16 + rA;
#pragma unroll
            for (int nb = 0; nb < 4; nb++) {
                int col = n0 + warp_n * 32 + nb * 8 + 2 * cq;
                *(float2*)&C[(size_t)row * N + col] =
                    make_float2(acc[mb][nb][0], acc[mb][nb][1]);
                *(float2*)&C[(size_t)(row + 8) * N + col] =
                    make_float2(acc[mb][nb][2], acc[mb][nb][3]);
            }
        }
        return;
    }

    // --- fused RoPE + fragment scatter epilogue (QKV GEMM only) ---
    float* ep = (float*)sg4;             // overlay [128][132]
#pragma unroll
    for (int mb = 0; mb < 4; mb++) {
        int row = warp_m * 64 + mb * 16 + rA;
#pragma unroll
        for (int nb = 0; nb < 4; nb++) {
            int col = warp_n * 32 + nb * 8 + 2 * cq;
            *(float2*)&ep[row * EPAD + col] = make_float2(acc[mb][nb][0], acc[mb][nb][1]);
            *(float2*)&ep[(row + 8) * EPAD + col] = make_float2(acc[mb][nb][2], acc[mb][nb][3]);
        }
    }
    __syncthreads();

    const int sel = n0 / C_;
    const int cbase = n0 % C_;

#pragma unroll 4
    for (int e = 0; e < 64; e++) {
        int elem = e * 256 + tid;
        int r = elem >> 7, c = elem & 127;
        float val = ep[r * EPAD + c];

        int cc = cbase + c;
        int h = cc >> 6, d = cc & 63;
        int m = m0 + r;
        int b = m >> 11, t = m & (T_ - 1);

        if (sel < 2 && d < RD_) {
            int j = (d < 8) ? d : d - 8;
            float freq = __powf(10000.0f, -(float)j / 8.0f);
            float ang = (float)t * freq;
            float cs = cosf(ang), sn = sinf(ang);
            float partner = ep[r * EPAD + ((d < 8) ? c + 8 : c - 8)];
            val = (d < 8) ? (val * cs - partner * sn) : (val * cs + partner * sn);
        }
        if (sel == 0) val *= 0.125f * 1.4426950408889634f;
        val = f2tf32(val);

        const int bh = b * NH_ + h;
        if (sel == 0) {
            int g = t >> 4, tl = t & 15;
            int hi = tl >> 3, ra = tl & 7;
            int kb = d >> 3, c7 = d & 7, reg = c7 >> 2, q4 = c7 & 3;
            size_t off = (((size_t)bh * 128 + g) * 8 + kb) * 128 + (ra * 4 + q4) * 4 + hi + 2 * reg;
            g_qf[off] = val;
        } else if (sel == 1) {
            int kt = t >> 6, tl = t & 63;
            int nb = tl >> 3, ra = tl & 7;
            int kb = d >> 3, c7 = d & 7, reg = c7 >> 2, q4 = c7 & 3;
            size_t off = ((size_t)bh * 32 + kt) * 4096
                       + ((nb * 4 + (kb >> 1)) * 32 + ra * 4 + q4) * 4 + (kb & 1) * 2 + reg;
            g_kf[off] = val;
        } else {
            int kt = t >> 6, tl = t & 63;
            int kb2 = tl >> 3, c7 = tl & 7, reg = c7 >> 2, q4 = c7 & 3;
            int nb2 = d >> 3, ra = d & 7;
            size_t off = ((size_t)bh * 32 + kt) * 4096
                       + ((kb2 * 4 + (nb2 >> 1)) * 32 + ra * 4 + q4) * 4 + (nb2 & 1) * 2 + reg;
            g_vf[off] = val;
        }
    }
}

// ---------------- Flash attention: TF32 mma.sync, 2 CTAs/SM --------------------
__global__ __launch_bounds__(256, 2) void flash_kernel()
{
    extern __shared__ float4 smf[];
    float4* Ksf0 = smf;
    float4* Ksf1 = Ksf0 + 1024;
    float4* Vsf0 = Ksf1 + 1024;
    float4* Vsf1 = Vsf0 + 1024;

    const int tid = threadIdx.x;
    const int warp = tid >> 5;
    const int lane = tid & 31;
    const int rA = lane >> 2;
    const int cq = lane & 3;

    const int qt = (int)gridDim.x - 1 - (int)blockIdx.x;
    const int bh = blockIdx.y;
    const int q0 = qt * 128;

    const int b = bh / NH_, h = bh % NH_;
    const int qrow = q0 + warp * 16 + rA;

    const float4* Qf = (const float4*)g_qf;
    float qa[8][4];
#pragma unroll
    for (int kb = 0; kb < 8; kb++) {
        float4 f = Qf[(((size_t)bh * 128 + 8 * qt + warp) * 8 + kb) * 32 + lane];
        qa[kb][0] = f.x; qa[kb][1] = f.y; qa[kb][2] = f.z; qa[kb][3] = f.w;
    }

    float o[8][4];
#pragma unroll
    for (int i = 0; i < 8; i++)
#pragma unroll
        for (int j = 0; j < 4; j++) o[i][j] = 0.f;
    float mA = -1e30f, mB = -1e30f, lA = 0.f, lB = 0.f;

    const float4* Kf = (const float4*)g_kf;
    const float4* Vf = (const float4*)g_vf;

    auto issue_tile = [&](int kt, float4* Ksb, float4* Vsb) {
        const size_t tb = ((size_t)bh * 32 + kt) * 1024;
#pragma unroll
        for (int l = 0; l < 4; l++) {
            int slot = l * 256 + tid;
            cp_async16(smem_u32(&Ksb[slot]), &Kf[tb + slot]);
            cp_async16(smem_u32(&Vsb[slot]), &Vf[tb + slot]);
        }
        cp_async_commit();
    };

    issue_tile(0, Ksf0, Vsf0);

    const int srcA = (lane & ~3) | (cq >> 1);
    const int srcB = srcA + 2;
    const bool par = (cq & 1);

    const int ktiles = 2 * qt + 2;
    for (int kt = 0; kt < ktiles; kt++) {
        float4* Ksf = (kt & 1) ? Ksf1 : Ksf0;
        float4* Vsf = (kt & 1) ? Vsf1 : Vsf0;
        const bool have_next = (kt + 1 < ktiles);
        if (have_next) {
            issue_tile(kt + 1, (kt & 1) ? Ksf0 : Ksf1, (kt & 1) ? Vsf0 : Vsf1);
            cp_async_wait1();
        } else {
            cp_async_wait0();
        }
        __syncthreads();

        float s[8][4];
#pragma unroll
        for (int nb = 0; nb < 8; nb++)
#pragma unroll
            for (int j = 0; j < 4; j++) s[nb][j] = 0.f;
#pragma unroll
        for (int kbp = 0; kbp < 4; kbp++) {
#pragma unroll
            for (int nb = 0; nb < 8; nb++) {
                float4 f = Ksf[(nb * 4 + kbp) * 32 + lane];
                mma_tf32(s[nb], qa[2 * kbp][0], qa[2 * kbp][1], qa[2 * kbp][2], qa[2 * kbp][3], f.x, f.y);
                mma_tf32(s[nb], qa[2 * kbp + 1][0], qa[2 * kbp + 1][1], qa[2 * kbp + 1][2], qa[2 * kbp + 1][3], f.z, f.w);
            }
        }

        const int k0 = kt * 64;
        if (k0 + 63 > qrow) {
#pragma unroll
            for (int nb = 0; nb < 8; nb++) {
                int col = k0 + 8 * nb + 2 * cq;
                if (col > qrow)     s[nb][0] = -1e30f;
                if (col + 1 > qrow) s[nb][1] = -1e30f;
                if (col > qrow + 8)     s[nb][2] = -1e30f;
                if (col + 1 > qrow + 8) s[nb][3] = -1e30f;
            }
        }

        float rmaxA = -1e30f, rmaxB = -1e30f;
#pragma unroll
        for (int nb = 0; nb < 8; nb++) {
            rmaxA = fmaxf(rmaxA, fmaxf(s[nb][0], s[nb][1]));
            rmaxB = fmaxf(rmaxB, fmaxf(s[nb][2], s[nb][3]));
        }
        rmaxA = fmaxf(rmaxA, __shfl_xor_sync(0xffffffffu, rmaxA, 1));
        rmaxA = fmaxf(rmaxA, __shfl_xor_sync(0xffffffffu, rmaxA, 2));
        rmaxB = fmaxf(rmaxB, __shfl_xor_sync(0xffffffffu, rmaxB, 1));
        rmaxB = fmaxf(rmaxB, __shfl_xor_sync(0xffffffffu, rmaxB, 2));

        float mnA = fmaxf(mA, rmaxA), mnB = fmaxf(mB, rmaxB);
        float alA = exp2f(mA - mnA), alB = exp2f(mB - mnB);
        mA = mnA; mB = mnB;

        float sumA = 0.f, sumB = 0.f;
#pragma unroll
        for (int nb = 0; nb < 8; nb++) {
            s[nb][0] = exp2f(s[nb][0] - mA); sumA += s[nb][0];
            s[nb][1] = exp2f(s[nb][1] - mA); sumA += s[nb][1];
            s[nb][2] = exp2f(s[nb][2] - mB); sumB += s[nb][2];
            s[nb][3] = exp2f(s[nb][3] - mB); sumB += s[nb][3];
        }
        sumA += __shfl_xor_sync(0xffffffffu, sumA, 1);
        sumA += __shfl_xor_sync(0xffffffffu, sumA, 2);
        sumB += __shfl_xor_sync(0xffffffffu, sumB, 1);
        sumB += __shfl_xor_sync(0xffffffffu, sumB, 2);
        lA = lA * alA + sumA;
        lB = lB * alB + sumB;

#pragma unroll
        for (int nb = 0; nb < 8; nb++) {
            o[nb][0] *= alA; o[nb][1] *= alA;
            o[nb][2] *= alB; o[nb][3] *= alB;
        }

#pragma unroll
        for (int nb = 0; nb < 8; nb++)
#pragma unroll
            for (int j = 0; j < 4; j++) s[nb][j] = f2tf32(s[nb][j]);

#pragma unroll
        for (int kb2 = 0; kb2 < 8; kb2++) {
            float t0, t1;
            t0 = __shfl_sync(0xffffffffu, s[kb2][0], srcA);
            t1 = __shfl_sync(0xffffffffu, s[kb2][1], srcA);
            float pa0 = par ? t1 : t0;
            t0 = __shfl_sync(0xffffffffu, s[kb2][0], srcB);
            t1 = __shfl_sync(0xffffffffu, s[kb2][1], srcB);
            float pa2 = par ? t1 : t0;
            t0 = __shfl_sync(0xffffffffu, s[kb2][2], srcA);
            t1 = __shfl_sync(0xffffffffu, s[kb2][3], srcA);
            float pa1 = par ? t1 : t0;
            t0 = __shfl_sync(0xffffffffu, s[kb2][2], srcB);
            t1 = __shfl_sync(0xffffffffu, s[kb2][3], srcB);
            float pa3 = par ? t1 : t0;

#pragma unroll
            for (int nb2p = 0; nb2p < 4; nb2p++) {
                float4 f = Vsf[(kb2 * 4 + nb2p) * 32 + lane];
                mma_tf32(o[2 * nb2p],     pa0, pa1, pa2, pa3, f.x, f.y);
                mma_tf32(o[2 * nb2p + 1], pa0, pa1, pa2, pa3, f.z, f.w);
            }
        }
        __syncthreads();
    }

    // epilogue: normalize, tf32-round, C->A layout shuffle, store A-fragment order
    float invA = 1.f / lA, invB = 1.f / lB;
    float4* Of4 = (float4*)g_of;
#pragma unroll
    for (int nb2 = 0; nb2 < 8; nb2++) {
        float s0 = f2tf32(o[nb2][0] * invA);
        float s1 = f2tf32(o[nb2][1] * invA);
        float s2 = f2tf32(o[nb2][2] * invB);
        float s3 = f2tf32(o[nb2][3] * invB);

        float t0, t1;
        t0 = __shfl_sync(0xffffffffu, s0, srcA);
        t1 = __shfl_sync(0xffffffffu, s1, srcA);
        float pa0 = par ? t1 : t0;
        t0 = __shfl_sync(0xffffffffu, s0, srcB);
        t1 = __shfl_sync(0xffffffffu, s1, srcB);
        float pa2 = par ? t1 : t0;
        t0 = __shfl_sync(0xffffffffu, s2, srcA);
        t1 = __shfl_sync(0xffffffffu, s3, srcA);
        float pa1 = par ? t1 : t0;
        t0 = __shfl_sync(0xffffffffu, s2, srcB);
        t1 = __shfl_sync(0xffffffffu, s3, srcB);
        float pa3 = par ? t1 : t0;

        int itl = nb2 >> 2, ks = nb2 & 3;
        size_t idx = (((size_t)((b * 16 + qt) * KB24 + (2 * h + itl)) * 8 + warp) * 4 + ks) * 32 + lane;
        Of4[idx] = make_float4(pa0, pa1, pa2, pa3);
    }
}

// ---------------- launch ------------------------------------------------------
extern "C" void kernel_launch(void* const* d_in, const int* in_sizes, int n_in,
                              void* d_out, int out_size)
{
    const float* x     = (const float*)d_in[0];
    const float* w_qkv = (const float*)d_in[1];
    const float* w_out = (const float*)d_in[2];
    float* out = (float*)d_out;

    float *xf_p, *of_p, *wqf_p, *wof_p;
    cudaGetSymbolAddress((void**)&xf_p, g_xf);
    cudaGetSymbolAddress((void**)&of_p, g_of);
    cudaGetSymbolAddress((void**)&wqf_p, g_wqf);
    cudaGetSymbolAddress((void**)&wof_p, g_wof);

    // 0) round + fragment-reorder inputs
    prep_kernel<<<2048, 256>>>(x, w_qkv, w_out);

    cudaFuncSetAttribute(gemm_tf32_kernel, cudaFuncAttributeMaxDynamicSharedMemorySize, GEMM_SMEM);

    // 1) QKV GEMM with fused RoPE + fragment scatter
    {
        dim3 grid(NQKV / 128, M_ / 128);
        gemm_tf32_kernel<<<grid, 256, GEMM_SMEM>>>(
            (const float4*)xf_p, (const float4*)wqf_p, nullptr, KB24, NQKV, 1);
    }

    // 2) flash attention (writes g_of in A-fragment order)
    {
        const int smem = 4 * 1024 * sizeof(float4);     // 64 KB
        cudaFuncSetAttribute(flash_kernel, cudaFuncAttributeMaxDynamicSharedMemorySize, smem);
        dim3 grid(T_ / 128, B_ * NH_);
        flash_kernel<<<grid, 256, smem>>>();
    }

    // 3) out projection (plain epilogue, row-major final output)
    {
        dim3 grid(C_ / 128, M_ / 128);
        gemm_tf32_kernel<<<grid, 256, GEMM_SMEM>>>(
            (const float4*)of_p, (const float4*)wof_p, out, KB24, C_, 0);
    }
}

// round 14
// speedup vs baseline: 4.4892x; 1.0534x over previous
#include <cuda_runtime.h>
#include <cuda_bf16.h>
#include <cstdint>
#include <math.h>

#define B_  4
#define T_  2048
#define C_  768
#define NH_ 12
#define HD_ 64
#define RD_ 16
#define M_  (B_ * T_)          // 8192
#define NQKV (3 * C_)          // 2304
#define KB24 24                // 768 / 32

// ---------------- scratch ----------------------------------------------------
__device__ float g_qf[B_ * NH_ * T_ * HD_];      // Q frag order, tf32, scale*log2e folded
__device__ float g_kf[B_ * NH_ * T_ * HD_];      // K frag order, tf32
__device__ float g_vf[B_ * NH_ * T_ * HD_];      // V frag order, tf32
__device__ float g_of[M_ * C_];                  // attn out, A-fragment order, tf32
__device__ float g_xf[M_ * C_];                  // x, A-fragment order, tf32
__device__ float g_wqf[NQKV * C_];               // w_qkv, B-fragment order, tf32
__device__ float g_wof[C_ * C_];                 // w_out, B-fragment order, tf32

// ---------------- helpers -----------------------------------------------------
__device__ __forceinline__ float f2tf32(float x) {
    unsigned u;
    asm("cvt.rna.tf32.f32 %0, %1;" : "=r"(u) : "f"(x));
    return __uint_as_float(u);
}

__device__ __forceinline__ void mma_tf32(float* c,
    float a0, float a1, float a2, float a3, float b0, float b1)
{
    asm volatile(
        "mma.sync.aligned.m16n8k8.row.col.f32.tf32.tf32.f32 "
        "{%0,%1,%2,%3}, {%4,%5,%6,%7}, {%8,%9}, {%0,%1,%2,%3};"
        : "+f"(c[0]), "+f"(c[1]), "+f"(c[2]), "+f"(c[3])
        : "r"(__float_as_uint(a0)), "r"(__float_as_uint(a1)),
          "r"(__float_as_uint(a2)), "r"(__float_as_uint(a3)),
          "r"(__float_as_uint(b0)), "r"(__float_as_uint(b1)));
}

__device__ __forceinline__ void cp_async16(unsigned int smem_addr, const void* gptr) {
    asm volatile("cp.async.ca.shared.global [%0], [%1], 16;\n"
                 :: "r"(smem_addr), "l"(gptr));
}
__device__ __forceinline__ void cp_async_commit() {
    asm volatile("cp.async.commit_group;\n" ::: "memory");
}
__device__ __forceinline__ void cp_async_wait0() {
    asm volatile("cp.async.wait_group 0;\n" ::: "memory");
}
__device__ __forceinline__ void cp_async_wait1() {
    asm volatile("cp.async.wait_group 1;\n" ::: "memory");
}
__device__ __forceinline__ unsigned int smem_u32(const void* p) {
    return (unsigned int)__cvta_generic_to_shared(p);
}

// ---------------- prep: tf32-round + fragment reorder x / weights ---------------
__global__ __launch_bounds__(256) void prep_kernel(
    const float* __restrict__ x, const float* __restrict__ wq, const float* __restrict__ wo)
{
    int i = blockIdx.x * 256 + threadIdx.x;
    int stride = gridDim.x * 256;

    for (int j = i; j < M_ * C_; j += stride) {
        int m = j / C_, k = j - m * C_;
        float v = f2tf32(x[j]);
        int mblk = m >> 7, mi = m & 127;
        int wm = mi >> 6, mb = (mi >> 4) & 3, hi = (mi >> 3) & 1, ra = mi & 7;
        int it = k >> 5, kin = k & 31, ks = kin >> 3, c7 = kin & 7, half = c7 >> 2, cq = c7 & 3;
        size_t idx = (((size_t)(mblk * KB24 + it) * 8 + (wm * 4 + mb)) * 4 + ks) * 32 + (ra * 4 + cq);
        g_xf[idx * 4 + half * 2 + hi] = v;
    }
    for (int j = i; j < NQKV * C_; j += stride) {
        int n = j / C_, k = j - n * C_;
        float v = f2tf32(wq[j]);
        int nblk = n >> 7, ni = n & 127;
        int wn = ni >> 5, nb = (ni >> 3) & 3, ra = ni & 7;
        int p = nb >> 1, pb = nb & 1;
        int it = k >> 5, kin = k & 31, ks = kin >> 3, c7 = kin & 7, half = c7 >> 2, cq = c7 & 3;
        size_t idx = (((size_t)(nblk * KB24 + it) * 8 + (wn * 2 + p)) * 4 + ks) * 32 + (ra * 4 + cq);
        g_wqf[idx * 4 + pb * 2 + half] = v;
    }
    for (int j = i; j < C_ * C_; j += stride) {
        int n = j / C_, k = j - n * C_;
        float v = f2tf32(wo[j]);
        int nblk = n >> 7, ni = n & 127;
        int wn = ni >> 5, nb = (ni >> 3) & 3, ra = ni & 7;
        int p = nb >> 1, pb = nb & 1;
        int it = k >> 5, kin = k & 31, ks = kin >> 3, c7 = kin & 7, half = c7 >> 2, cq = c7 & 3;
        size_t idx = (((size_t)(nblk * KB24 + it) * 8 + (wn * 2 + p)) * 4 + ks) * 32 + (ra * 4 + cq);
        g_wof[idx * 4 + pb * 2 + half] = v;
    }
}

// ---------------- TF32 MMA GEMM, 3-stage pipeline, 1 barrier/iter --------------
#define EPAD 132
#define GEMM_SMEM (3 * 2048 * 16)    // 98304 B (3 stages x (A 1024 + B 1024) float4)

__global__ __launch_bounds__(256, 2) void gemm_tf32_kernel(
    const float4* __restrict__ Af, const float4* __restrict__ Bf,
    float* __restrict__ C, int KB, int N, int fuse_rope)
{
    extern __shared__ float4 sg4[];

    const int tid = threadIdx.x;
    const int warp = tid >> 5;
    const int lane = tid & 31;
    const int rA = lane >> 2;
    const int cq = lane & 3;
    const int warp_m = warp & 1;
    const int warp_n = warp >> 1;

    float acc[4][4][4];
#pragma unroll
    for (int a = 0; a < 4; a++)
#pragma unroll
        for (int b = 0; b < 4; b++)
#pragma unroll
            for (int c = 0; c < 4; c++) acc[a][b][c] = 0.f;

    auto issue = [&](int it, int st) {
        const float4* ga = Af + (size_t)(blockIdx.y * KB + it) * 1024;
        const float4* gb = Bf + (size_t)(blockIdx.x * KB + it) * 1024;
        float4* da = sg4 + st * 2048;
        float4* db = da + 1024;
#pragma unroll
        for (int l = 0; l < 4; l++) {
            int slot = l * 256 + tid;
            cp_async16(smem_u32(&da[slot]), &ga[slot]);
            cp_async16(smem_u32(&db[slot]), &gb[slot]);
        }
        cp_async_commit();
    };

    issue(0, 0);
    if (KB > 1) issue(1, 1);

    int st = 0, st2 = 2;                 // stage of it, stage of it+2
    for (int it = 0; it < KB; it++) {
        if (it + 1 < KB) cp_async_wait1(); else cp_async_wait0();
        __syncthreads();

        float4* As = sg4 + st * 2048;
        float4* Bs = As + 1024;
#pragma unroll
        for (int ks = 0; ks < 4; ks++) {
            float4 a4[4];
#pragma unroll
            for (int mb = 0; mb < 4; mb++)
                a4[mb] = As[((warp_m * 4 + mb) * 4 + ks) * 32 + lane];
            float4 b4[2];
#pragma unroll
            for (int p = 0; p < 2; p++)
                b4[p] = Bs[((warp_n * 2 + p) * 4 + ks) * 32 + lane];
#pragma unroll
            for (int mb = 0; mb < 4; mb++) {
                mma_tf32(acc[mb][0], a4[mb].x, a4[mb].y, a4[mb].z, a4[mb].w, b4[0].x, b4[0].y);
                mma_tf32(acc[mb][1], a4[mb].x, a4[mb].y, a4[mb].z, a4[mb].w, b4[0].z, b4[0].w);
                mma_tf32(acc[mb][2], a4[mb].x, a4[mb].y, a4[mb].z, a4[mb].w, b4[1].x, b4[1].y);
                mma_tf32(acc[mb][3], a4[mb].x, a4[mb].y, a4[mb].z, a4[mb].w, b4[1].z, b4[1].w);
            }
        }

        if (it + 2 < KB) issue(it + 2, st2);
        st = (st == 2) ? 0 : st + 1;
        st2 = (st2 == 2) ? 0 : st2 + 1;
    }

    const int m0 = blockIdx.y * 128;
    const int n0 = blockIdx.x * 128;

    if (!fuse_rope) {
#pragma unroll
        for (int mb = 0; mb < 4; mb++) {
            int row = m0 + warp_m * 64 + mb * 16 + rA;
#pragma unroll
            for (int nb = 0; nb < 4; nb++) {
                int col = n0 + warp_n * 32 + nb * 8 + 2 * cq;
                *(float2*)&C[(size_t)row * N + col] =
                    make_float2(acc[mb][nb][0], acc[mb][nb][1]);
                *(float2*)&C[(size_t)(row + 8) * N + col] =
                    make_float2(acc[mb][nb][2], acc[mb][nb][3]);
            }
        }
        return;
    }

    // --- fused RoPE + fragment scatter epilogue (QKV GEMM only) ---
    __syncthreads();                     // all compute done; reuse smem
    float* ep = (float*)sg4;             // overlay [128][132]
#pragma unroll
    for (int mb = 0; mb < 4; mb++) {
        int row = warp_m * 64 + mb * 16 + rA;
#pragma unroll
        for (int nb = 0; nb < 4; nb++) {
            int col = warp_n * 32 + nb * 8 + 2 * cq;
            *(float2*)&ep[row * EPAD + col] = make_float2(acc[mb][nb][0], acc[mb][nb][1]);
            *(float2*)&ep[(row + 8) * EPAD + col] = make_float2(acc[mb][nb][2], acc[mb][nb][3]);
        }
    }
    __syncthreads();

    const int sel = n0 / C_;
    const int cbase = n0 % C_;

#pragma unroll 4
    for (int e = 0; e < 64; e++) {
        int elem = e * 256 + tid;
        int r = elem >> 7, c = elem & 127;
        float val = ep[r * EPAD + c];

        int cc = cbase + c;
        int h = cc >> 6, d = cc & 63;
        int m = m0 + r;
        int b = m >> 11, t = m & (T_ - 1);

        if (sel < 2 && d < RD_) {
            int j = (d < 8) ? d : d - 8;
            float freq = __powf(10000.0f, -(float)j / 8.0f);
            float ang = (float)t * freq;
            float cs = cosf(ang), sn = sinf(ang);
            float partner = ep[r * EPAD + ((d < 8) ? c + 8 : c - 8)];
            val = (d < 8) ? (val * cs - partner * sn) : (val * cs + partner * sn);
        }
        if (sel == 0) val *= 0.125f * 1.4426950408889634f;
        val = f2tf32(val);

        const int bh = b * NH_ + h;
        if (sel == 0) {
            int g = t >> 4, tl = t & 15;
            int hi = tl >> 3, ra = tl & 7;
            int kb = d >> 3, c7 = d & 7, reg = c7 >> 2, q4 = c7 & 3;
            size_t off = (((size_t)bh * 128 + g) * 8 + kb) * 128 + (ra * 4 + q4) * 4 + hi + 2 * reg;
            g_qf[off] = val;
        } else if (sel == 1) {
            int kt = t >> 6, tl = t & 63;
            int nb = tl >> 3, ra = tl & 7;
            int kb = d >> 3, c7 = d & 7, reg = c7 >> 2, q4 = c7 & 3;
            size_t off = ((size_t)bh * 32 + kt) * 4096
                       + ((nb * 4 + (kb >> 1)) * 32 + ra * 4 + q4) * 4 + (kb & 1) * 2 + reg;
            g_kf[off] = val;
        } else {
            int kt = t >> 6, tl = t & 63;
            int kb2 = tl >> 3, c7 = tl & 7, reg = c7 >> 2, q4 = c7 & 3;
            int nb2 = d >> 3, ra = d & 7;
            size_t off = ((size_t)bh * 32 + kt) * 4096
                       + ((kb2 * 4 + (nb2 >> 1)) * 32 + ra * 4 + q4) * 4 + (nb2 & 1) * 2 + reg;
            g_vf[off] = val;
        }
    }
}

// ---------------- Flash attention: 3-stage pipeline, 1 barrier/tile ------------
#define FLASH_SMEM (6 * 1024 * 16)   // 98304 B (3 stages x (K 1024 + V 1024) float4)

__global__ __launch_bounds__(256, 2) void flash_kernel()
{
    extern __shared__ float4 smf[];

    const int tid = threadIdx.x;
    const int warp = tid >> 5;
    const int lane = tid & 31;
    const int rA = lane >> 2;
    const int cq = lane & 3;

    const int qt = (int)gridDim.x - 1 - (int)blockIdx.x;
    const int bh = blockIdx.y;
    const int q0 = qt * 128;

    const int b = bh / NH_, h = bh % NH_;
    const int qrow = q0 + warp * 16 + rA;

    const float4* Qf = (const float4*)g_qf;
    float qa[8][4];
#pragma unroll
    for (int kb = 0; kb < 8; kb++) {
        float4 f = Qf[(((size_t)bh * 128 + 8 * qt + warp) * 8 + kb) * 32 + lane];
        qa[kb][0] = f.x; qa[kb][1] = f.y; qa[kb][2] = f.z; qa[kb][3] = f.w;
    }

    float o[8][4];
#pragma unroll
    for (int i = 0; i < 8; i++)
#pragma unroll
        for (int j = 0; j < 4; j++) o[i][j] = 0.f;
    float mA = -1e30f, mB = -1e30f, lA = 0.f, lB = 0.f;

    const float4* Kf = (const float4*)g_kf;
    const float4* Vf = (const float4*)g_vf;

    auto issue_tile = [&](int kt, int st) {
        const size_t tb = ((size_t)bh * 32 + kt) * 1024;
        float4* Ksb = smf + st * 1024;
        float4* Vsb = smf + 3072 + st * 1024;
#pragma unroll
        for (int l = 0; l < 4; l++) {
            int slot = l * 256 + tid;
            cp_async16(smem_u32(&Ksb[slot]), &Kf[tb + slot]);
            cp_async16(smem_u32(&Vsb[slot]), &Vf[tb + slot]);
        }
        cp_async_commit();
    };

    const int ktiles = 2 * qt + 2;
    issue_tile(0, 0);
    if (ktiles > 1) issue_tile(1, 1);

    const int srcA = (lane & ~3) | (cq >> 1);
    const int srcB = srcA + 2;
    const bool par = (cq & 1);

    int st = 0, st2 = 2;
    for (int kt = 0; kt < ktiles; kt++) {
        if (kt + 1 < ktiles) cp_async_wait1(); else cp_async_wait0();
        __syncthreads();

        float4* Ksf = smf + st * 1024;
        float4* Vsf = smf + 3072 + st * 1024;

        float s[8][4];
#pragma unroll
        for (int nb = 0; nb < 8; nb++)
#pragma unroll
            for (int j = 0; j < 4; j++) s[nb][j] = 0.f;
#pragma unroll
        for (int kbp = 0; kbp < 4; kbp++) {
#pragma unroll
            for (int nb = 0; nb < 8; nb++) {
                float4 f = Ksf[(nb * 4 + kbp) * 32 + lane];
                mma_tf32(s[nb], qa[2 * kbp][0], qa[2 * kbp][1], qa[2 * kbp][2], qa[2 * kbp][3], f.x, f.y);
                mma_tf32(s[nb], qa[2 * kbp + 1][0], qa[2 * kbp + 1][1], qa[2 * kbp + 1][2], qa[2 * kbp + 1][3], f.z, f.w);
            }
        }

        const int k0 = kt * 64;
        if (k0 + 63 > qrow) {
#pragma unroll
            for (int nb = 0; nb < 8; nb++) {
                int col = k0 + 8 * nb + 2 * cq;
                if (col > qrow)     s[nb][0] = -1e30f;
                if (col + 1 > qrow) s[nb][1] = -1e30f;
                if (col > qrow + 8)     s[nb][2] = -1e30f;
                if (col + 1 > qrow + 8) s[nb][3] = -1e30f;
            }
        }

        float rmaxA = -1e30f, rmaxB = -1e30f;
#pragma unroll
        for (int nb = 0; nb < 8; nb++) {
            rmaxA = fmaxf(rmaxA, fmaxf(s[nb][0], s[nb][1]));
            rmaxB = fmaxf(rmaxB, fmaxf(s[nb][2], s[nb][3]));
        }
        rmaxA = fmaxf(rmaxA, __shfl_xor_sync(0xffffffffu, rmaxA, 1));
        rmaxA = fmaxf(rmaxA, __shfl_xor_sync(0xffffffffu, rmaxA, 2));
        rmaxB = fmaxf(rmaxB, __shfl_xor_sync(0xffffffffu, rmaxB, 1));
        rmaxB = fmaxf(rmaxB, __shfl_xor_sync(0xffffffffu, rmaxB, 2));

        float mnA = fmaxf(mA, rmaxA), mnB = fmaxf(mB, rmaxB);
        float alA = exp2f(mA - mnA), alB = exp2f(mB - mnB);
        mA = mnA; mB = mnB;

        float sumA = 0.f, sumB = 0.f;
#pragma unroll
        for (int nb = 0; nb < 8; nb++) {
            s[nb][0] = exp2f(s[nb][0] - mA); sumA += s[nb][0];
            s[nb][1] = exp2f(s[nb][1] - mA); sumA += s[nb][1];
            s[nb][2] = exp2f(s[nb][2] - mB); sumB += s[nb][2];
            s[nb][3] = exp2f(s[nb][3] - mB); sumB += s[nb][3];
        }
        sumA += __shfl_xor_sync(0xffffffffu, sumA, 1);
        sumA += __shfl_xor_sync(0xffffffffu, sumA, 2);
        sumB += __shfl_xor_sync(0xffffffffu, sumB, 1);
        sumB += __shfl_xor_sync(0xffffffffu, sumB, 2);
        lA = lA * alA + sumA;
        lB = lB * alB + sumB;

#pragma unroll
        for (int nb = 0; nb < 8; nb++) {
            o[nb][0] *= alA; o[nb][1] *= alA;
            o[nb][2] *= alB; o[nb][3] *= alB;
        }

#pragma unroll
        for (int nb = 0; nb < 8; nb++)
#pragma unroll
            for (int j = 0; j < 4; j++) s[nb][j] = f2tf32(s[nb][j]);

#pragma unroll
        for (int kb2 = 0; kb2 < 8; kb2++) {
            float t0, t1;
            t0 = __shfl_sync(0xffffffffu, s[kb2][0], srcA);
            t1 = __shfl_sync(0xffffffffu, s[kb2][1], srcA);
            float pa0 = par ? t1 : t0;
            t0 = __shfl_sync(0xffffffffu, s[kb2][0], srcB);
            t1 = __shfl_sync(0xffffffffu, s[kb2][1], srcB);
            float pa2 = par ? t1 : t0;
            t0 = __shfl_sync(0xffffffffu, s[kb2][2], srcA);
            t1 = __shfl_sync(0xffffffffu, s[kb2][3], srcA);
            float pa1 = par ? t1 : t0;
            t0 = __shfl_sync(0xffffffffu, s[kb2][2], srcB);
            t1 = __shfl_sync(0xffffffffu, s[kb2][3], srcB);
            float pa3 = par ? t1 : t0;

#pragma unroll
            for (int nb2p = 0; nb2p < 4; nb2p++) {
                float4 f = Vsf[(kb2 * 4 + nb2p) * 32 + lane];
                mma_tf32(o[2 * nb2p],     pa0, pa1, pa2, pa3, f.x, f.y);
                mma_tf32(o[2 * nb2p + 1], pa0, pa1, pa2, pa3, f.z, f.w);
            }
        }

        if (kt + 2 < ktiles) issue_tile(kt + 2, st2);
        st = (st == 2) ? 0 : st + 1;
        st2 = (st2 == 2) ? 0 : st2 + 1;
    }

    // epilogue: normalize, tf32-round, C->A layout shuffle, store A-fragment order
    float invA = 1.f / lA, invB = 1.f / lB;
    float4* Of4 = (float4*)g_of;
#pragma unroll
    for (int nb2 = 0; nb2 < 8; nb2++) {
        float s0 = f2tf32(o[nb2][0] * invA);
        float s1 = f2tf32(o[nb2][1] * invA);
        float s2 = f2tf32(o[nb2][2] * invB);
        float s3 = f2tf32(o[nb2][3] * invB);

        float t0, t1;
        t0 = __shfl_sync(0xffffffffu, s0, srcA);
        t1 = __shfl_sync(0xffffffffu, s1, srcA);
        float pa0 = par ? t1 : t0;
        t0 = __shfl_sync(0xffffffffu, s0, srcB);
        t1 = __shfl_sync(0xffffffffu, s1, srcB);
        float pa2 = par ? t1 : t0;
        t0 = __shfl_sync(0xffffffffu, s2, srcA);
        t1 = __shfl_sync(0xffffffffu, s3, srcA);
        float pa1 = par ? t1 : t0;
        t0 = __shfl_sync(0xffffffffu, s2, srcB);
        t1 = __shfl_sync(0xffffffffu, s3, srcB);
        float pa3 = par ? t1 : t0;

        int itl = nb2 >> 2, ks = nb2 & 3;
        size_t idx = (((size_t)((b * 16 + qt) * KB24 + (2 * h + itl)) * 8 + warp) * 4 + ks) * 32 + lane;
        Of4[idx] = make_float4(pa0, pa1, pa2, pa3);
    }
}

// ---------------- launch ------------------------------------------------------
extern "C" void kernel_launch(void* const* d_in, const int* in_sizes, int n_in,
                              void* d_out, int out_size)
{
    const float* x     = (const float*)d_in[0];
    const float* w_qkv = (const float*)d_in[1];
    const float* w_out = (const float*)d_in[2];
    float* out = (float*)d_out;

    float *xf_p, *of_p, *wqf_p, *wof_p;
    cudaGetSymbolAddress((void**)&xf_p, g_xf);
    cudaGetSymbolAddress((void**)&of_p, g_of);
    cudaGetSymbolAddress((void**)&wqf_p, g_wqf);
    cudaGetSymbolAddress((void**)&wof_p, g_wof);

    // 0) round + fragment-reorder inputs
    prep_kernel<<<2048, 256>>>(x, w_qkv, w_out);

    cudaFuncSetAttribute(gemm_tf32_kernel, cudaFuncAttributeMaxDynamicSharedMemorySize, GEMM_SMEM);
    cudaFuncSetAttribute(flash_kernel, cudaFuncAttributeMaxDynamicSharedMemorySize, FLASH_SMEM);

    // 1) QKV GEMM with fused RoPE + fragment scatter
    {
        dim3 grid(NQKV / 128, M_ / 128);
        gemm_tf32_kernel<<<grid, 256, GEMM_SMEM>>>(
            (const float4*)xf_p, (const float4*)wqf_p, nullptr, KB24, NQKV, 1);
    }

    // 2) flash attention (writes g_of in A-fragment order)
    {
        dim3 grid(T_ / 128, B_ * NH_);
        flash_kernel<<<grid, 256, FLASH_SMEM>>>();
    }

    // 3) out projection (plain epilogue, row-major final output)
    {
        dim3 grid(C_ / 128, M_ / 128);
        gemm_tf32_kernel<<<grid, 256, GEMM_SMEM>>>(
            (const float4*)of_p, (const float4*)wof_p, out, KB24, C_, 0);
    }
}